// round 9
// baseline (speedup 1.0000x reference)
#include <cuda_runtime.h>
#include <cuda_bf16.h>
#include <cuda_fp16.h>
#include <mma.h>
#include <math.h>
#include <stdint.h>

using namespace nvcuda;

#define B_     256
#define T_     64
#define VOCAB_ 10000
#define V1     10001
#define V1P    10240
#define VIS_   1024
#define RNN_   512
#define TB     16384
#define NCTA   128
#define LOG2E  1.4426950408889634f

// ---------------- scratch ----------------
__device__ float d_hbuf[2][B_ * RNN_];
__device__ __nv_bfloat16 d_Sb [(size_t)TB * RNN_];    // sentinel states bf16
__device__ __nv_bfloat16 d_OWb[(size_t)RNN_ * V1P];   // out_W bf16 padded

__device__ unsigned g_cnt = 0;
__device__ volatile unsigned g_sense = 0;

__device__ __forceinline__ void gbar(unsigned &ls)
{
    __syncthreads();
    if (threadIdx.x == 0) {
        ls ^= 1u;
        __threadfence();
        if (atomicAdd(&g_cnt, 1u) == NCTA - 1u) {
            g_cnt = 0u;
            __threadfence();
            g_sense = ls;
        } else {
            while (g_sense != ls) { }
            __threadfence();
        }
    }
    __syncthreads();
}

__device__ __forceinline__ float tanh_p(float x)
{
    float ax = fabsf(x);
    float e  = __expf(-2.0f * ax);
    float r  = __fdividef(1.0f - e, 1.0f + e);
    return copysignf(r, x);
}
__device__ __forceinline__ float sigmoid_p(float x)
{
    return __fdividef(1.0f, 1.0f + __expf(-x));
}

// cp.async helpers
__device__ __forceinline__ void cp16(uint32_t dst, const void* src)
{
    asm volatile("cp.async.cg.shared.global [%0], [%1], 16;" :: "r"(dst), "l"(src));
}
__device__ __forceinline__ void cp_commit()
{
    asm volatile("cp.async.commit_group;" ::: "memory");
}
template<int N> __device__ __forceinline__ void cp_wait()
{
    asm volatile("cp.async.wait_group %0;" :: "n"(N) : "memory");
}

// ---------------- prep: out_W -> bf16 padded ----------------
__global__ __launch_bounds__(256) void k_prep(const float* __restrict__ out_W)
{
    size_t idx = (size_t)blockIdx.x * 256 + threadIdx.x;
    if (idx >= (size_t)RNN_ * V1P) return;
    int k = (int)(idx / V1P), v = (int)(idx % V1P);
    float w = (v < V1) ? out_W[(size_t)k * V1 + v] : 0.f;
    d_OWb[idx] = __float2bfloat16(w);
}

// =====================================================================
// k_rnn: 128 persistent CTAs. CTA (ct>>5, ct&31) owns batch rows
// m0..m0+63 and hidden units u0..u0+15 (all 5 gate blocks = 80 cols,
// padded to 96). Weights streamed with cp.async double buffering;
// gates/c-state/VPG live in smem; pointwise is CTA-local.
// One global barrier per step (h double-buffered).
// =====================================================================
#define RNN_SMEM 141568
__global__ __launch_bounds__(256) void k_rnn(
    const float* __restrict__ vis,     const int*   __restrict__ seqz,
    const float* __restrict__ emb,     const float* __restrict__ W_ih,
    const float* __restrict__ W_hh,    const float* __restrict__ b_lstm,
    const float* __restrict__ vis2g_W, const float* __restrict__ vis2g_b,
    const float* __restrict__ w2g_W,   const float* __restrict__ h2g_W)
{
    extern __shared__ char smraw[];
    float* As_  = (float*)(smraw);             // [2][64][64]
    float* Bs_  = (float*)(smraw + 32768);     // [2][64][104]
    float* vpg  = (float*)(smraw + 86016);     // [64][96]
    float* csm  = (float*)(smraw + 110592);    // [64][104]
    float* cst  = (float*)(smraw + 137216);    // [64][16]
    int*   stok = (int*)  (smraw + 141312);    // [64]

    const int tid = threadIdx.x;
    const int ct  = blockIdx.x;
    const int wid = tid >> 5;
    const int wm  = wid >> 1;                  // 0..3, 16 rows
    const int wn  = wid & 1;                   // 0..1, 48 cols (3 frags)
    const int m0  = (ct >> 5) * 64;
    const int u0  = (ct & 31) * 16;
    unsigned ls = 0;

    uint32_t aB = (uint32_t)__cvta_generic_to_shared(As_);
    uint32_t bB = (uint32_t)__cvta_generic_to_shared(Bs_);

    // A slice issue: 64 rows x 64 k-cols. mode 0=vis, 1=h, 2=emb
    auto issueA = [&](int s, int d, int prol, const float* hb) {
        int k0 = s * 64;
        #pragma unroll
        for (int j = 0; j < 4; j++) {
            int idx = tid + j * 256;           // 0..1023
            int r = idx >> 4, sg = (idx & 15) << 2;
            const float* src;
            if (prol)            src = vis + (size_t)(m0 + r) * VIS_ + k0 + sg;
            else if (k0 < 512)   src = hb  + (size_t)(m0 + r) * RNN_ + k0 + sg;
            else                 src = emb + (size_t)stok[r] * 512 + (k0 - 512) + sg;
            cp16(aB + (uint32_t)(((d * 64 + r) * 64 + sg) * 4), src);
        }
    };
    // B slice issue: 64 k-rows x 80 real cols (5 blocks of 16)
    auto issueB = [&](int s, int d, int prol) {
        int k0 = s * 64;
        #pragma unroll
        for (int j = 0; j < 5; j++) {
            int e = tid + j * 256;             // 0..1279
            int r = e / 20, q = e % 20;
            int blk = q >> 2, f4 = (q & 3) << 2;
            int kk = k0 + r;
            const float* src;
            if (prol) {
                src = (blk < 4) ? W_ih + (size_t)kk * 2048 + blk * 512 + u0 + f4
                                : vis2g_W + (size_t)kk * 512 + u0 + f4;
            } else if (kk < 512) {
                src = (blk < 4) ? W_hh + (size_t)kk * 2048 + blk * 512 + u0 + f4
                                : h2g_W + (size_t)kk * 512 + u0 + f4;
            } else {
                src = (blk < 4) ? W_ih + (size_t)(1024 + kk - 512) * 2048 + blk * 512 + u0 + f4
                                : w2g_W + (size_t)(kk - 512) * 512 + u0 + f4;
            }
            cp16(bB + (uint32_t)(((d * 64 + r) * 104 + blk * 16 + f4) * 4), src);
        }
    };

    // pipelined GEMM: 16 slices of K=64; result -> csm
    auto gemm = [&](int prol, const float* hb) {
        wmma::fragment<wmma::accumulator, 16, 16, 8, float> acc[3];
        #pragma unroll
        for (int f = 0; f < 3; f++) wmma::fill_fragment(acc[f], 0.f);

        issueA(0, 0, prol, hb); issueB(0, 0, prol); cp_commit();
        for (int s = 0; s < 16; s++) {
            if (s < 16 - 1) {
                issueA(s + 1, (s + 1) & 1, prol, hb);
                issueB(s + 1, (s + 1) & 1, prol);
                cp_commit();
                cp_wait<1>();
            } else {
                cp_wait<0>();
            }
            __syncthreads();
            int d = s & 1;
            #pragma unroll
            for (int k8 = 0; k8 < 8; k8++) {
                wmma::fragment<wmma::matrix_a, 16, 16, 8, wmma::precision::tf32, wmma::row_major> af;
                wmma::load_matrix_sync(af, As_ + (d * 64 + wm * 16) * 64 + k8 * 8, 64);
                #pragma unroll
                for (int e = 0; e < af.num_elements; e++)
                    af.x[e] = wmma::__float_to_tf32(af.x[e]);
                #pragma unroll
                for (int f = 0; f < 3; f++) {
                    wmma::fragment<wmma::matrix_b, 16, 16, 8, wmma::precision::tf32, wmma::row_major> bf;
                    wmma::load_matrix_sync(bf, Bs_ + (d * 64 + k8 * 8) * 104 + wn * 48 + f * 16, 104);
                    #pragma unroll
                    for (int e = 0; e < bf.num_elements; e++)
                        bf.x[e] = wmma::__float_to_tf32(bf.x[e]);
                    wmma::mma_sync(acc[f], af, bf, acc[f]);
                }
            }
            __syncthreads();
        }
        #pragma unroll
        for (int f = 0; f < 3; f++)
            wmma::store_matrix_sync(csm + (wm * 16) * 104 + wn * 48 + f * 16,
                                    acc[f], 104, wmma::mem_row_major);
        __syncthreads();
    };

    // ---- init: zero B pad block (cols 80..95, both buffers), c-state, h[0] slice ----
    #pragma unroll
    for (int j = 0; j < 8; j++) {
        int e = tid + j * 256;                 // 0..2047
        int d = e >> 10, r = (e >> 4) & 63, c = e & 15;
        Bs_[(d * 64 + r) * 104 + 80 + c] = 0.f;
    }
    #pragma unroll
    for (int j = 0; j < 4; j++) {
        int e = tid + j * 256;                 // 0..1023
        int r = e >> 4, u = e & 15;
        cst[r * 16 + u] = 0.f;
        d_hbuf[0][(m0 + r) * RNN_ + u0 + u] = 0.f;
    }
    __syncthreads();

    // ---- prologue: VPG = vis @ [W_ih_vis | vis2g] + bias ----
    gemm(1, nullptr);
    for (int e = tid; e < 64 * 80; e += 256) {
        int r = e / 80, q = e % 80;
        int blk = q >> 4, cc = q & 15;
        float bias = (blk < 4) ? b_lstm[blk * 512 + u0 + cc] : vis2g_b[u0 + cc];
        vpg[r * 96 + blk * 16 + cc] = csm[r * 104 + blk * 16 + cc] + bias;
    }
    gbar(ls);                                  // barrier #1

    // ---- 64 steps ----
    for (int t = 0; t < T_; t++) {
        const float* hb = d_hbuf[t & 1];
        float* hn = d_hbuf[(t & 1) ^ 1];
        if (tid < 64)
            stok[tid] = (t == 0) ? (VOCAB_ + 1) : seqz[(m0 + tid) * T_ + t - 1];
        __syncthreads();

        gemm(0, hb);

        // CTA-local pointwise: 64 rows x 16 units
        #pragma unroll
        for (int j = 0; j < 4; j++) {
            int e = tid + j * 256;
            int r = e >> 4, u = e & 15;
            const float* vp = vpg + r * 96;
            const float* gg = csm + r * 104;
            float ig = vp[u]      + gg[u];
            float fg = vp[16 + u] + gg[16 + u];
            float g_ = vp[32 + u] + gg[32 + u];
            float og = vp[48 + u] + gg[48 + u];
            float gp = vp[64 + u] + gg[64 + u];
            float cold = cst[r * 16 + u];
            float cn = sigmoid_p(fg) * cold + sigmoid_p(ig) * tanh_p(g_);
            float tc = tanh_p(cn);
            cst[r * 16 + u] = cn;
            hn[(m0 + r) * RNN_ + u0 + u] = sigmoid_p(og) * tc;
            d_Sb[((size_t)(t * 256 + m0 + r)) * RNN_ + u0 + u] =
                __float2bfloat16(sigmoid_p(gp) * tc);
        }
        gbar(ls);                              // h(t) published
    }
    gbar(ls);   // total barriers = 1 + 64 + 1 = 66 (even -> state restored)
}

// =====================================================================
// k_lse: bf16 WMMA logits, cp.async double-buffered B, f16x2 packed exp
// for the logsumexp sum (logits bounded: no online max needed),
// exact fp32 target logit, masked output.
// =====================================================================
#define LSE_SMEM 212992
#define NCH 157                                 // ceil(10001/64)
__global__ __launch_bounds__(256) void k_lse(
    const float* __restrict__ out_b,
    const int* __restrict__ seqz, float* __restrict__ out)
{
    extern __shared__ unsigned char dyn[];
    __nv_bfloat16* Asm = (__nv_bfloat16*)dyn;            // 64 x 512
    __nv_bfloat16* Bsm = (__nv_bfloat16*)(dyn + 65536);  // 2 x (512 x 64)
    float*         Csm = (float*)(dyn + 196608);         // 64 x 64
    __shared__ float s_tgt[64];
    __shared__ int   s_tg[64];
    __shared__ float red_s[4][64];

    const int tid = threadIdx.x;
    const int m0  = blockIdx.x * 64;
    const int wid = tid >> 5;
    const int warp_m = wid >> 1;
    const int warp_n = wid & 1;
    uint32_t bB = (uint32_t)__cvta_generic_to_shared(Bsm);

    if (tid < 64) {
        int r = m0 + tid;
        int t = r >> 8, b = r & 255;
        s_tg[tid] = seqz[b * T_ + t];
    }

    // A tile resident
    #pragma unroll
    for (int i = 0; i < 16; i++) {
        int idx = tid + i * 256;
        int r = idx >> 6, c = idx & 63;
        ((uint4*)Asm)[idx] = ((const uint4*)(d_Sb + (size_t)(m0 + r) * RNN_))[c];
    }
    __syncthreads();

    auto issueB = [&](int ch, int d) {
        int v0 = ch * 64;
        #pragma unroll
        for (int j = 0; j < 16; j++) {
            int idx = tid + j * 256;           // 0..4095
            int k = idx >> 3, c8 = (idx & 7) << 3;
            cp16(bB + (uint32_t)(d * 65536 + (k * 64 + c8) * 2),
                 d_OWb + (size_t)k * V1P + v0 + c8);
        }
    };

    const int row = tid >> 2;
    const int qtr = tid & 3;
    const int mytg = s_tg[row];
    float rs = 0.f;

    issueB(0, 0); cp_commit();
    for (int c = 0; c < NCH; c++) {
        if (c < NCH - 1) { issueB(c + 1, (c + 1) & 1); cp_commit(); cp_wait<1>(); }
        else             { cp_wait<0>(); }
        __syncthreads();

        const __nv_bfloat16* Bcur = Bsm + (c & 1) * 32768;
        wmma::fragment<wmma::accumulator, 16, 16, 16, float> acc[2];
        wmma::fill_fragment(acc[0], 0.f);
        wmma::fill_fragment(acc[1], 0.f);
        #pragma unroll
        for (int k = 0; k < 32; k++) {
            wmma::fragment<wmma::matrix_a, 16, 16, 16, __nv_bfloat16, wmma::row_major> af;
            wmma::load_matrix_sync(af, Asm + (warp_m * 16) * 512 + k * 16, 512);
            #pragma unroll
            for (int nf = 0; nf < 2; nf++) {
                wmma::fragment<wmma::matrix_b, 16, 16, 16, __nv_bfloat16, wmma::row_major> bf;
                wmma::load_matrix_sync(bf, Bcur + (k * 16) * 64 + warp_n * 32 + nf * 16, 64);
                wmma::mma_sync(acc[nf], af, bf, acc[nf]);
            }
        }
        #pragma unroll
        for (int nf = 0; nf < 2; nf++)
            wmma::store_matrix_sync(Csm + (warp_m * 16) * 64 + warp_n * 32 + nf * 16,
                                    acc[nf], 64, wmma::mem_row_major);
        __syncthreads();

        // epilogue: packed f16x2 exp sum (logits bounded, no overflow)
        int v0 = c * 64;
        float lsum = 0.f;
        #pragma unroll
        for (int j = 0; j < 8; j++) {
            int cc = (qtr << 4) + 2 * j;
            int v = v0 + cc;
            float l0 = (v     < V1) ? (Csm[row * 64 + cc]     + out_b[v])     : -1e4f;
            float l1 = (v + 1 < V1) ? (Csm[row * 64 + cc + 1] + out_b[v + 1]) : -1e4f;
            uint32_t h2, e2;
            asm("cvt.rn.f16x2.f32 %0, %1, %2;" : "=r"(h2) : "f"(l1 * LOG2E), "f"(l0 * LOG2E));
            asm("ex2.approx.f16x2 %0, %1;" : "=r"(e2) : "r"(h2));
            __half2 hh = *reinterpret_cast<__half2*>(&e2);
            float2 ff = __half22float2(hh);
            lsum += ff.x + ff.y;
        }
        rs += lsum;
        if (mytg >= v0 && mytg < v0 + 64 && ((mytg - v0) >> 4) == qtr)
            s_tgt[row] = Csm[row * 64 + (mytg - v0)] + out_b[mytg];
        __syncthreads();
    }

    red_s[qtr][row] = rs;
    __syncthreads();
    if (tid < 64) {
        int r = m0 + tid;
        float S = red_s[0][tid] + red_s[1][tid] + red_s[2][tid] + red_s[3][tid];
        float lse = logf(S);
        int t = r >> 8, b = r & 255;
        float mask = (t == 0) ? 1.f : ((seqz[b * T_ + (t - 1)] != 0) ? 1.f : 0.f);
        out[r] = (s_tgt[tid] - lse) * mask;
    }
}

// ---------------- launch ----------------
extern "C" void kernel_launch(void* const* d_in, const int* in_sizes, int n_in,
                              void* d_out, int out_size)
{
    const float *vis = 0, *emb = 0, *W_ih = 0, *W_hh = 0, *b_lstm = 0;
    const float *vis2g_W = 0, *vis2g_b = 0, *w2g_W = 0, *h2g_W = 0;
    const float *out_W = 0, *out_b = 0;
    const int *seqz = 0;
    int trio[3]; int ntrio = 0;
    for (int i = 0; i < n_in; i++) {
        switch (in_sizes[i]) {
            case 16384:   seqz    = (const int*)  d_in[i]; break;
            case 5121024: emb     = (const float*)d_in[i]; break;
            case 3145728: W_ih    = (const float*)d_in[i]; break;
            case 1048576: W_hh    = (const float*)d_in[i]; break;
            case 2048:    b_lstm  = (const float*)d_in[i]; break;
            case 524288:  vis2g_W = (const float*)d_in[i]; break;
            case 512:     vis2g_b = (const float*)d_in[i]; break;
            case 5120512: out_W   = (const float*)d_in[i]; break;
            case 10001:   out_b   = (const float*)d_in[i]; break;
            case 262144:  if (ntrio < 3) trio[ntrio++] = i; break;
            default: break;
        }
    }
    if (ntrio == 3) {
        vis   = (const float*)d_in[trio[0]];
        w2g_W = (const float*)d_in[trio[1]];
        h2g_W = (const float*)d_in[trio[2]];
    }
    if (!vis)     vis     = (const float*)d_in[0];
    if (!seqz)    seqz    = (const int*)  d_in[1];
    if (!emb)     emb     = (const float*)d_in[2];
    if (!W_ih)    W_ih    = (const float*)d_in[3];
    if (!W_hh)    W_hh    = (const float*)d_in[4];
    if (!b_lstm)  b_lstm  = (const float*)d_in[5];
    if (!vis2g_W) vis2g_W = (const float*)d_in[6];
    if (!vis2g_b) vis2g_b = (const float*)d_in[7];
    if (!w2g_W)   w2g_W   = (const float*)d_in[8];
    if (!h2g_W)   h2g_W   = (const float*)d_in[9];
    if (!out_W)   out_W   = (const float*)d_in[10];
    if (!out_b)   out_b   = (const float*)d_in[11];
    float* out = (float*)d_out;

    cudaFuncSetAttribute(k_rnn, cudaFuncAttributeMaxDynamicSharedMemorySize, RNN_SMEM);
    cudaFuncSetAttribute(k_lse, cudaFuncAttributeMaxDynamicSharedMemorySize, LSE_SMEM);

    k_prep<<<(int)(((size_t)RNN_ * V1P + 255) / 256), 256>>>(out_W);
    k_rnn<<<NCTA, 256, RNN_SMEM>>>(vis, seqz, emb, W_ih, W_hh, b_lstm,
                                   vis2g_W, vis2g_b, w2g_W, h2g_W);
    k_lse<<<TB / 64, 256, LSE_SMEM>>>(out_b, seqz, out);
}

// round 10
// speedup vs baseline: 1.6566x; 1.6566x over previous
#include <cuda_runtime.h>
#include <cuda_bf16.h>
#include <cuda_fp16.h>
#include <mma.h>
#include <math.h>
#include <stdint.h>

using namespace nvcuda;

#define B_     256
#define T_     64
#define VOCAB_ 10000
#define V1     10001
#define V1P    10240
#define VIS_   1024
#define RNN_   512
#define GEXT   2560
#define TB     16384
#define NCTA   128
#define LOG2E  1.4426950408889634f

// ---------------- scratch ----------------
__device__ float d_hbuf[2][B_ * RNN_];
__device__ float d_WPG[(size_t)TB * GEXT];            // word-part gates (168 MB)
__device__ __nv_bfloat16 d_Sb [(size_t)TB * RNN_];    // sentinel states bf16
__device__ __nv_bfloat16 d_OWb[(size_t)RNN_ * V1P];   // out_W bf16 padded

__device__ unsigned g_cnt = 0;
__device__ volatile unsigned g_sense = 0;

__device__ __forceinline__ void gbar(unsigned &ls)
{
    __syncthreads();
    if (threadIdx.x == 0) {
        ls ^= 1u;
        __threadfence();
        if (atomicAdd(&g_cnt, 1u) == NCTA - 1u) {
            g_cnt = 0u;
            __threadfence();
            g_sense = ls;
        } else {
            while (g_sense != ls) { }
            __threadfence();
        }
    }
    __syncthreads();
}

// MUFU tanh (1 op) and sigmoid built on it
__device__ __forceinline__ float tanh_f(float x)
{
    float y;
    asm("tanh.approx.f32 %0, %1;" : "=f"(y) : "f"(x));
    return y;
}
__device__ __forceinline__ float sig_f(float x)
{
    return fmaf(0.5f, tanh_f(0.5f * x), 0.5f);
}

// cp.async helpers
__device__ __forceinline__ void cp16(uint32_t dst, const void* src)
{
    asm volatile("cp.async.cg.shared.global [%0], [%1], 16;" :: "r"(dst), "l"(src));
}
__device__ __forceinline__ void cp_commit()
{
    asm volatile("cp.async.commit_group;" ::: "memory");
}
template<int N> __device__ __forceinline__ void cp_wait()
{
    asm volatile("cp.async.wait_group %0;" :: "n"(N) : "memory");
}

// tf32 fragment load helpers
#define LOAD_A_TF32(frag, ptr, ldm) do { \
    wmma::load_matrix_sync(frag, ptr, ldm); \
    for (int _e = 0; _e < (frag).num_elements; _e++) \
        (frag).x[_e] = wmma::__float_to_tf32((frag).x[_e]); \
} while (0)

// ---------------- prep: out_W -> bf16 padded ----------------
__global__ __launch_bounds__(256) void k_prep(const float* __restrict__ out_W)
{
    size_t idx = (size_t)blockIdx.x * 256 + threadIdx.x;
    if (idx >= (size_t)RNN_ * V1P) return;
    int k = (int)(idx / V1P), v = (int)(idx % V1P);
    float w = (v < V1) ? out_W[(size_t)k * V1 + v] : 0.f;
    d_OWb[idx] = __float2bfloat16(w);
}

// =====================================================================
// k_wpg: WPG[16384,2560] = emb[words] @ [W_ih_word | w2g], tf32 WMMA.
// grid (20 n-tiles, 128 m-tiles), 128x128 tile, K=512.
// =====================================================================
#define WPG_SMEM 66048
__global__ __launch_bounds__(256) void k_wpg(
    const int* __restrict__ seqz, const float* __restrict__ emb,
    const float* __restrict__ W_ih, const float* __restrict__ w2g_W)
{
    extern __shared__ char smraw[];
    float* As_ = (float*)smraw;                 // [2][128][32]
    float* Bs_ = (float*)(smraw + 32768);       // [2][32][128]
    int*  stok = (int*)(smraw + 65536);         // [128]
    const int tid = threadIdx.x;
    const int n0 = blockIdx.x * 128;
    const int m0 = blockIdx.y * 128;
    const int wid = tid >> 5;
    const int warp_m = wid >> 1;                // 0..3
    const int warp_n = wid & 1;                 // 0..1
    uint32_t aB = (uint32_t)__cvta_generic_to_shared(As_);
    uint32_t bB = (uint32_t)__cvta_generic_to_shared(Bs_);

    if (tid < 128) {
        int row = m0 + tid;
        int t = row >> 8, b = row & 255;
        stok[tid] = (t == 0) ? (VOCAB_ + 1) : seqz[b * T_ + t - 1];
    }
    __syncthreads();

    auto issueA = [&](int s, int d) {
        int k0 = s * 32;
        #pragma unroll
        for (int j = 0; j < 4; j++) {
            int idx = tid + j * 256;
            int r = idx >> 3, sg = (idx & 7) << 2;
            cp16(aB + (uint32_t)((d * 4096 + r * 32 + sg) * 4),
                 emb + (size_t)stok[r] * RNN_ + k0 + sg);
        }
    };
    auto issueB = [&](int s, int d) {
        int k0 = s * 32;
        #pragma unroll
        for (int j = 0; j < 4; j++) {
            int idx = tid + j * 256;
            int kr = idx >> 5, c4 = (idx & 31) << 2;
            int kk = k0 + kr;
            const float* src = (n0 < 2048)
                ? W_ih + (size_t)(VIS_ + kk) * 2048 + n0 + c4
                : w2g_W + (size_t)kk * RNN_ + (n0 - 2048) + c4;
            cp16(bB + (uint32_t)((d * 4096 + kr * 128 + c4) * 4), src);
        }
    };

    wmma::fragment<wmma::accumulator, 16, 16, 8, float> acc[2][4];
    #pragma unroll
    for (int i = 0; i < 2; i++)
        #pragma unroll
        for (int j = 0; j < 4; j++) wmma::fill_fragment(acc[i][j], 0.f);

    issueA(0, 0); issueB(0, 0); cp_commit();
    for (int s = 0; s < 16; s++) {
        if (s < 15) { issueA(s + 1, (s + 1) & 1); issueB(s + 1, (s + 1) & 1); cp_commit(); cp_wait<1>(); }
        else        { cp_wait<0>(); }
        __syncthreads();
        int d = s & 1;
        #pragma unroll
        for (int k8 = 0; k8 < 4; k8++) {
            wmma::fragment<wmma::matrix_a, 16, 16, 8, wmma::precision::tf32, wmma::row_major> af[2];
            wmma::fragment<wmma::matrix_b, 16, 16, 8, wmma::precision::tf32, wmma::row_major> bf[4];
            #pragma unroll
            for (int i = 0; i < 2; i++)
                LOAD_A_TF32(af[i], As_ + d * 4096 + (warp_m * 32 + i * 16) * 32 + k8 * 8, 32);
            #pragma unroll
            for (int j = 0; j < 4; j++)
                LOAD_A_TF32(bf[j], Bs_ + d * 4096 + (k8 * 8) * 128 + warp_n * 64 + j * 16, 128);
            #pragma unroll
            for (int i = 0; i < 2; i++)
                #pragma unroll
                for (int j = 0; j < 4; j++)
                    wmma::mma_sync(acc[i][j], af[i], bf[j], acc[i][j]);
        }
        __syncthreads();
    }
    #pragma unroll
    for (int i = 0; i < 2; i++)
        #pragma unroll
        for (int j = 0; j < 4; j++)
            wmma::store_matrix_sync(
                d_WPG + (size_t)(m0 + warp_m * 32 + i * 16) * GEXT + n0 + warp_n * 64 + j * 16,
                acc[i][j], GEXT, wmma::mem_row_major);
}

// =====================================================================
// k_rnn v3: 128 persistent CTAs. CTA (ct&1 -> 128 batch rows,
// ct>>1 -> 8 hidden units x 5 gates = 40 cols padded 48).
// Recurrence weights (512x48 fp32) RESIDENT in smem all 64 steps.
// Per step: stream h slices (cp.async), tf32 WMMA, CTA-local pointwise.
// =====================================================================
#define RNN_SMEM 155648
__global__ __launch_bounds__(256) void k_rnn(
    const float* __restrict__ vis,
    const float* __restrict__ W_ih,    const float* __restrict__ W_hh,
    const float* __restrict__ b_lstm,
    const float* __restrict__ vis2g_W, const float* __restrict__ vis2g_b,
    const float* __restrict__ h2g_W)
{
    extern __shared__ char smraw[];
    float* Wres = (float*)smraw;                  // [512][48] resident weights
    float* As_  = (float*)(smraw + 98304);        // [2][128][32]; aliased gsm[128][48]
    float* vpgr = (float*)(smraw + 131072);       // [128][40]
    float* cst  = (float*)(smraw + 151552);       // [128][8]
    float* gsm  = As_;
    float* bscr = Wres;                           // prologue B scratch [2][32][48]

    const int tid = threadIdx.x;
    const int ct  = blockIdx.x;
    const int wid = tid >> 5;
    const int u0  = (ct >> 1) * 8;
    const int m0  = (ct & 1) * 128;
    unsigned ls = 0;
    uint32_t aB = (uint32_t)__cvta_generic_to_shared(As_);
    uint32_t wB = (uint32_t)__cvta_generic_to_shared(Wres);

    // ---- init: cst zero, pad cols of bscr, own h0 slice zero ----
    #pragma unroll
    for (int j = 0; j < 4; j++) {
        int e = tid + j * 256;                    // 0..1023
        cst[e] = 0.f;
        int r = e >> 3, u = e & 7;
        d_hbuf[0][(m0 + r) * RNN_ + u0 + u] = 0.f;
    }
    #pragma unroll
    for (int j = 0; j < 2; j++) {
        int e = tid + j * 256;                    // 0..511
        int d = e >> 8, rr = (e >> 3) & 31, c = 40 + (e & 7);
        bscr[d * 1536 + rr * 48 + c] = 0.f;
    }
    __syncthreads();

    // ---- prologue GEMM: vis-part gates (K=1024) -> gsm ----
    {
        wmma::fragment<wmma::accumulator, 16, 16, 8, float> acc[3];
        #pragma unroll
        for (int f = 0; f < 3; f++) wmma::fill_fragment(acc[f], 0.f);

        auto issA = [&](int s, int d) {
            int k0 = s * 32;
            #pragma unroll
            for (int j = 0; j < 4; j++) {
                int idx = tid + j * 256;
                int r = idx >> 3, sg = (idx & 7) << 2;
                cp16(aB + (uint32_t)((d * 4096 + r * 32 + sg) * 4),
                     vis + (size_t)(m0 + r) * VIS_ + k0 + sg);
            }
        };
        auto issB = [&](int s, int d) {
            int k0 = s * 32;
            #pragma unroll
            for (int j = 0; j < 2; j++) {
                int e = tid + j * 256;
                if (e < 320) {
                    int r = e / 10, q = e % 10;
                    int g = q >> 1, c4 = (q & 1) << 2;
                    int kk = k0 + r;
                    const float* src = (g < 4)
                        ? W_ih + (size_t)kk * 2048 + g * 512 + u0 + c4
                        : vis2g_W + (size_t)kk * RNN_ + u0 + c4;
                    cp16(wB + (uint32_t)((d * 1536 + r * 48 + q * 4) * 4), src);
                }
            }
        };

        issA(0, 0); issB(0, 0); cp_commit();
        for (int s = 0; s < 32; s++) {
            if (s < 31) { issA(s + 1, (s + 1) & 1); issB(s + 1, (s + 1) & 1); cp_commit(); cp_wait<1>(); }
            else        { cp_wait<0>(); }
            __syncthreads();
            int d = s & 1;
            #pragma unroll
            for (int k8 = 0; k8 < 4; k8++) {
                wmma::fragment<wmma::matrix_a, 16, 16, 8, wmma::precision::tf32, wmma::row_major> af;
                LOAD_A_TF32(af, As_ + d * 4096 + (wid * 16) * 32 + k8 * 8, 32);
                #pragma unroll
                for (int f = 0; f < 3; f++) {
                    wmma::fragment<wmma::matrix_b, 16, 16, 8, wmma::precision::tf32, wmma::row_major> bf;
                    LOAD_A_TF32(bf, bscr + d * 1536 + (k8 * 8) * 48 + f * 16, 48);
                    wmma::mma_sync(acc[f], af, bf, acc[f]);
                }
            }
            __syncthreads();
        }
        #pragma unroll
        for (int f = 0; f < 3; f++)
            wmma::store_matrix_sync(gsm + (wid * 16) * 48 + f * 16, acc[f], 48, wmma::mem_row_major);
        __syncthreads();
    }

    // ---- load resident recurrence weights (overwrites bscr) ----
    #pragma unroll
    for (int j = 0; j < 20; j++) {
        int e = tid + j * 256;                    // 0..5119
        int r = e / 10, q = e % 10;
        int g = q >> 1, c4 = (q & 1) << 2;
        const float* src = (g < 4)
            ? W_hh + (size_t)r * 2048 + g * 512 + u0 + c4
            : h2g_W + (size_t)r * RNN_ + u0 + c4;
        cp16(wB + (uint32_t)((r * 48 + q * 4) * 4), src);
    }
    cp_commit();

    // vpgr = gsm + bias (gsm lives in As region; safe until first step's issue)
    #pragma unroll
    for (int j = 0; j < 20; j++) {
        int e = tid + j * 256;                    // 0..5119 = 128 x 40
        int r = e / 40, q = e % 40;
        int g = q >> 3, u = q & 7;
        float bias = (g < 4) ? b_lstm[g * 512 + u0 + u] : vis2g_b[u0 + u];
        vpgr[r * 40 + q] = gsm[r * 48 + q] + bias;
    }
    cp_wait<0>();
    __syncthreads();
    // zero weight pad cols 40..47
    #pragma unroll
    for (int j = 0; j < 16; j++) {
        int e = tid + j * 256;                    // 0..4095
        int r = e >> 3, c = 40 + (e & 7);
        Wres[r * 48 + c] = 0.f;
    }
    gbar(ls);                                     // barrier #1

    // ---- 64 steps ----
    for (int t = 0; t < T_; t++) {
        const float* hb = d_hbuf[t & 1];
        float* hn = d_hbuf[(t & 1) ^ 1];

        auto issH = [&](int s, int d) {
            int k0 = s * 32;
            #pragma unroll
            for (int j = 0; j < 4; j++) {
                int idx = tid + j * 256;
                int r = idx >> 3, sg = (idx & 7) << 2;
                cp16(aB + (uint32_t)((d * 4096 + r * 32 + sg) * 4),
                     hb + (size_t)(m0 + r) * RNN_ + k0 + sg);
            }
        };

        wmma::fragment<wmma::accumulator, 16, 16, 8, float> acc[3];
        #pragma unroll
        for (int f = 0; f < 3; f++) wmma::fill_fragment(acc[f], 0.f);

        issH(0, 0); cp_commit();
        for (int s = 0; s < 16; s++) {
            if (s < 15) { issH(s + 1, (s + 1) & 1); cp_commit(); cp_wait<1>(); }
            else        { cp_wait<0>(); }
            __syncthreads();
            int d = s & 1;
            #pragma unroll
            for (int k8 = 0; k8 < 4; k8++) {
                wmma::fragment<wmma::matrix_a, 16, 16, 8, wmma::precision::tf32, wmma::row_major> af;
                LOAD_A_TF32(af, As_ + d * 4096 + (wid * 16) * 32 + k8 * 8, 32);
                #pragma unroll
                for (int f = 0; f < 3; f++) {
                    wmma::fragment<wmma::matrix_b, 16, 16, 8, wmma::precision::tf32, wmma::row_major> bf;
                    LOAD_A_TF32(bf, Wres + (s * 32 + k8 * 8) * 48 + f * 16, 48);
                    wmma::mma_sync(acc[f], af, bf, acc[f]);
                }
            }
            __syncthreads();
        }
        #pragma unroll
        for (int f = 0; f < 3; f++)
            wmma::store_matrix_sync(gsm + (wid * 16) * 48 + f * 16, acc[f], 48, wmma::mem_row_major);
        __syncthreads();

        // pointwise: 128 rows x 8 units, CTA-local
        const float* wpbase = d_WPG + (size_t)(t * 256 + m0) * GEXT;
        #pragma unroll
        for (int j = 0; j < 4; j++) {
            int e = tid + j * 256;                // 0..1023
            int r = e >> 3, u = e & 7;
            const float* gg = gsm + r * 48;
            const float* vp = vpgr + r * 40;
            const float* wp = wpbase + (size_t)r * GEXT + u0 + u;
            float ig = gg[u]      + vp[u]      + wp[0];
            float fg = gg[8 + u]  + vp[8 + u]  + wp[512];
            float g_ = gg[16 + u] + vp[16 + u] + wp[1024];
            float og = gg[24 + u] + vp[24 + u] + wp[1536];
            float gp = gg[32 + u] + vp[32 + u] + wp[2048];
            float cold = cst[e];
            float cn = sig_f(fg) * cold + sig_f(ig) * tanh_f(g_);
            float tc = tanh_f(cn);
            cst[e] = cn;
            hn[(m0 + r) * RNN_ + u0 + u] = sig_f(og) * tc;
            d_Sb[(size_t)(t * 256 + m0 + r) * RNN_ + u0 + u] =
                __float2bfloat16(sig_f(gp) * tc);
        }
        gbar(ls);                                 // h(t) published
    }
    gbar(ls);   // total barriers = 1 + 64 + 1 = 66 (even -> state restored)
}

// =====================================================================
// k_lse: unchanged from R9 (bf16 WMMA + cp.async + f16x2 exp).
// =====================================================================
#define LSE_SMEM 212992
#define NCH 157
__global__ __launch_bounds__(256) void k_lse(
    const float* __restrict__ out_b,
    const int* __restrict__ seqz, float* __restrict__ out)
{
    extern __shared__ unsigned char dyn[];
    __nv_bfloat16* Asm = (__nv_bfloat16*)dyn;
    __nv_bfloat16* Bsm = (__nv_bfloat16*)(dyn + 65536);
    float*         Csm = (float*)(dyn + 196608);
    __shared__ float s_tgt[64];
    __shared__ int   s_tg[64];
    __shared__ float red_s[4][64];

    const int tid = threadIdx.x;
    const int m0  = blockIdx.x * 64;
    const int wid = tid >> 5;
    const int warp_m = wid >> 1;
    const int warp_n = wid & 1;
    uint32_t bB = (uint32_t)__cvta_generic_to_shared(Bsm);

    if (tid < 64) {
        int r = m0 + tid;
        int t = r >> 8, b = r & 255;
        s_tg[tid] = seqz[b * T_ + t];
    }

    #pragma unroll
    for (int i = 0; i < 16; i++) {
        int idx = tid + i * 256;
        int r = idx >> 6, c = idx & 63;
        ((uint4*)Asm)[idx] = ((const uint4*)(d_Sb + (size_t)(m0 + r) * RNN_))[c];
    }
    __syncthreads();

    auto issueB = [&](int ch, int d) {
        int v0 = ch * 64;
        #pragma unroll
        for (int j = 0; j < 16; j++) {
            int idx = tid + j * 256;
            int k = idx >> 3, c8 = (idx & 7) << 3;
            cp16(bB + (uint32_t)(d * 65536 + (k * 64 + c8) * 2),
                 d_OWb + (size_t)k * V1P + v0 + c8);
        }
    };

    const int row = tid >> 2;
    const int qtr = tid & 3;
    const int mytg = s_tg[row];
    float rs = 0.f;

    issueB(0, 0); cp_commit();
    for (int c = 0; c < NCH; c++) {
        if (c < NCH - 1) { issueB(c + 1, (c + 1) & 1); cp_commit(); cp_wait<1>(); }
        else             { cp_wait<0>(); }
        __syncthreads();

        const __nv_bfloat16* Bcur = Bsm + (c & 1) * 32768;
        wmma::fragment<wmma::accumulator, 16, 16, 16, float> acc[2];
        wmma::fill_fragment(acc[0], 0.f);
        wmma::fill_fragment(acc[1], 0.f);
        #pragma unroll
        for (int k = 0; k < 32; k++) {
            wmma::fragment<wmma::matrix_a, 16, 16, 16, __nv_bfloat16, wmma::row_major> af;
            wmma::load_matrix_sync(af, Asm + (warp_m * 16) * 512 + k * 16, 512);
            #pragma unroll
            for (int nf = 0; nf < 2; nf++) {
                wmma::fragment<wmma::matrix_b, 16, 16, 16, __nv_bfloat16, wmma::row_major> bf;
                wmma::load_matrix_sync(bf, Bcur + (k * 16) * 64 + warp_n * 32 + nf * 16, 64);
                wmma::mma_sync(acc[nf], af, bf, acc[nf]);
            }
        }
        #pragma unroll
        for (int nf = 0; nf < 2; nf++)
            wmma::store_matrix_sync(Csm + (warp_m * 16) * 64 + warp_n * 32 + nf * 16,
                                    acc[nf], 64, wmma::mem_row_major);
        __syncthreads();

        int v0 = c * 64;
        float lsum = 0.f;
        #pragma unroll
        for (int j = 0; j < 8; j++) {
            int cc = (qtr << 4) + 2 * j;
            int v = v0 + cc;
            float l0 = (v     < V1) ? (Csm[row * 64 + cc]     + out_b[v])     : -1e4f;
            float l1 = (v + 1 < V1) ? (Csm[row * 64 + cc + 1] + out_b[v + 1]) : -1e4f;
            uint32_t h2, e2;
            asm("cvt.rn.f16x2.f32 %0, %1, %2;" : "=r"(h2) : "f"(l1 * LOG2E), "f"(l0 * LOG2E));
            asm("ex2.approx.f16x2 %0, %1;" : "=r"(e2) : "r"(h2));
            __half2 hh = *reinterpret_cast<__half2*>(&e2);
            float2 ff = __half22float2(hh);
            lsum += ff.x + ff.y;
        }
        rs += lsum;
        if (mytg >= v0 && mytg < v0 + 64 && ((mytg - v0) >> 4) == qtr)
            s_tgt[row] = Csm[row * 64 + (mytg - v0)] + out_b[mytg];
        __syncthreads();
    }

    red_s[qtr][row] = rs;
    __syncthreads();
    if (tid < 64) {
        int r = m0 + tid;
        float S = red_s[0][tid] + red_s[1][tid] + red_s[2][tid] + red_s[3][tid];
        float lse = logf(S);
        int t = r >> 8, b = r & 255;
        float mask = (t == 0) ? 1.f : ((seqz[b * T_ + (t - 1)] != 0) ? 1.f : 0.f);
        out[r] = (s_tgt[tid] - lse) * mask;
    }
}

// ---------------- launch ----------------
extern "C" void kernel_launch(void* const* d_in, const int* in_sizes, int n_in,
                              void* d_out, int out_size)
{
    const float *vis = 0, *emb = 0, *W_ih = 0, *W_hh = 0, *b_lstm = 0;
    const float *vis2g_W = 0, *vis2g_b = 0, *w2g_W = 0, *h2g_W = 0;
    const float *out_W = 0, *out_b = 0;
    const int *seqz = 0;
    int trio[3]; int ntrio = 0;
    for (int i = 0; i < n_in; i++) {
        switch (in_sizes[i]) {
            case 16384:   seqz    = (const int*)  d_in[i]; break;
            case 5121024: emb     = (const float*)d_in[i]; break;
            case 3145728: W_ih    = (const float*)d_in[i]; break;
            case 1048576: W_hh    = (const float*)d_in[i]; break;
            case 2048:    b_lstm  = (const float*)d_in[i]; break;
            case 524288:  vis2g_W = (const float*)d_in[i]; break;
            case 512:     vis2g_b = (const float*)d_in[i]; break;
            case 5120512: out_W   = (const float*)d_in[i]; break;
            case 10001:   out_b   = (const float*)d_in[i]; break;
            case 262144:  if (ntrio < 3) trio[ntrio++] = i; break;
            default: break;
        }
    }
    if (ntrio == 3) {
        vis   = (const float*)d_in[trio[0]];
        w2g_W = (const float*)d_in[trio[1]];
        h2g_W = (const float*)d_in[trio[2]];
    }
    if (!vis)     vis     = (const float*)d_in[0];
    if (!seqz)    seqz    = (const int*)  d_in[1];
    if (!emb)     emb     = (const float*)d_in[2];
    if (!W_ih)    W_ih    = (const float*)d_in[3];
    if (!W_hh)    W_hh    = (const float*)d_in[4];
    if (!b_lstm)  b_lstm  = (const float*)d_in[5];
    if (!vis2g_W) vis2g_W = (const float*)d_in[6];
    if (!vis2g_b) vis2g_b = (const float*)d_in[7];
    if (!w2g_W)   w2g_W   = (const float*)d_in[8];
    if (!h2g_W)   h2g_W   = (const float*)d_in[9];
    if (!out_W)   out_W   = (const float*)d_in[10];
    if (!out_b)   out_b   = (const float*)d_in[11];
    float* out = (float*)d_out;

    cudaFuncSetAttribute(k_wpg, cudaFuncAttributeMaxDynamicSharedMemorySize, WPG_SMEM);
    cudaFuncSetAttribute(k_rnn, cudaFuncAttributeMaxDynamicSharedMemorySize, RNN_SMEM);
    cudaFuncSetAttribute(k_lse, cudaFuncAttributeMaxDynamicSharedMemorySize, LSE_SMEM);

    k_prep<<<(int)(((size_t)RNN_ * V1P + 255) / 256), 256>>>(out_W);
    k_wpg<<<dim3(20, 128), 256, WPG_SMEM>>>(seqz, emb, W_ih, w2g_W);
    k_rnn<<<NCTA, 256, RNN_SMEM>>>(vis, W_ih, W_hh, b_lstm, vis2g_W, vis2g_b, h2g_W);
    k_lse<<<TB / 64, 256, LSE_SMEM>>>(out_b, seqz, out);
}

// round 11
// speedup vs baseline: 1.9110x; 1.1536x over previous
#include <cuda_runtime.h>
#include <cuda_bf16.h>
#include <cuda_fp16.h>
#include <mma.h>
#include <math.h>
#include <stdint.h>

using namespace nvcuda;

#define B_     256
#define T_     64
#define VOCAB_ 10000
#define V1     10001
#define V1P    10240
#define VIS_   1024
#define RNN_   512
#define GEXT   2560
#define TB     16384
#define NCTA   128
#define LOG2E  1.4426950408889634f

// ---------------- scratch ----------------
__device__ __nv_bfloat16 d_hbuf[2][B_ * RNN_];
__device__ float d_WPG[(size_t)TB * GEXT];            // word-part gates (168 MB)
__device__ __nv_bfloat16 d_Sb [(size_t)TB * RNN_];    // sentinel states bf16
__device__ __nv_bfloat16 d_OWb[(size_t)RNN_ * V1P];   // out_W bf16 padded

__device__ unsigned g_cnt = 0;
__device__ volatile unsigned g_sense = 0;

__device__ __forceinline__ void gbar(unsigned &ls)
{
    __syncthreads();
    if (threadIdx.x == 0) {
        ls ^= 1u;
        __threadfence();
        if (atomicAdd(&g_cnt, 1u) == NCTA - 1u) {
            g_cnt = 0u;
            __threadfence();
            g_sense = ls;
        } else {
            while (g_sense != ls) { }
            __threadfence();
        }
    }
    __syncthreads();
}

__device__ __forceinline__ float tanh_f(float x)
{
    float y;
    asm("tanh.approx.f32 %0, %1;" : "=f"(y) : "f"(x));
    return y;
}
__device__ __forceinline__ float sig_f(float x)
{
    return fmaf(0.5f, tanh_f(0.5f * x), 0.5f);
}

__device__ __forceinline__ void cp16(uint32_t dst, const void* src)
{
    asm volatile("cp.async.cg.shared.global [%0], [%1], 16;" :: "r"(dst), "l"(src));
}
__device__ __forceinline__ void cp_commit()
{
    asm volatile("cp.async.commit_group;" ::: "memory");
}
template<int N> __device__ __forceinline__ void cp_wait()
{
    asm volatile("cp.async.wait_group %0;" :: "n"(N) : "memory");
}

#define LOAD_A_TF32(frag, ptr, ldm) do { \
    wmma::load_matrix_sync(frag, ptr, ldm); \
    for (int _e = 0; _e < (frag).num_elements; _e++) \
        (frag).x[_e] = wmma::__float_to_tf32((frag).x[_e]); \
} while (0)

// ---------------- prep: out_W -> bf16 padded ----------------
__global__ __launch_bounds__(256) void k_prep(const float* __restrict__ out_W)
{
    size_t idx = (size_t)blockIdx.x * 256 + threadIdx.x;
    if (idx >= (size_t)RNN_ * V1P) return;
    int k = (int)(idx / V1P), v = (int)(idx % V1P);
    float w = (v < V1) ? out_W[(size_t)k * V1 + v] : 0.f;
    d_OWb[idx] = __float2bfloat16(w);
}

// =====================================================================
// k_wpg: WPG[16384,2560] = emb[words] @ [W_ih_word | w2g], tf32 WMMA.
// =====================================================================
#define WPG_SMEM 66048
__global__ __launch_bounds__(256) void k_wpg(
    const int* __restrict__ seqz, const float* __restrict__ emb,
    const float* __restrict__ W_ih, const float* __restrict__ w2g_W)
{
    extern __shared__ char smraw[];
    float* As_ = (float*)smraw;                 // [2][128][32]
    float* Bs_ = (float*)(smraw + 32768);       // [2][32][128]
    int*  stok = (int*)(smraw + 65536);         // [128]
    const int tid = threadIdx.x;
    const int n0 = blockIdx.x * 128;
    const int m0 = blockIdx.y * 128;
    const int wid = tid >> 5;
    const int warp_m = wid >> 1;
    const int warp_n = wid & 1;
    uint32_t aB = (uint32_t)__cvta_generic_to_shared(As_);
    uint32_t bB = (uint32_t)__cvta_generic_to_shared(Bs_);

    if (tid < 128) {
        int row = m0 + tid;
        int t = row >> 8, b = row & 255;
        stok[tid] = (t == 0) ? (VOCAB_ + 1) : seqz[b * T_ + t - 1];
    }
    __syncthreads();

    auto issueA = [&](int s, int d) {
        int k0 = s * 32;
        #pragma unroll
        for (int j = 0; j < 4; j++) {
            int idx = tid + j * 256;
            int r = idx >> 3, sg = (idx & 7) << 2;
            cp16(aB + (uint32_t)((d * 4096 + r * 32 + sg) * 4),
                 emb + (size_t)stok[r] * RNN_ + k0 + sg);
        }
    };
    auto issueB = [&](int s, int d) {
        int k0 = s * 32;
        #pragma unroll
        for (int j = 0; j < 4; j++) {
            int idx = tid + j * 256;
            int kr = idx >> 5, c4 = (idx & 31) << 2;
            int kk = k0 + kr;
            const float* src = (n0 < 2048)
                ? W_ih + (size_t)(VIS_ + kk) * 2048 + n0 + c4
                : w2g_W + (size_t)kk * RNN_ + (n0 - 2048) + c4;
            cp16(bB + (uint32_t)((d * 4096 + kr * 128 + c4) * 4), src);
        }
    };

    wmma::fragment<wmma::accumulator, 16, 16, 8, float> acc[2][4];
    #pragma unroll
    for (int i = 0; i < 2; i++)
        #pragma unroll
        for (int j = 0; j < 4; j++) wmma::fill_fragment(acc[i][j], 0.f);

    issueA(0, 0); issueB(0, 0); cp_commit();
    for (int s = 0; s < 16; s++) {
        if (s < 15) { issueA(s + 1, (s + 1) & 1); issueB(s + 1, (s + 1) & 1); cp_commit(); cp_wait<1>(); }
        else        { cp_wait<0>(); }
        __syncthreads();
        int d = s & 1;
        #pragma unroll
        for (int k8 = 0; k8 < 4; k8++) {
            wmma::fragment<wmma::matrix_a, 16, 16, 8, wmma::precision::tf32, wmma::row_major> af[2];
            wmma::fragment<wmma::matrix_b, 16, 16, 8, wmma::precision::tf32, wmma::row_major> bf[4];
            #pragma unroll
            for (int i = 0; i < 2; i++)
                LOAD_A_TF32(af[i], As_ + d * 4096 + (warp_m * 32 + i * 16) * 32 + k8 * 8, 32);
            #pragma unroll
            for (int j = 0; j < 4; j++)
                LOAD_A_TF32(bf[j], Bs_ + d * 4096 + (k8 * 8) * 128 + warp_n * 64 + j * 16, 128);
            #pragma unroll
            for (int i = 0; i < 2; i++)
                #pragma unroll
                for (int j = 0; j < 4; j++)
                    wmma::mma_sync(acc[i][j], af[i], bf[j], acc[i][j]);
        }
        __syncthreads();
    }
    #pragma unroll
    for (int i = 0; i < 2; i++)
        #pragma unroll
        for (int j = 0; j < 4; j++)
            wmma::store_matrix_sync(
                d_WPG + (size_t)(m0 + warp_m * 32 + i * 16) * GEXT + n0 + warp_n * 64 + j * 16,
                acc[i][j], GEXT, wmma::mem_row_major);
}

// =====================================================================
// k_rnn v4: 128 persistent CTAs, bf16 resident recurrence weights.
// CTA (ct&1 -> 128 batch rows, ct>>1 -> 8 units x 5 gates = 40 cols/48).
// Per step: wp tile + h slices via cp.async, bf16 WMMA k16, CTA-local
// pointwise from smem, 1 global barrier.
// =====================================================================
// smem layout (bytes):
//   0      Wres  bf16 [512][48]          49152
//   49152  As    bf16 [2][128][64]       32768   (alias: prologue f32 A [2][128][32]; gsm f32 [128][48])
//   81920  vpgr  f32  [128][40]          20480
//   102400 wpsm  f32  [128][40]          20480
//   122880 cst   f32  [128][8]            4096
//   126976 bscr  f32  [2][32][48]        12288   (prologue B)
#define RNN_SMEM 139264
__global__ __launch_bounds__(256) void k_rnn(
    const float* __restrict__ vis,
    const float* __restrict__ W_ih,    const float* __restrict__ W_hh,
    const float* __restrict__ b_lstm,
    const float* __restrict__ vis2g_W, const float* __restrict__ vis2g_b,
    const float* __restrict__ h2g_W)
{
    extern __shared__ char smraw[];
    __nv_bfloat16* Wres = (__nv_bfloat16*)smraw;
    __nv_bfloat16* Asb  = (__nv_bfloat16*)(smraw + 49152);
    float* Asf  = (float*)(smraw + 49152);        // prologue A (f32)
    float* gsm  = (float*)(smraw + 49152);        // gates result (f32, after GEMM)
    float* vpgr = (float*)(smraw + 81920);
    float* wpsm = (float*)(smraw + 102400);
    float* cst  = (float*)(smraw + 122880);
    float* bscr = (float*)(smraw + 126976);

    const int tid = threadIdx.x;
    const int ct  = blockIdx.x;
    const int wid = tid >> 5;                      // 0..7, 16 rows each
    const int u0  = (ct >> 1) * 8;
    const int m0  = (ct & 1) * 128;
    unsigned ls = 0;
    uint32_t aB = (uint32_t)__cvta_generic_to_shared(smraw + 49152);
    uint32_t bB = (uint32_t)__cvta_generic_to_shared(bscr);
    uint32_t wpB = (uint32_t)__cvta_generic_to_shared(wpsm);

    // ---- init: cst zero, bscr pad cols, own h0 slice zero (bf16) ----
    #pragma unroll
    for (int j = 0; j < 4; j++) {
        int e = tid + j * 256;                     // 0..1023
        cst[e] = 0.f;
        int r = e >> 3, u = e & 7;
        d_hbuf[0][(m0 + r) * RNN_ + u0 + u] = __float2bfloat16(0.f);
    }
    #pragma unroll
    for (int j = 0; j < 2; j++) {
        int e = tid + j * 256;                     // 0..511
        int d = e >> 8, rr = (e >> 3) & 31, c = 40 + (e & 7);
        bscr[d * 1536 + rr * 48 + c] = 0.f;
    }
    __syncthreads();

    // ---- prologue GEMM (tf32): vis-part gates, K=1024, 32 slices of 32 ----
    {
        wmma::fragment<wmma::accumulator, 16, 16, 8, float> acc[3];
        #pragma unroll
        for (int f = 0; f < 3; f++) wmma::fill_fragment(acc[f], 0.f);

        auto issA = [&](int s, int d) {
            int k0 = s * 32;
            #pragma unroll
            for (int j = 0; j < 4; j++) {
                int idx = tid + j * 256;
                int r = idx >> 3, sg = (idx & 7) << 2;
                cp16(aB + (uint32_t)((d * 4096 + r * 32 + sg) * 4),
                     vis + (size_t)(m0 + r) * VIS_ + k0 + sg);
            }
        };
        auto issB = [&](int s, int d) {
            int k0 = s * 32;
            #pragma unroll
            for (int j = 0; j < 2; j++) {
                int e = tid + j * 256;
                if (e < 320) {
                    int r = e / 10, q = e % 10;
                    int g = q >> 1, c4 = (q & 1) << 2;
                    int kk = k0 + r;
                    const float* src = (g < 4)
                        ? W_ih + (size_t)kk * 2048 + g * 512 + u0 + c4
                        : vis2g_W + (size_t)kk * RNN_ + u0 + c4;
                    cp16(bB + (uint32_t)((d * 1536 + r * 48 + q * 4) * 4), src);
                }
            }
        };

        issA(0, 0); issB(0, 0); cp_commit();
        for (int s = 0; s < 32; s++) {
            if (s < 31) { issA(s + 1, (s + 1) & 1); issB(s + 1, (s + 1) & 1); cp_commit(); cp_wait<1>(); }
            else        { cp_wait<0>(); }
            __syncthreads();
            int d = s & 1;
            #pragma unroll
            for (int k8 = 0; k8 < 4; k8++) {
                wmma::fragment<wmma::matrix_a, 16, 16, 8, wmma::precision::tf32, wmma::row_major> af;
                LOAD_A_TF32(af, Asf + d * 4096 + (wid * 16) * 32 + k8 * 8, 32);
                #pragma unroll
                for (int f = 0; f < 3; f++) {
                    wmma::fragment<wmma::matrix_b, 16, 16, 8, wmma::precision::tf32, wmma::row_major> bf;
                    LOAD_A_TF32(bf, bscr + d * 1536 + (k8 * 8) * 48 + f * 16, 48);
                    wmma::mma_sync(acc[f], af, bf, acc[f]);
                }
            }
            __syncthreads();
        }
        #pragma unroll
        for (int f = 0; f < 3; f++)
            wmma::store_matrix_sync(gsm + (wid * 16) * 48 + f * 16, acc[f], 48, wmma::mem_row_major);
        __syncthreads();
    }

    // vpgr = gsm + bias
    #pragma unroll
    for (int j = 0; j < 20; j++) {
        int e = tid + j * 256;                     // 0..5119 = 128 x 40
        int r = e / 40, q = e % 40;
        int g = q >> 3, u = q & 7;
        float bias = (g < 4) ? b_lstm[g * 512 + u0 + u] : vis2g_b[u0 + u];
        vpgr[r * 40 + q] = gsm[r * 48 + q] + bias;
    }
    __syncthreads();

    // ---- load resident bf16 recurrence weights [512][48] ----
    #pragma unroll
    for (int j = 0; j < 80; j++) {
        int e = tid + j * 256;                     // 0..20479
        int k = e / 40, q = e % 40;
        int g = q >> 3, u = q & 7;
        float w = (g < 4) ? W_hh[(size_t)k * 2048 + g * 512 + u0 + u]
                          : h2g_W[(size_t)k * RNN_ + u0 + u];
        Wres[k * 48 + q] = __float2bfloat16(w);
    }
    #pragma unroll
    for (int j = 0; j < 16; j++) {
        int e = tid + j * 256;                     // 0..4095
        int k = e >> 3, c = 40 + (e & 7);
        Wres[k * 48 + c] = __float2bfloat16(0.f);
    }
    gbar(ls);                                      // barrier #1

    // ---- 64 steps ----
    for (int t = 0; t < T_; t++) {
        const __nv_bfloat16* hb = d_hbuf[t & 1];
        __nv_bfloat16* hn = d_hbuf[(t & 1) ^ 1];
        const float* wpbase = d_WPG + (size_t)(t * 256 + m0) * GEXT;

        auto issH = [&](int s, int d) {
            int k0 = s * 64;
            #pragma unroll
            for (int j = 0; j < 4; j++) {
                int idx = tid + j * 256;           // 0..1023
                int r = idx >> 3, c8 = (idx & 7) << 3;   // 8 bf16 = 16B
                cp16(aB + (uint32_t)((d * 128 + r) * 64 + c8) * 2,
                     hb + (size_t)(m0 + r) * RNN_ + k0 + c8);
            }
        };
        // wp tile prefetch (group shared with slice 0)
        {
            #pragma unroll
            for (int j = 0; j < 5; j++) {
                int e = tid + j * 256;             // 0..1279
                int r = e / 10, q = e % 10;
                int g = q >> 1, half = q & 1;
                cp16(wpB + (uint32_t)((r * 40 + g * 8 + half * 4) * 4),
                     wpbase + (size_t)r * GEXT + g * 512 + u0 + half * 4);
            }
        }

        wmma::fragment<wmma::accumulator, 16, 16, 16, float> acc[3];
        #pragma unroll
        for (int f = 0; f < 3; f++) wmma::fill_fragment(acc[f], 0.f);

        issH(0, 0); cp_commit();
        for (int s = 0; s < 8; s++) {
            if (s < 7) { issH(s + 1, (s + 1) & 1); cp_commit(); cp_wait<1>(); }
            else       { cp_wait<0>(); }
            __syncthreads();
            int d = s & 1;
            #pragma unroll
            for (int k16 = 0; k16 < 4; k16++) {
                wmma::fragment<wmma::matrix_a, 16, 16, 16, __nv_bfloat16, wmma::row_major> af;
                wmma::load_matrix_sync(af, Asb + (d * 128 + wid * 16) * 64 + k16 * 16, 64);
                #pragma unroll
                for (int f = 0; f < 3; f++) {
                    wmma::fragment<wmma::matrix_b, 16, 16, 16, __nv_bfloat16, wmma::row_major> bf;
                    wmma::load_matrix_sync(bf, Wres + (s * 64 + k16 * 16) * 48 + f * 16, 48);
                    wmma::mma_sync(acc[f], af, bf, acc[f]);
                }
            }
            __syncthreads();
        }
        #pragma unroll
        for (int f = 0; f < 3; f++)
            wmma::store_matrix_sync(gsm + (wid * 16) * 48 + f * 16, acc[f], 48, wmma::mem_row_major);
        __syncthreads();

        // pointwise: 128 rows x 8 units, all-smem operands
        #pragma unroll
        for (int j = 0; j < 4; j++) {
            int e = tid + j * 256;                 // 0..1023
            int r = e >> 3, u = e & 7;
            const float* gg = gsm + r * 48;
            const float* vp = vpgr + r * 40;
            const float* wp = wpsm + r * 40;
            float ig = gg[u]      + vp[u]      + wp[u];
            float fg = gg[8 + u]  + vp[8 + u]  + wp[8 + u];
            float g_ = gg[16 + u] + vp[16 + u] + wp[16 + u];
            float og = gg[24 + u] + vp[24 + u] + wp[24 + u];
            float gp = gg[32 + u] + vp[32 + u] + wp[32 + u];
            float cold = cst[e];
            float cn = sig_f(fg) * cold + sig_f(ig) * tanh_f(g_);
            float tc = tanh_f(cn);
            cst[e] = cn;
            hn[(m0 + r) * RNN_ + u0 + u] = __float2bfloat16(sig_f(og) * tc);
            d_Sb[(size_t)(t * 256 + m0 + r) * RNN_ + u0 + u] =
                __float2bfloat16(sig_f(gp) * tc);
        }
        gbar(ls);                                  // h(t) published
    }
    gbar(ls);   // barriers: 1 + 64 + 1 = 66 (even -> state restored)
}

// =====================================================================
// k_lse v3: 128 rows/CTA, 512 threads (16 warps), chunk 32 double-buffered,
// bf16 WMMA + f16x2 packed exp; exact fp32 target logit.
// =====================================================================
#define LSE_SMEM 212992
#define NCH 313                                    // ceil(10001/32)
__global__ __launch_bounds__(512) void k_lse(
    const float* __restrict__ out_b,
    const int* __restrict__ seqz, float* __restrict__ out)
{
    extern __shared__ unsigned char dyn[];
    __nv_bfloat16* Asm = (__nv_bfloat16*)dyn;             // 128 x 512 (128 KB)
    __nv_bfloat16* Bsm = (__nv_bfloat16*)(dyn + 131072);  // 2 x (512 x 32) (64 KB)
    float*         Csm = (float*)(dyn + 196608);          // 128 x 32 (16 KB)
    __shared__ float s_tgt[128];
    __shared__ int   s_tg[128];
    __shared__ float red_s[4][128];

    const int tid = threadIdx.x;
    const int m0  = blockIdx.x * 128;
    const int wid = tid >> 5;                      // 0..15
    const int warp_m = wid >> 1;                   // 0..7 (16 rows)
    const int warp_n = wid & 1;                    // 0..1 (16 cols)
    uint32_t bB = (uint32_t)__cvta_generic_to_shared(Bsm);

    if (tid < 128) {
        int r = m0 + tid;
        int t = r >> 8, b = r & 255;
        s_tg[tid] = seqz[b * T_ + t];
    }

    // A tile resident: 128 x 512 bf16 = 8192 uint4
    #pragma unroll
    for (int i = 0; i < 16; i++) {
        int idx = tid + i * 512;
        int r = idx >> 6, c = idx & 63;
        ((uint4*)Asm)[idx] = ((const uint4*)(d_Sb + (size_t)(m0 + r) * RNN_))[c];
    }
    __syncthreads();

    auto issueB = [&](int ch, int d) {
        int v0 = ch * 32;
        #pragma unroll
        for (int j = 0; j < 4; j++) {
            int idx = tid + j * 512;               // 0..2047
            int k = idx >> 2, c8 = (idx & 3) << 3;
            cp16(bB + (uint32_t)(d * 32768 + (k * 32 + c8) * 2),
                 d_OWb + (size_t)k * V1P + v0 + c8);
        }
    };

    const int row = tid >> 2;                      // 0..127
    const int qtr = tid & 3;                       // 8 cols each
    const int mytg = s_tg[row];
    float rs = 0.f;

    issueB(0, 0); cp_commit();
    for (int c = 0; c < NCH; c++) {
        if (c < NCH - 1) { issueB(c + 1, (c + 1) & 1); cp_commit(); cp_wait<1>(); }
        else             { cp_wait<0>(); }
        __syncthreads();

        const __nv_bfloat16* Bcur = Bsm + (c & 1) * 16384;
        wmma::fragment<wmma::accumulator, 16, 16, 16, float> acc;
        wmma::fill_fragment(acc, 0.f);
        #pragma unroll
        for (int k = 0; k < 32; k++) {
            wmma::fragment<wmma::matrix_a, 16, 16, 16, __nv_bfloat16, wmma::row_major> af;
            wmma::fragment<wmma::matrix_b, 16, 16, 16, __nv_bfloat16, wmma::row_major> bf;
            wmma::load_matrix_sync(af, Asm + (warp_m * 16) * 512 + k * 16, 512);
            wmma::load_matrix_sync(bf, Bcur + (k * 16) * 32 + warp_n * 16, 32);
            wmma::mma_sync(acc, af, bf, acc);
        }
        wmma::store_matrix_sync(Csm + (warp_m * 16) * 32 + warp_n * 16,
                                acc, 32, wmma::mem_row_major);
        __syncthreads();

        // epilogue: 4 threads/row x 8 cols, packed f16x2 exp
        int v0 = c * 32;
        float lsum = 0.f;
        #pragma unroll
        for (int j = 0; j < 4; j++) {
            int cc = (qtr << 3) + 2 * j;
            int v = v0 + cc;
            float l0 = (v     < V1) ? (Csm[row * 32 + cc]     + out_b[v])     : -1e4f;
            float l1 = (v + 1 < V1) ? (Csm[row * 32 + cc + 1] + out_b[v + 1]) : -1e4f;
            uint32_t h2, e2;
            asm("cvt.rn.f16x2.f32 %0, %1, %2;" : "=r"(h2) : "f"(l1 * LOG2E), "f"(l0 * LOG2E));
            asm("ex2.approx.f16x2 %0, %1;" : "=r"(e2) : "r"(h2));
            __half2 hh = *reinterpret_cast<__half2*>(&e2);
            float2 ff = __half22float2(hh);
            lsum += ff.x + ff.y;
        }
        rs += lsum;
        if (mytg >= v0 && mytg < v0 + 32 && ((mytg - v0) >> 3) == qtr)
            s_tgt[row] = Csm[row * 32 + (mytg - v0)] + out_b[mytg];
        __syncthreads();
    }

    red_s[qtr][row] = rs;
    __syncthreads();
    if (tid < 128) {
        int r = m0 + tid;
        float S = red_s[0][tid] + red_s[1][tid] + red_s[2][tid] + red_s[3][tid];
        float lse = logf(S);
        int t = r >> 8, b = r & 255;
        float mask = (t == 0) ? 1.f : ((seqz[b * T_ + (t - 1)] != 0) ? 1.f : 0.f);
        out[r] = (s_tgt[tid] - lse) * mask;
    }
}

// ---------------- launch ----------------
extern "C" void kernel_launch(void* const* d_in, const int* in_sizes, int n_in,
                              void* d_out, int out_size)
{
    const float *vis = 0, *emb = 0, *W_ih = 0, *W_hh = 0, *b_lstm = 0;
    const float *vis2g_W = 0, *vis2g_b = 0, *w2g_W = 0, *h2g_W = 0;
    const float *out_W = 0, *out_b = 0;
    const int *seqz = 0;
    int trio[3]; int ntrio = 0;
    for (int i = 0; i < n_in; i++) {
        switch (in_sizes[i]) {
            case 16384:   seqz    = (const int*)  d_in[i]; break;
            case 5121024: emb     = (const float*)d_in[i]; break;
            case 3145728: W_ih    = (const float*)d_in[i]; break;
            case 1048576: W_hh    = (const float*)d_in[i]; break;
            case 2048:    b_lstm  = (const float*)d_in[i]; break;
            case 524288:  vis2g_W = (const float*)d_in[i]; break;
            case 512:     vis2g_b = (const float*)d_in[i]; break;
            case 5120512: out_W   = (const float*)d_in[i]; break;
            case 10001:   out_b   = (const float*)d_in[i]; break;
            case 262144:  if (ntrio < 3) trio[ntrio++] = i; break;
            default: break;
        }
    }
    if (ntrio == 3) {
        vis   = (const float*)d_in[trio[0]];
        w2g_W = (const float*)d_in[trio[1]];
        h2g_W = (const float*)d_in[trio[2]];
    }
    if (!vis)     vis     = (const float*)d_in[0];
    if (!seqz)    seqz    = (const int*)  d_in[1];
    if (!emb)     emb     = (const float*)d_in[2];
    if (!W_ih)    W_ih    = (const float*)d_in[3];
    if (!W_hh)    W_hh    = (const float*)d_in[4];
    if (!b_lstm)  b_lstm  = (const float*)d_in[5];
    if (!vis2g_W) vis2g_W = (const float*)d_in[6];
    if (!vis2g_b) vis2g_b = (const float*)d_in[7];
    if (!w2g_W)   w2g_W   = (const float*)d_in[8];
    if (!h2g_W)   h2g_W   = (const float*)d_in[9];
    if (!out_W)   out_W   = (const float*)d_in[10];
    if (!out_b)   out_b   = (const float*)d_in[11];
    float* out = (float*)d_out;

    cudaFuncSetAttribute(k_wpg, cudaFuncAttributeMaxDynamicSharedMemorySize, WPG_SMEM);
    cudaFuncSetAttribute(k_rnn, cudaFuncAttributeMaxDynamicSharedMemorySize, RNN_SMEM);
    cudaFuncSetAttribute(k_lse, cudaFuncAttributeMaxDynamicSharedMemorySize, LSE_SMEM);

    k_prep<<<(int)(((size_t)RNN_ * V1P + 255) / 256), 256>>>(out_W);
    k_wpg<<<dim3(20, 128), 256, WPG_SMEM>>>(seqz, emb, W_ih, w2g_W);
    k_rnn<<<NCTA, 256, RNN_SMEM>>>(vis, W_ih, W_hh, b_lstm, vis2g_W, vis2g_b, h2g_W);
    k_lse<<<TB / 128, 512, LSE_SMEM>>>(out_b, seqz, out);
}

// round 12
// speedup vs baseline: 1.9134x; 1.0012x over previous
#include <cuda_runtime.h>
#include <cuda_bf16.h>
#include <cuda_fp16.h>
#include <mma.h>
#include <math.h>
#include <stdint.h>

using namespace nvcuda;

#define B_     256
#define T_     64
#define VOCAB_ 10000
#define V1     10001
#define V1P    10240
#define VIS_   1024
#define RNN_   512
#define GEXT   2560
#define TB     16384
#define NCTA   128
#define LOG2E  1.4426950408889634f

// ---------------- scratch ----------------
__device__ __nv_bfloat16 d_hbuf[2][B_ * RNN_];
__device__ float d_WPG[(size_t)TB * GEXT];            // word-part gates (168 MB)
__device__ __nv_bfloat16 d_Sb [(size_t)TB * RNN_];    // sentinel states bf16
__device__ __nv_bfloat16 d_OWb[(size_t)RNN_ * V1P];   // out_W bf16 padded

__device__ unsigned g_cnt = 0;
__device__ volatile unsigned g_sense = 0;

__device__ __forceinline__ void gbar(unsigned &ls)
{
    __syncthreads();
    if (threadIdx.x == 0) {
        ls ^= 1u;
        __threadfence();
        if (atomicAdd(&g_cnt, 1u) == NCTA - 1u) {
            g_cnt = 0u;
            __threadfence();
            g_sense = ls;
        } else {
            while (g_sense != ls) { }
            __threadfence();
        }
    }
    __syncthreads();
}

__device__ __forceinline__ float tanh_f(float x)
{
    float y;
    asm("tanh.approx.f32 %0, %1;" : "=f"(y) : "f"(x));
    return y;
}
__device__ __forceinline__ float sig_f(float x)
{
    return fmaf(0.5f, tanh_f(0.5f * x), 0.5f);
}

__device__ __forceinline__ void cp16(uint32_t dst, const void* src)
{
    asm volatile("cp.async.cg.shared.global [%0], [%1], 16;" :: "r"(dst), "l"(src));
}
__device__ __forceinline__ void cp_commit()
{
    asm volatile("cp.async.commit_group;" ::: "memory");
}
template<int N> __device__ __forceinline__ void cp_wait()
{
    asm volatile("cp.async.wait_group %0;" :: "n"(N) : "memory");
}

#define LOAD_A_TF32(frag, ptr, ldm) do { \
    wmma::load_matrix_sync(frag, ptr, ldm); \
    for (int _e = 0; _e < (frag).num_elements; _e++) \
        (frag).x[_e] = wmma::__float_to_tf32((frag).x[_e]); \
} while (0)

// ---------------- prep: out_W -> bf16 padded ----------------
__global__ __launch_bounds__(256) void k_prep(const float* __restrict__ out_W)
{
    size_t idx = (size_t)blockIdx.x * 256 + threadIdx.x;
    if (idx >= (size_t)RNN_ * V1P) return;
    int k = (int)(idx / V1P), v = (int)(idx % V1P);
    float w = (v < V1) ? out_W[(size_t)k * V1 + v] : 0.f;
    d_OWb[idx] = __float2bfloat16(w);
}

// =====================================================================
// k_wpg: WPG[16384,2560] = emb[words] @ [W_ih_word | w2g], tf32 WMMA.
// =====================================================================
#define WPG_SMEM 66048
__global__ __launch_bounds__(256) void k_wpg(
    const int* __restrict__ seqz, const float* __restrict__ emb,
    const float* __restrict__ W_ih, const float* __restrict__ w2g_W)
{
    extern __shared__ char smraw[];
    float* As_ = (float*)smraw;                 // [2][128][32]
    float* Bs_ = (float*)(smraw + 32768);       // [2][32][128]
    int*  stok = (int*)(smraw + 65536);         // [128]
    const int tid = threadIdx.x;
    const int n0 = blockIdx.x * 128;
    const int m0 = blockIdx.y * 128;
    const int wid = tid >> 5;
    const int warp_m = wid >> 1;
    const int warp_n = wid & 1;
    uint32_t aB = (uint32_t)__cvta_generic_to_shared(As_);
    uint32_t bB = (uint32_t)__cvta_generic_to_shared(Bs_);

    if (tid < 128) {
        int row = m0 + tid;
        int t = row >> 8, b = row & 255;
        stok[tid] = (t == 0) ? (VOCAB_ + 1) : seqz[b * T_ + t - 1];
    }
    __syncthreads();

    auto issueA = [&](int s, int d) {
        int k0 = s * 32;
        #pragma unroll
        for (int j = 0; j < 4; j++) {
            int idx = tid + j * 256;
            int r = idx >> 3, sg = (idx & 7) << 2;
            cp16(aB + (uint32_t)((d * 4096 + r * 32 + sg) * 4),
                 emb + (size_t)stok[r] * RNN_ + k0 + sg);
        }
    };
    auto issueB = [&](int s, int d) {
        int k0 = s * 32;
        #pragma unroll
        for (int j = 0; j < 4; j++) {
            int idx = tid + j * 256;
            int kr = idx >> 5, c4 = (idx & 31) << 2;
            int kk = k0 + kr;
            const float* src = (n0 < 2048)
                ? W_ih + (size_t)(VIS_ + kk) * 2048 + n0 + c4
                : w2g_W + (size_t)kk * RNN_ + (n0 - 2048) + c4;
            cp16(bB + (uint32_t)((d * 4096 + kr * 128 + c4) * 4), src);
        }
    };

    wmma::fragment<wmma::accumulator, 16, 16, 8, float> acc[2][4];
    #pragma unroll
    for (int i = 0; i < 2; i++)
        #pragma unroll
        for (int j = 0; j < 4; j++) wmma::fill_fragment(acc[i][j], 0.f);

    issueA(0, 0); issueB(0, 0); cp_commit();
    for (int s = 0; s < 16; s++) {
        if (s < 15) { issueA(s + 1, (s + 1) & 1); issueB(s + 1, (s + 1) & 1); cp_commit(); cp_wait<1>(); }
        else        { cp_wait<0>(); }
        __syncthreads();
        int d = s & 1;
        #pragma unroll
        for (int k8 = 0; k8 < 4; k8++) {
            wmma::fragment<wmma::matrix_a, 16, 16, 8, wmma::precision::tf32, wmma::row_major> af[2];
            wmma::fragment<wmma::matrix_b, 16, 16, 8, wmma::precision::tf32, wmma::row_major> bf[4];
            #pragma unroll
            for (int i = 0; i < 2; i++)
                LOAD_A_TF32(af[i], As_ + d * 4096 + (warp_m * 32 + i * 16) * 32 + k8 * 8, 32);
            #pragma unroll
            for (int j = 0; j < 4; j++)
                LOAD_A_TF32(bf[j], Bs_ + d * 4096 + (k8 * 8) * 128 + warp_n * 64 + j * 16, 128);
            #pragma unroll
            for (int i = 0; i < 2; i++)
                #pragma unroll
                for (int j = 0; j < 4; j++)
                    wmma::mma_sync(acc[i][j], af[i], bf[j], acc[i][j]);
        }
        __syncthreads();
    }
    #pragma unroll
    for (int i = 0; i < 2; i++)
        #pragma unroll
        for (int j = 0; j < 4; j++)
            wmma::store_matrix_sync(
                d_WPG + (size_t)(m0 + warp_m * 32 + i * 16) * GEXT + n0 + warp_n * 64 + j * 16,
                acc[i][j], GEXT, wmma::mem_row_major);
}

// =====================================================================
// k_rnn v4: 128 persistent CTAs, bf16 resident recurrence weights.
// CTA (ct&1 -> 128 batch rows, ct>>1 -> 8 units x 5 gates = 40 cols/48).
// Per step: wp tile + h slices via cp.async, bf16 WMMA k16, CTA-local
// pointwise from smem, 1 global barrier.
// =====================================================================
// smem layout (bytes):
//   0      Wres  bf16 [512][48]          49152
//   49152  As    bf16 [2][128][64]       32768   (alias: prologue f32 A [2][128][32]; gsm f32 [128][48])
//   81920  vpgr  f32  [128][40]          20480
//   102400 wpsm  f32  [128][40]          20480
//   122880 cst   f32  [128][8]            4096
//   126976 bscr  f32  [2][32][48]        12288   (prologue B)
#define RNN_SMEM 139264
__global__ __launch_bounds__(256) void k_rnn(
    const float* __restrict__ vis,
    const float* __restrict__ W_ih,    const float* __restrict__ W_hh,
    const float* __restrict__ b_lstm,
    const float* __restrict__ vis2g_W, const float* __restrict__ vis2g_b,
    const float* __restrict__ h2g_W)
{
    extern __shared__ char smraw[];
    __nv_bfloat16* Wres = (__nv_bfloat16*)smraw;
    __nv_bfloat16* Asb  = (__nv_bfloat16*)(smraw + 49152);
    float* Asf  = (float*)(smraw + 49152);        // prologue A (f32)
    float* gsm  = (float*)(smraw + 49152);        // gates result (f32, after GEMM)
    float* vpgr = (float*)(smraw + 81920);
    float* wpsm = (float*)(smraw + 102400);
    float* cst  = (float*)(smraw + 122880);
    float* bscr = (float*)(smraw + 126976);

    const int tid = threadIdx.x;
    const int ct  = blockIdx.x;
    const int wid = tid >> 5;                      // 0..7, 16 rows each
    const int u0  = (ct >> 1) * 8;
    const int m0  = (ct & 1) * 128;
    unsigned ls = 0;
    uint32_t aB = (uint32_t)__cvta_generic_to_shared(smraw + 49152);
    uint32_t bB = (uint32_t)__cvta_generic_to_shared(bscr);
    uint32_t wpB = (uint32_t)__cvta_generic_to_shared(wpsm);

    // ---- init: cst zero, bscr pad cols, own h0 slice zero (bf16) ----
    #pragma unroll
    for (int j = 0; j < 4; j++) {
        int e = tid + j * 256;                     // 0..1023
        cst[e] = 0.f;
        int r = e >> 3, u = e & 7;
        d_hbuf[0][(m0 + r) * RNN_ + u0 + u] = __float2bfloat16(0.f);
    }
    #pragma unroll
    for (int j = 0; j < 2; j++) {
        int e = tid + j * 256;                     // 0..511
        int d = e >> 8, rr = (e >> 3) & 31, c = 40 + (e & 7);
        bscr[d * 1536 + rr * 48 + c] = 0.f;
    }
    __syncthreads();

    // ---- prologue GEMM (tf32): vis-part gates, K=1024, 32 slices of 32 ----
    {
        wmma::fragment<wmma::accumulator, 16, 16, 8, float> acc[3];
        #pragma unroll
        for (int f = 0; f < 3; f++) wmma::fill_fragment(acc[f], 0.f);

        auto issA = [&](int s, int d) {
            int k0 = s * 32;
            #pragma unroll
            for (int j = 0; j < 4; j++) {
                int idx = tid + j * 256;
                int r = idx >> 3, sg = (idx & 7) << 2;
                cp16(aB + (uint32_t)((d * 4096 + r * 32 + sg) * 4),
                     vis + (size_t)(m0 + r) * VIS_ + k0 + sg);
            }
        };
        auto issB = [&](int s, int d) {
            int k0 = s * 32;
            #pragma unroll
            for (int j = 0; j < 2; j++) {
                int e = tid + j * 256;
                if (e < 320) {
                    int r = e / 10, q = e % 10;
                    int g = q >> 1, c4 = (q & 1) << 2;
                    int kk = k0 + r;
                    const float* src = (g < 4)
                        ? W_ih + (size_t)kk * 2048 + g * 512 + u0 + c4
                        : vis2g_W + (size_t)kk * RNN_ + u0 + c4;
                    cp16(bB + (uint32_t)((d * 1536 + r * 48 + q * 4) * 4), src);
                }
            }
        };

        issA(0, 0); issB(0, 0); cp_commit();
        for (int s = 0; s < 32; s++) {
            if (s < 31) { issA(s + 1, (s + 1) & 1); issB(s + 1, (s + 1) & 1); cp_commit(); cp_wait<1>(); }
            else        { cp_wait<0>(); }
            __syncthreads();
            int d = s & 1;
            #pragma unroll
            for (int k8 = 0; k8 < 4; k8++) {
                wmma::fragment<wmma::matrix_a, 16, 16, 8, wmma::precision::tf32, wmma::row_major> af;
                LOAD_A_TF32(af, Asf + d * 4096 + (wid * 16) * 32 + k8 * 8, 32);
                #pragma unroll
                for (int f = 0; f < 3; f++) {
                    wmma::fragment<wmma::matrix_b, 16, 16, 8, wmma::precision::tf32, wmma::row_major> bf;
                    LOAD_A_TF32(bf, bscr + d * 1536 + (k8 * 8) * 48 + f * 16, 48);
                    wmma::mma_sync(acc[f], af, bf, acc[f]);
                }
            }
            __syncthreads();
        }
        #pragma unroll
        for (int f = 0; f < 3; f++)
            wmma::store_matrix_sync(gsm + (wid * 16) * 48 + f * 16, acc[f], 48, wmma::mem_row_major);
        __syncthreads();
    }

    // vpgr = gsm + bias
    #pragma unroll
    for (int j = 0; j < 20; j++) {
        int e = tid + j * 256;                     // 0..5119 = 128 x 40
        int r = e / 40, q = e % 40;
        int g = q >> 3, u = q & 7;
        float bias = (g < 4) ? b_lstm[g * 512 + u0 + u] : vis2g_b[u0 + u];
        vpgr[r * 40 + q] = gsm[r * 48 + q] + bias;
    }
    __syncthreads();

    // ---- load resident bf16 recurrence weights [512][48] ----
    #pragma unroll
    for (int j = 0; j < 80; j++) {
        int e = tid + j * 256;                     // 0..20479
        int k = e / 40, q = e % 40;
        int g = q >> 3, u = q & 7;
        float w = (g < 4) ? W_hh[(size_t)k * 2048 + g * 512 + u0 + u]
                          : h2g_W[(size_t)k * RNN_ + u0 + u];
        Wres[k * 48 + q] = __float2bfloat16(w);
    }
    #pragma unroll
    for (int j = 0; j < 16; j++) {
        int e = tid + j * 256;                     // 0..4095
        int k = e >> 3, c = 40 + (e & 7);
        Wres[k * 48 + c] = __float2bfloat16(0.f);
    }
    gbar(ls);                                      // barrier #1

    // ---- 64 steps ----
    for (int t = 0; t < T_; t++) {
        const __nv_bfloat16* hb = d_hbuf[t & 1];
        __nv_bfloat16* hn = d_hbuf[(t & 1) ^ 1];
        const float* wpbase = d_WPG + (size_t)(t * 256 + m0) * GEXT;

        auto issH = [&](int s, int d) {
            int k0 = s * 64;
            #pragma unroll
            for (int j = 0; j < 4; j++) {
                int idx = tid + j * 256;           // 0..1023
                int r = idx >> 3, c8 = (idx & 7) << 3;   // 8 bf16 = 16B
                cp16(aB + (uint32_t)((d * 128 + r) * 64 + c8) * 2,
                     hb + (size_t)(m0 + r) * RNN_ + k0 + c8);
            }
        };
        // wp tile prefetch (group shared with slice 0)
        {
            #pragma unroll
            for (int j = 0; j < 5; j++) {
                int e = tid + j * 256;             // 0..1279
                int r = e / 10, q = e % 10;
                int g = q >> 1, half = q & 1;
                cp16(wpB + (uint32_t)((r * 40 + g * 8 + half * 4) * 4),
                     wpbase + (size_t)r * GEXT + g * 512 + u0 + half * 4);
            }
        }

        wmma::fragment<wmma::accumulator, 16, 16, 16, float> acc[3];
        #pragma unroll
        for (int f = 0; f < 3; f++) wmma::fill_fragment(acc[f], 0.f);

        issH(0, 0); cp_commit();
        for (int s = 0; s < 8; s++) {
            if (s < 7) { issH(s + 1, (s + 1) & 1); cp_commit(); cp_wait<1>(); }
            else       { cp_wait<0>(); }
            __syncthreads();
            int d = s & 1;
            #pragma unroll
            for (int k16 = 0; k16 < 4; k16++) {
                wmma::fragment<wmma::matrix_a, 16, 16, 16, __nv_bfloat16, wmma::row_major> af;
                wmma::load_matrix_sync(af, Asb + (d * 128 + wid * 16) * 64 + k16 * 16, 64);
                #pragma unroll
                for (int f = 0; f < 3; f++) {
                    wmma::fragment<wmma::matrix_b, 16, 16, 16, __nv_bfloat16, wmma::row_major> bf;
                    wmma::load_matrix_sync(bf, Wres + (s * 64 + k16 * 16) * 48 + f * 16, 48);
                    wmma::mma_sync(acc[f], af, bf, acc[f]);
                }
            }
            __syncthreads();
        }
        #pragma unroll
        for (int f = 0; f < 3; f++)
            wmma::store_matrix_sync(gsm + (wid * 16) * 48 + f * 16, acc[f], 48, wmma::mem_row_major);
        __syncthreads();

        // pointwise: 128 rows x 8 units, all-smem operands
        #pragma unroll
        for (int j = 0; j < 4; j++) {
            int e = tid + j * 256;                 // 0..1023
            int r = e >> 3, u = e & 7;
            const float* gg = gsm + r * 48;
            const float* vp = vpgr + r * 40;
            const float* wp = wpsm + r * 40;
            float ig = gg[u]      + vp[u]      + wp[u];
            float fg = gg[8 + u]  + vp[8 + u]  + wp[8 + u];
            float g_ = gg[16 + u] + vp[16 + u] + wp[16 + u];
            float og = gg[24 + u] + vp[24 + u] + wp[24 + u];
            float gp = gg[32 + u] + vp[32 + u] + wp[32 + u];
            float cold = cst[e];
            float cn = sig_f(fg) * cold + sig_f(ig) * tanh_f(g_);
            float tc = tanh_f(cn);
            cst[e] = cn;
            hn[(m0 + r) * RNN_ + u0 + u] = __float2bfloat16(sig_f(og) * tc);
            d_Sb[(size_t)(t * 256 + m0 + r) * RNN_ + u0 + u] =
                __float2bfloat16(sig_f(gp) * tc);
        }
        gbar(ls);                                  // h(t) published
    }
    gbar(ls);   // barriers: 1 + 64 + 1 = 66 (even -> state restored)
}

// =====================================================================
// k_lse v3: 128 rows/CTA, 512 threads (16 warps), chunk 32 double-buffered,
// bf16 WMMA + f16x2 packed exp; exact fp32 target logit.
// =====================================================================
#define LSE_SMEM 212992
#define NCH 313                                    // ceil(10001/32)
__global__ __launch_bounds__(512) void k_lse(
    const float* __restrict__ out_b,
    const int* __restrict__ seqz, float* __restrict__ out)
{
    extern __shared__ unsigned char dyn[];
    __nv_bfloat16* Asm = (__nv_bfloat16*)dyn;             // 128 x 512 (128 KB)
    __nv_bfloat16* Bsm = (__nv_bfloat16*)(dyn + 131072);  // 2 x (512 x 32) (64 KB)
    float*         Csm = (float*)(dyn + 196608);          // 128 x 32 (16 KB)
    __shared__ float s_tgt[128];
    __shared__ int   s_tg[128];
    __shared__ float red_s[4][128];

    const int tid = threadIdx.x;
    const int m0  = blockIdx.x * 128;
    const int wid = tid >> 5;                      // 0..15
    const int warp_m = wid >> 1;                   // 0..7 (16 rows)
    const int warp_n = wid & 1;                    // 0..1 (16 cols)
    uint32_t bB = (uint32_t)__cvta_generic_to_shared(Bsm);

    if (tid < 128) {
        int r = m0 + tid;
        int t = r >> 8, b = r & 255;
        s_tg[tid] = seqz[b * T_ + t];
    }

    // A tile resident: 128 x 512 bf16 = 8192 uint4
    #pragma unroll
    for (int i = 0; i < 16; i++) {
        int idx = tid + i * 512;
        int r = idx >> 6, c = idx & 63;
        ((uint4*)Asm)[idx] = ((const uint4*)(d_Sb + (size_t)(m0 + r) * RNN_))[c];
    }
    __syncthreads();

    auto issueB = [&](int ch, int d) {
        int v0 = ch * 32;
        #pragma unroll
        for (int j = 0; j < 4; j++) {
            int idx = tid + j * 512;               // 0..2047
            int k = idx >> 2, c8 = (idx & 3) << 3;
            cp16(bB + (uint32_t)(d * 32768 + (k * 32 + c8) * 2),
                 d_OWb + (size_t)k * V1P + v0 + c8);
        }
    };

    const int row = tid >> 2;                      // 0..127
    const int qtr = tid & 3;                       // 8 cols each
    const int mytg = s_tg[row];
    float rs = 0.f;

    issueB(0, 0); cp_commit();
    for (int c = 0; c < NCH; c++) {
        if (c < NCH - 1) { issueB(c + 1, (c + 1) & 1); cp_commit(); cp_wait<1>(); }
        else             { cp_wait<0>(); }
        __syncthreads();

        const __nv_bfloat16* Bcur = Bsm + (c & 1) * 16384;
        wmma::fragment<wmma::accumulator, 16, 16, 16, float> acc;
        wmma::fill_fragment(acc, 0.f);
        #pragma unroll
        for (int k = 0; k < 32; k++) {
            wmma::fragment<wmma::matrix_a, 16, 16, 16, __nv_bfloat16, wmma::row_major> af;
            wmma::fragment<wmma::matrix_b, 16, 16, 16, __nv_bfloat16, wmma::row_major> bf;
            wmma::load_matrix_sync(af, Asm + (warp_m * 16) * 512 + k * 16, 512);
            wmma::load_matrix_sync(bf, Bcur + (k * 16) * 32 + warp_n * 16, 32);
            wmma::mma_sync(acc, af, bf, acc);
        }
        wmma::store_matrix_sync(Csm + (warp_m * 16) * 32 + warp_n * 16,
                                acc, 32, wmma::mem_row_major);
        __syncthreads();

        // epilogue: 4 threads/row x 8 cols, packed f16x2 exp
        int v0 = c * 32;
        float lsum = 0.f;
        #pragma unroll
        for (int j = 0; j < 4; j++) {
            int cc = (qtr << 3) + 2 * j;
            int v = v0 + cc;
            float l0 = (v     < V1) ? (Csm[row * 32 + cc]     + out_b[v])     : -1e4f;
            float l1 = (v + 1 < V1) ? (Csm[row * 32 + cc + 1] + out_b[v + 1]) : -1e4f;
            uint32_t h2, e2;
            asm("cvt.rn.f16x2.f32 %0, %1, %2;" : "=r"(h2) : "f"(l1 * LOG2E), "f"(l0 * LOG2E));
            asm("ex2.approx.f16x2 %0, %1;" : "=r"(e2) : "r"(h2));
            __half2 hh = *reinterpret_cast<__half2*>(&e2);
            float2 ff = __half22float2(hh);
            lsum += ff.x + ff.y;
        }
        rs += lsum;
        if (mytg >= v0 && mytg < v0 + 32 && ((mytg - v0) >> 3) == qtr)
            s_tgt[row] = Csm[row * 32 + (mytg - v0)] + out_b[mytg];
        __syncthreads();
    }

    red_s[qtr][row] = rs;
    __syncthreads();
    if (tid < 128) {
        int r = m0 + tid;
        float S = red_s[0][tid] + red_s[1][tid] + red_s[2][tid] + red_s[3][tid];
        float lse = logf(S);
        int t = r >> 8, b = r & 255;
        float mask = (t == 0) ? 1.f : ((seqz[b * T_ + (t - 1)] != 0) ? 1.f : 0.f);
        out[r] = (s_tgt[tid] - lse) * mask;
    }
}

// ---------------- launch ----------------
extern "C" void kernel_launch(void* const* d_in, const int* in_sizes, int n_in,
                              void* d_out, int out_size)
{
    const float *vis = 0, *emb = 0, *W_ih = 0, *W_hh = 0, *b_lstm = 0;
    const float *vis2g_W = 0, *vis2g_b = 0, *w2g_W = 0, *h2g_W = 0;
    const float *out_W = 0, *out_b = 0;
    const int *seqz = 0;
    int trio[3]; int ntrio = 0;
    for (int i = 0; i < n_in; i++) {
        switch (in_sizes[i]) {
            case 16384:   seqz    = (const int*)  d_in[i]; break;
            case 5121024: emb     = (const float*)d_in[i]; break;
            case 3145728: W_ih    = (const float*)d_in[i]; break;
            case 1048576: W_hh    = (const float*)d_in[i]; break;
            case 2048:    b_lstm  = (const float*)d_in[i]; break;
            case 524288:  vis2g_W = (const float*)d_in[i]; break;
            case 512:     vis2g_b = (const float*)d_in[i]; break;
            case 5120512: out_W   = (const float*)d_in[i]; break;
            case 10001:   out_b   = (const float*)d_in[i]; break;
            case 262144:  if (ntrio < 3) trio[ntrio++] = i; break;
            default: break;
        }
    }
    if (ntrio == 3) {
        vis   = (const float*)d_in[trio[0]];
        w2g_W = (const float*)d_in[trio[1]];
        h2g_W = (const float*)d_in[trio[2]];
    }
    if (!vis)     vis     = (const float*)d_in[0];
    if (!seqz)    seqz    = (const int*)  d_in[1];
    if (!emb)     emb     = (const float*)d_in[2];
    if (!W_ih)    W_ih    = (const float*)d_in[3];
    if (!W_hh)    W_hh    = (const float*)d_in[4];
    if (!b_lstm)  b_lstm  = (const float*)d_in[5];
    if (!vis2g_W) vis2g_W = (const float*)d_in[6];
    if (!vis2g_b) vis2g_b = (const float*)d_in[7];
    if (!w2g_W)   w2g_W   = (const float*)d_in[8];
    if (!h2g_W)   h2g_W   = (const float*)d_in[9];
    if (!out_W)   out_W   = (const float*)d_in[10];
    if (!out_b)   out_b   = (const float*)d_in[11];
    float* out = (float*)d_out;

    cudaFuncSetAttribute(k_wpg, cudaFuncAttributeMaxDynamicSharedMemorySize, WPG_SMEM);
    cudaFuncSetAttribute(k_rnn, cudaFuncAttributeMaxDynamicSharedMemorySize, RNN_SMEM);
    cudaFuncSetAttribute(k_lse, cudaFuncAttributeMaxDynamicSharedMemorySize, LSE_SMEM);

    k_prep<<<(int)(((size_t)RNN_ * V1P + 255) / 256), 256>>>(out_W);
    k_wpg<<<dim3(20, 128), 256, WPG_SMEM>>>(seqz, emb, W_ih, w2g_W);
    k_rnn<<<NCTA, 256, RNN_SMEM>>>(vis, W_ih, W_hh, b_lstm, vis2g_W, vis2g_b, h2g_W);
    k_lse<<<TB / 128, 512, LSE_SMEM>>>(out_b, seqz, out);
}

// round 13
// speedup vs baseline: 1.9136x; 1.0001x over previous
#include <cuda_runtime.h>
#include <cuda_bf16.h>
#include <cuda_fp16.h>
#include <mma.h>
#include <math.h>
#include <stdint.h>

using namespace nvcuda;

#define B_     256
#define T_     64
#define VOCAB_ 10000
#define V1     10001
#define V1P    10240
#define VIS_   1024
#define RNN_   512
#define GEXT   2560
#define TB     16384
#define NCTA   128
#define LOG2E  1.4426950408889634f

// ---------------- scratch ----------------
__device__ __nv_bfloat16 d_hbuf[2][B_ * RNN_];
__device__ float d_WPG[(size_t)TB * GEXT];            // word-part gates (168 MB)
__device__ __nv_bfloat16 d_Sb [(size_t)TB * RNN_];    // sentinel states bf16
__device__ __nv_bfloat16 d_OWb[(size_t)RNN_ * V1P];   // out_W bf16 padded

__device__ unsigned g_cnt = 0;
__device__ volatile unsigned g_sense = 0;

__device__ __forceinline__ void gbar(unsigned &ls)
{
    __syncthreads();
    if (threadIdx.x == 0) {
        ls ^= 1u;
        __threadfence();
        if (atomicAdd(&g_cnt, 1u) == NCTA - 1u) {
            g_cnt = 0u;
            __threadfence();
            g_sense = ls;
        } else {
            while (g_sense != ls) { }
            __threadfence();
        }
    }
    __syncthreads();
}

__device__ __forceinline__ float tanh_f(float x)
{
    float y;
    asm("tanh.approx.f32 %0, %1;" : "=f"(y) : "f"(x));
    return y;
}
__device__ __forceinline__ float sig_f(float x)
{
    return fmaf(0.5f, tanh_f(0.5f * x), 0.5f);
}

__device__ __forceinline__ void cp16(uint32_t dst, const void* src)
{
    asm volatile("cp.async.cg.shared.global [%0], [%1], 16;" :: "r"(dst), "l"(src));
}
__device__ __forceinline__ void cp_commit()
{
    asm volatile("cp.async.commit_group;" ::: "memory");
}
template<int N> __device__ __forceinline__ void cp_wait()
{
    asm volatile("cp.async.wait_group %0;" :: "n"(N) : "memory");
}

#define LOAD_A_TF32(frag, ptr, ldm) do { \
    wmma::load_matrix_sync(frag, ptr, ldm); \
    for (int _e = 0; _e < (frag).num_elements; _e++) \
        (frag).x[_e] = wmma::__float_to_tf32((frag).x[_e]); \
} while (0)

// ---------------- prep: out_W -> bf16 padded ----------------
__global__ __launch_bounds__(256) void k_prep(const float* __restrict__ out_W)
{
    size_t idx = (size_t)blockIdx.x * 256 + threadIdx.x;
    if (idx >= (size_t)RNN_ * V1P) return;
    int k = (int)(idx / V1P), v = (int)(idx % V1P);
    float w = (v < V1) ? out_W[(size_t)k * V1 + v] : 0.f;
    d_OWb[idx] = __float2bfloat16(w);
}

// =====================================================================
// k_wpg: WPG[16384,2560] = emb[words] @ [W_ih_word | w2g], tf32 WMMA.
// =====================================================================
#define WPG_SMEM 66048
__global__ __launch_bounds__(256) void k_wpg(
    const int* __restrict__ seqz, const float* __restrict__ emb,
    const float* __restrict__ W_ih, const float* __restrict__ w2g_W)
{
    extern __shared__ char smraw[];
    float* As_ = (float*)smraw;                 // [2][128][32]
    float* Bs_ = (float*)(smraw + 32768);       // [2][32][128]
    int*  stok = (int*)(smraw + 65536);         // [128]
    const int tid = threadIdx.x;
    const int n0 = blockIdx.x * 128;
    const int m0 = blockIdx.y * 128;
    const int wid = tid >> 5;
    const int warp_m = wid >> 1;
    const int warp_n = wid & 1;
    uint32_t aB = (uint32_t)__cvta_generic_to_shared(As_);
    uint32_t bB = (uint32_t)__cvta_generic_to_shared(Bs_);

    if (tid < 128) {
        int row = m0 + tid;
        int t = row >> 8, b = row & 255;
        stok[tid] = (t == 0) ? (VOCAB_ + 1) : seqz[b * T_ + t - 1];
    }
    __syncthreads();

    auto issueA = [&](int s, int d) {
        int k0 = s * 32;
        #pragma unroll
        for (int j = 0; j < 4; j++) {
            int idx = tid + j * 256;
            int r = idx >> 3, sg = (idx & 7) << 2;
            cp16(aB + (uint32_t)((d * 4096 + r * 32 + sg) * 4),
                 emb + (size_t)stok[r] * RNN_ + k0 + sg);
        }
    };
    auto issueB = [&](int s, int d) {
        int k0 = s * 32;
        #pragma unroll
        for (int j = 0; j < 4; j++) {
            int idx = tid + j * 256;
            int kr = idx >> 5, c4 = (idx & 31) << 2;
            int kk = k0 + kr;
            const float* src = (n0 < 2048)
                ? W_ih + (size_t)(VIS_ + kk) * 2048 + n0 + c4
                : w2g_W + (size_t)kk * RNN_ + (n0 - 2048) + c4;
            cp16(bB + (uint32_t)((d * 4096 + kr * 128 + c4) * 4), src);
        }
    };

    wmma::fragment<wmma::accumulator, 16, 16, 8, float> acc[2][4];
    #pragma unroll
    for (int i = 0; i < 2; i++)
        #pragma unroll
        for (int j = 0; j < 4; j++) wmma::fill_fragment(acc[i][j], 0.f);

    issueA(0, 0); issueB(0, 0); cp_commit();
    for (int s = 0; s < 16; s++) {
        if (s < 15) { issueA(s + 1, (s + 1) & 1); issueB(s + 1, (s + 1) & 1); cp_commit(); cp_wait<1>(); }
        else        { cp_wait<0>(); }
        __syncthreads();
        int d = s & 1;
        #pragma unroll
        for (int k8 = 0; k8 < 4; k8++) {
            wmma::fragment<wmma::matrix_a, 16, 16, 8, wmma::precision::tf32, wmma::row_major> af[2];
            wmma::fragment<wmma::matrix_b, 16, 16, 8, wmma::precision::tf32, wmma::row_major> bf[4];
            #pragma unroll
            for (int i = 0; i < 2; i++)
                LOAD_A_TF32(af[i], As_ + d * 4096 + (warp_m * 32 + i * 16) * 32 + k8 * 8, 32);
            #pragma unroll
            for (int j = 0; j < 4; j++)
                LOAD_A_TF32(bf[j], Bs_ + d * 4096 + (k8 * 8) * 128 + warp_n * 64 + j * 16, 128);
            #pragma unroll
            for (int i = 0; i < 2; i++)
                #pragma unroll
                for (int j = 0; j < 4; j++)
                    wmma::mma_sync(acc[i][j], af[i], bf[j], acc[i][j]);
        }
        __syncthreads();
    }
    #pragma unroll
    for (int i = 0; i < 2; i++)
        #pragma unroll
        for (int j = 0; j < 4; j++)
            wmma::store_matrix_sync(
                d_WPG + (size_t)(m0 + warp_m * 32 + i * 16) * GEXT + n0 + warp_n * 64 + j * 16,
                acc[i][j], GEXT, wmma::mem_row_major);
}

// =====================================================================
// k_rnn v4: 128 persistent CTAs, bf16 resident recurrence weights.
// CTA (ct&1 -> 128 batch rows, ct>>1 -> 8 units x 5 gates = 40 cols/48).
// Per step: wp tile + h slices via cp.async, bf16 WMMA k16, CTA-local
// pointwise from smem, 1 global barrier.
// =====================================================================
// smem layout (bytes):
//   0      Wres  bf16 [512][48]          49152
//   49152  As    bf16 [2][128][64]       32768   (alias: prologue f32 A [2][128][32]; gsm f32 [128][48])
//   81920  vpgr  f32  [128][40]          20480
//   102400 wpsm  f32  [128][40]          20480
//   122880 cst   f32  [128][8]            4096
//   126976 bscr  f32  [2][32][48]        12288   (prologue B)
#define RNN_SMEM 139264
__global__ __launch_bounds__(256) void k_rnn(
    const float* __restrict__ vis,
    const float* __restrict__ W_ih,    const float* __restrict__ W_hh,
    const float* __restrict__ b_lstm,
    const float* __restrict__ vis2g_W, const float* __restrict__ vis2g_b,
    const float* __restrict__ h2g_W)
{
    extern __shared__ char smraw[];
    __nv_bfloat16* Wres = (__nv_bfloat16*)smraw;
    __nv_bfloat16* Asb  = (__nv_bfloat16*)(smraw + 49152);
    float* Asf  = (float*)(smraw + 49152);        // prologue A (f32)
    float* gsm  = (float*)(smraw + 49152);        // gates result (f32, after GEMM)
    float* vpgr = (float*)(smraw + 81920);
    float* wpsm = (float*)(smraw + 102400);
    float* cst  = (float*)(smraw + 122880);
    float* bscr = (float*)(smraw + 126976);

    const int tid = threadIdx.x;
    const int ct  = blockIdx.x;
    const int wid = tid >> 5;                      // 0..7, 16 rows each
    const int u0  = (ct >> 1) * 8;
    const int m0  = (ct & 1) * 128;
    unsigned ls = 0;
    uint32_t aB = (uint32_t)__cvta_generic_to_shared(smraw + 49152);
    uint32_t bB = (uint32_t)__cvta_generic_to_shared(bscr);
    uint32_t wpB = (uint32_t)__cvta_generic_to_shared(wpsm);

    // ---- init: cst zero, bscr pad cols, own h0 slice zero (bf16) ----
    #pragma unroll
    for (int j = 0; j < 4; j++) {
        int e = tid + j * 256;                     // 0..1023
        cst[e] = 0.f;
        int r = e >> 3, u = e & 7;
        d_hbuf[0][(m0 + r) * RNN_ + u0 + u] = __float2bfloat16(0.f);
    }
    #pragma unroll
    for (int j = 0; j < 2; j++) {
        int e = tid + j * 256;                     // 0..511
        int d = e >> 8, rr = (e >> 3) & 31, c = 40 + (e & 7);
        bscr[d * 1536 + rr * 48 + c] = 0.f;
    }
    __syncthreads();

    // ---- prologue GEMM (tf32): vis-part gates, K=1024, 32 slices of 32 ----
    {
        wmma::fragment<wmma::accumulator, 16, 16, 8, float> acc[3];
        #pragma unroll
        for (int f = 0; f < 3; f++) wmma::fill_fragment(acc[f], 0.f);

        auto issA = [&](int s, int d) {
            int k0 = s * 32;
            #pragma unroll
            for (int j = 0; j < 4; j++) {
                int idx = tid + j * 256;
                int r = idx >> 3, sg = (idx & 7) << 2;
                cp16(aB + (uint32_t)((d * 4096 + r * 32 + sg) * 4),
                     vis + (size_t)(m0 + r) * VIS_ + k0 + sg);
            }
        };
        auto issB = [&](int s, int d) {
            int k0 = s * 32;
            #pragma unroll
            for (int j = 0; j < 2; j++) {
                int e = tid + j * 256;
                if (e < 320) {
                    int r = e / 10, q = e % 10;
                    int g = q >> 1, c4 = (q & 1) << 2;
                    int kk = k0 + r;
                    const float* src = (g < 4)
                        ? W_ih + (size_t)kk * 2048 + g * 512 + u0 + c4
                        : vis2g_W + (size_t)kk * RNN_ + u0 + c4;
                    cp16(bB + (uint32_t)((d * 1536 + r * 48 + q * 4) * 4), src);
                }
            }
        };

        issA(0, 0); issB(0, 0); cp_commit();
        for (int s = 0; s < 32; s++) {
            if (s < 31) { issA(s + 1, (s + 1) & 1); issB(s + 1, (s + 1) & 1); cp_commit(); cp_wait<1>(); }
            else        { cp_wait<0>(); }
            __syncthreads();
            int d = s & 1;
            #pragma unroll
            for (int k8 = 0; k8 < 4; k8++) {
                wmma::fragment<wmma::matrix_a, 16, 16, 8, wmma::precision::tf32, wmma::row_major> af;
                LOAD_A_TF32(af, Asf + d * 4096 + (wid * 16) * 32 + k8 * 8, 32);
                #pragma unroll
                for (int f = 0; f < 3; f++) {
                    wmma::fragment<wmma::matrix_b, 16, 16, 8, wmma::precision::tf32, wmma::row_major> bf;
                    LOAD_A_TF32(bf, bscr + d * 1536 + (k8 * 8) * 48 + f * 16, 48);
                    wmma::mma_sync(acc[f], af, bf, acc[f]);
                }
            }
            __syncthreads();
        }
        #pragma unroll
        for (int f = 0; f < 3; f++)
            wmma::store_matrix_sync(gsm + (wid * 16) * 48 + f * 16, acc[f], 48, wmma::mem_row_major);
        __syncthreads();
    }

    // vpgr = gsm + bias
    #pragma unroll
    for (int j = 0; j < 20; j++) {
        int e = tid + j * 256;                     // 0..5119 = 128 x 40
        int r = e / 40, q = e % 40;
        int g = q >> 3, u = q & 7;
        float bias = (g < 4) ? b_lstm[g * 512 + u0 + u] : vis2g_b[u0 + u];
        vpgr[r * 40 + q] = gsm[r * 48 + q] + bias;
    }
    __syncthreads();

    // ---- load resident bf16 recurrence weights [512][48] ----
    #pragma unroll
    for (int j = 0; j < 80; j++) {
        int e = tid + j * 256;                     // 0..20479
        int k = e / 40, q = e % 40;
        int g = q >> 3, u = q & 7;
        float w = (g < 4) ? W_hh[(size_t)k * 2048 + g * 512 + u0 + u]
                          : h2g_W[(size_t)k * RNN_ + u0 + u];
        Wres[k * 48 + q] = __float2bfloat16(w);
    }
    #pragma unroll
    for (int j = 0; j < 16; j++) {
        int e = tid + j * 256;                     // 0..4095
        int k = e >> 3, c = 40 + (e & 7);
        Wres[k * 48 + c] = __float2bfloat16(0.f);
    }
    gbar(ls);                                      // barrier #1

    // ---- 64 steps ----
    for (int t = 0; t < T_; t++) {
        const __nv_bfloat16* hb = d_hbuf[t & 1];
        __nv_bfloat16* hn = d_hbuf[(t & 1) ^ 1];
        const float* wpbase = d_WPG + (size_t)(t * 256 + m0) * GEXT;

        auto issH = [&](int s, int d) {
            int k0 = s * 64;
            #pragma unroll
            for (int j = 0; j < 4; j++) {
                int idx = tid + j * 256;           // 0..1023
                int r = idx >> 3, c8 = (idx & 7) << 3;   // 8 bf16 = 16B
                cp16(aB + (uint32_t)((d * 128 + r) * 64 + c8) * 2,
                     hb + (size_t)(m0 + r) * RNN_ + k0 + c8);
            }
        };
        // wp tile prefetch (group shared with slice 0)
        {
            #pragma unroll
            for (int j = 0; j < 5; j++) {
                int e = tid + j * 256;             // 0..1279
                int r = e / 10, q = e % 10;
                int g = q >> 1, half = q & 1;
                cp16(wpB + (uint32_t)((r * 40 + g * 8 + half * 4) * 4),
                     wpbase + (size_t)r * GEXT + g * 512 + u0 + half * 4);
            }
        }

        wmma::fragment<wmma::accumulator, 16, 16, 16, float> acc[3];
        #pragma unroll
        for (int f = 0; f < 3; f++) wmma::fill_fragment(acc[f], 0.f);

        issH(0, 0); cp_commit();
        for (int s = 0; s < 8; s++) {
            if (s < 7) { issH(s + 1, (s + 1) & 1); cp_commit(); cp_wait<1>(); }
            else       { cp_wait<0>(); }
            __syncthreads();
            int d = s & 1;
            #pragma unroll
            for (int k16 = 0; k16 < 4; k16++) {
                wmma::fragment<wmma::matrix_a, 16, 16, 16, __nv_bfloat16, wmma::row_major> af;
                wmma::load_matrix_sync(af, Asb + (d * 128 + wid * 16) * 64 + k16 * 16, 64);
                #pragma unroll
                for (int f = 0; f < 3; f++) {
                    wmma::fragment<wmma::matrix_b, 16, 16, 16, __nv_bfloat16, wmma::row_major> bf;
                    wmma::load_matrix_sync(bf, Wres + (s * 64 + k16 * 16) * 48 + f * 16, 48);
                    wmma::mma_sync(acc[f], af, bf, acc[f]);
                }
            }
            __syncthreads();
        }
        #pragma unroll
        for (int f = 0; f < 3; f++)
            wmma::store_matrix_sync(gsm + (wid * 16) * 48 + f * 16, acc[f], 48, wmma::mem_row_major);
        __syncthreads();

        // pointwise: 128 rows x 8 units, all-smem operands
        #pragma unroll
        for (int j = 0; j < 4; j++) {
            int e = tid + j * 256;                 // 0..1023
            int r = e >> 3, u = e & 7;
            const float* gg = gsm + r * 48;
            const float* vp = vpgr + r * 40;
            const float* wp = wpsm + r * 40;
            float ig = gg[u]      + vp[u]      + wp[u];
            float fg = gg[8 + u]  + vp[8 + u]  + wp[8 + u];
            float g_ = gg[16 + u] + vp[16 + u] + wp[16 + u];
            float og = gg[24 + u] + vp[24 + u] + wp[24 + u];
            float gp = gg[32 + u] + vp[32 + u] + wp[32 + u];
            float cold = cst[e];
            float cn = sig_f(fg) * cold + sig_f(ig) * tanh_f(g_);
            float tc = tanh_f(cn);
            cst[e] = cn;
            hn[(m0 + r) * RNN_ + u0 + u] = __float2bfloat16(sig_f(og) * tc);
            d_Sb[(size_t)(t * 256 + m0 + r) * RNN_ + u0 + u] =
                __float2bfloat16(sig_f(gp) * tc);
        }
        gbar(ls);                                  // h(t) published
    }
    gbar(ls);   // barriers: 1 + 64 + 1 = 66 (even -> state restored)
}

// =====================================================================
// k_lse v3: 128 rows/CTA, 512 threads (16 warps), chunk 32 double-buffered,
// bf16 WMMA + f16x2 packed exp; exact fp32 target logit.
// =====================================================================
#define LSE_SMEM 212992
#define NCH 313                                    // ceil(10001/32)
__global__ __launch_bounds__(512) void k_lse(
    const float* __restrict__ out_b,
    const int* __restrict__ seqz, float* __restrict__ out)
{
    extern __shared__ unsigned char dyn[];
    __nv_bfloat16* Asm = (__nv_bfloat16*)dyn;             // 128 x 512 (128 KB)
    __nv_bfloat16* Bsm = (__nv_bfloat16*)(dyn + 131072);  // 2 x (512 x 32) (64 KB)
    float*         Csm = (float*)(dyn + 196608);          // 128 x 32 (16 KB)
    __shared__ float s_tgt[128];
    __shared__ int   s_tg[128];
    __shared__ float red_s[4][128];

    const int tid = threadIdx.x;
    const int m0  = blockIdx.x * 128;
    const int wid = tid >> 5;                      // 0..15
    const int warp_m = wid >> 1;                   // 0..7 (16 rows)
    const int warp_n = wid & 1;                    // 0..1 (16 cols)
    uint32_t bB = (uint32_t)__cvta_generic_to_shared(Bsm);

    if (tid < 128) {
        int r = m0 + tid;
        int t = r >> 8, b = r & 255;
        s_tg[tid] = seqz[b * T_ + t];
    }

    // A tile resident: 128 x 512 bf16 = 8192 uint4
    #pragma unroll
    for (int i = 0; i < 16; i++) {
        int idx = tid + i * 512;
        int r = idx >> 6, c = idx & 63;
        ((uint4*)Asm)[idx] = ((const uint4*)(d_Sb + (size_t)(m0 + r) * RNN_))[c];
    }
    __syncthreads();

    auto issueB = [&](int ch, int d) {
        int v0 = ch * 32;
        #pragma unroll
        for (int j = 0; j < 4; j++) {
            int idx = tid + j * 512;               // 0..2047
            int k = idx >> 2, c8 = (idx & 3) << 3;
            cp16(bB + (uint32_t)(d * 32768 + (k * 32 + c8) * 2),
                 d_OWb + (size_t)k * V1P + v0 + c8);
        }
    };

    const int row = tid >> 2;                      // 0..127
    const int qtr = tid & 3;                       // 8 cols each
    const int mytg = s_tg[row];
    float rs = 0.f;

    issueB(0, 0); cp_commit();
    for (int c = 0; c < NCH; c++) {
        if (c < NCH - 1) { issueB(c + 1, (c + 1) & 1); cp_commit(); cp_wait<1>(); }
        else             { cp_wait<0>(); }
        __syncthreads();

        const __nv_bfloat16* Bcur = Bsm + (c & 1) * 16384;
        wmma::fragment<wmma::accumulator, 16, 16, 16, float> acc;
        wmma::fill_fragment(acc, 0.f);
        #pragma unroll
        for (int k = 0; k < 32; k++) {
            wmma::fragment<wmma::matrix_a, 16, 16, 16, __nv_bfloat16, wmma::row_major> af;
            wmma::fragment<wmma::matrix_b, 16, 16, 16, __nv_bfloat16, wmma::row_major> bf;
            wmma::load_matrix_sync(af, Asm + (warp_m * 16) * 512 + k * 16, 512);
            wmma::load_matrix_sync(bf, Bcur + (k * 16) * 32 + warp_n * 16, 32);
            wmma::mma_sync(acc, af, bf, acc);
        }
        wmma::store_matrix_sync(Csm + (warp_m * 16) * 32 + warp_n * 16,
                                acc, 32, wmma::mem_row_major);
        __syncthreads();

        // epilogue: 4 threads/row x 8 cols, packed f16x2 exp
        int v0 = c * 32;
        float lsum = 0.f;
        #pragma unroll
        for (int j = 0; j < 4; j++) {
            int cc = (qtr << 3) + 2 * j;
            int v = v0 + cc;
            float l0 = (v     < V1) ? (Csm[row * 32 + cc]     + out_b[v])     : -1e4f;
            float l1 = (v + 1 < V1) ? (Csm[row * 32 + cc + 1] + out_b[v + 1]) : -1e4f;
            uint32_t h2, e2;
            asm("cvt.rn.f16x2.f32 %0, %1, %2;" : "=r"(h2) : "f"(l1 * LOG2E), "f"(l0 * LOG2E));
            asm("ex2.approx.f16x2 %0, %1;" : "=r"(e2) : "r"(h2));
            __half2 hh = *reinterpret_cast<__half2*>(&e2);
            float2 ff = __half22float2(hh);
            lsum += ff.x + ff.y;
        }
        rs += lsum;
        if (mytg >= v0 && mytg < v0 + 32 && ((mytg - v0) >> 3) == qtr)
            s_tgt[row] = Csm[row * 32 + (mytg - v0)] + out_b[mytg];
        __syncthreads();
    }

    red_s[qtr][row] = rs;
    __syncthreads();
    if (tid < 128) {
        int r = m0 + tid;
        float S = red_s[0][tid] + red_s[1][tid] + red_s[2][tid] + red_s[3][tid];
        float lse = logf(S);
        int t = r >> 8, b = r & 255;
        float mask = (t == 0) ? 1.f : ((seqz[b * T_ + (t - 1)] != 0) ? 1.f : 0.f);
        out[r] = (s_tgt[tid] - lse) * mask;
    }
}

// ---------------- launch ----------------
extern "C" void kernel_launch(void* const* d_in, const int* in_sizes, int n_in,
                              void* d_out, int out_size)
{
    const float *vis = 0, *emb = 0, *W_ih = 0, *W_hh = 0, *b_lstm = 0;
    const float *vis2g_W = 0, *vis2g_b = 0, *w2g_W = 0, *h2g_W = 0;
    const float *out_W = 0, *out_b = 0;
    const int *seqz = 0;
    int trio[3]; int ntrio = 0;
    for (int i = 0; i < n_in; i++) {
        switch (in_sizes[i]) {
            case 16384:   seqz    = (const int*)  d_in[i]; break;
            case 5121024: emb     = (const float*)d_in[i]; break;
            case 3145728: W_ih    = (const float*)d_in[i]; break;
            case 1048576: W_hh    = (const float*)d_in[i]; break;
            case 2048:    b_lstm  = (const float*)d_in[i]; break;
            case 524288:  vis2g_W = (const float*)d_in[i]; break;
            case 512:     vis2g_b = (const float*)d_in[i]; break;
            case 5120512: out_W   = (const float*)d_in[i]; break;
            case 10001:   out_b   = (const float*)d_in[i]; break;
            case 262144:  if (ntrio < 3) trio[ntrio++] = i; break;
            default: break;
        }
    }
    if (ntrio == 3) {
        vis   = (const float*)d_in[trio[0]];
        w2g_W = (const float*)d_in[trio[1]];
        h2g_W = (const float*)d_in[trio[2]];
    }
    if (!vis)     vis     = (const float*)d_in[0];
    if (!seqz)    seqz    = (const int*)  d_in[1];
    if (!emb)     emb     = (const float*)d_in[2];
    if (!W_ih)    W_ih    = (const float*)d_in[3];
    if (!W_hh)    W_hh    = (const float*)d_in[4];
    if (!b_lstm)  b_lstm  = (const float*)d_in[5];
    if (!vis2g_W) vis2g_W = (const float*)d_in[6];
    if (!vis2g_b) vis2g_b = (const float*)d_in[7];
    if (!w2g_W)   w2g_W   = (const float*)d_in[8];
    if (!h2g_W)   h2g_W   = (const float*)d_in[9];
    if (!out_W)   out_W   = (const float*)d_in[10];
    if (!out_b)   out_b   = (const float*)d_in[11];
    float* out = (float*)d_out;

    cudaFuncSetAttribute(k_wpg, cudaFuncAttributeMaxDynamicSharedMemorySize, WPG_SMEM);
    cudaFuncSetAttribute(k_rnn, cudaFuncAttributeMaxDynamicSharedMemorySize, RNN_SMEM);
    cudaFuncSetAttribute(k_lse, cudaFuncAttributeMaxDynamicSharedMemorySize, LSE_SMEM);

    k_prep<<<(int)(((size_t)RNN_ * V1P + 255) / 256), 256>>>(out_W);
    k_wpg<<<dim3(20, 128), 256, WPG_SMEM>>>(seqz, emb, W_ih, w2g_W);
    k_rnn<<<NCTA, 256, RNN_SMEM>>>(vis, W_ih, W_hh, b_lstm, vis2g_W, vis2g_b, h2g_W);
    k_lse<<<TB / 128, 512, LSE_SMEM>>>(out_b, seqz, out);
}

// round 14
// speedup vs baseline: 2.3006x; 1.2022x over previous
#include <cuda_runtime.h>
#include <cuda_bf16.h>
#include <cuda_fp16.h>
#include <mma.h>
#include <math.h>
#include <stdint.h>

using namespace nvcuda;

#define B_     256
#define T_     64
#define VOCAB_ 10000
#define V1     10001
#define V1P    10240
#define VIS_   1024
#define RNN_   512
#define GEXT   2560
#define TB     16384
#define NCTA   128
#define LOG2E  1.4426950408889634f

// ---------------- scratch ----------------
__device__ __nv_bfloat16 d_hbuf[2][B_ * RNN_];
__device__ float d_WPG[(size_t)TB * GEXT];            // word-part gates (168 MB)
__device__ __nv_bfloat16 d_Sb [(size_t)TB * RNN_];    // sentinel states bf16
__device__ __nv_bfloat16 d_OWb[(size_t)RNN_ * V1P];   // out_W bf16 padded

__device__ unsigned g_cnt = 0;
__device__ volatile unsigned g_sense = 0;

__device__ __forceinline__ void gbar(unsigned &ls)
{
    __syncthreads();
    if (threadIdx.x == 0) {
        ls ^= 1u;
        __threadfence();
        if (atomicAdd(&g_cnt, 1u) == NCTA - 1u) {
            g_cnt = 0u;
            __threadfence();
            g_sense = ls;
        } else {
            while (g_sense != ls) { }
            __threadfence();
        }
    }
    __syncthreads();
}

__device__ __forceinline__ float tanh_f(float x)
{
    float y;
    asm("tanh.approx.f32 %0, %1;" : "=f"(y) : "f"(x));
    return y;
}
__device__ __forceinline__ float sig_f(float x)
{
    return fmaf(0.5f, tanh_f(0.5f * x), 0.5f);
}

__device__ __forceinline__ void cp16(uint32_t dst, const void* src)
{
    asm volatile("cp.async.cg.shared.global [%0], [%1], 16;" :: "r"(dst), "l"(src));
}
__device__ __forceinline__ void cp_commit()
{
    asm volatile("cp.async.commit_group;" ::: "memory");
}
template<int N> __device__ __forceinline__ void cp_wait()
{
    asm volatile("cp.async.wait_group %0;" :: "n"(N) : "memory");
}

#define LOAD_A_TF32(frag, ptr, ldm) do { \
    wmma::load_matrix_sync(frag, ptr, ldm); \
    for (int _e = 0; _e < (frag).num_elements; _e++) \
        (frag).x[_e] = wmma::__float_to_tf32((frag).x[_e]); \
} while (0)

// ---------------- prep: out_W -> bf16 padded ----------------
__global__ __launch_bounds__(256) void k_prep(const float* __restrict__ out_W)
{
    size_t idx = (size_t)blockIdx.x * 256 + threadIdx.x;
    if (idx >= (size_t)RNN_ * V1P) return;
    int k = (int)(idx / V1P), v = (int)(idx % V1P);
    float w = (v < V1) ? out_W[(size_t)k * V1 + v] : 0.f;
    d_OWb[idx] = __float2bfloat16(w);
}

// =====================================================================
// k_wpg: WPG[16384,2560] = emb[words] @ [W_ih_word | w2g], tf32 WMMA.
// =====================================================================
#define WPG_SMEM 66048
__global__ __launch_bounds__(256) void k_wpg(
    const int* __restrict__ seqz, const float* __restrict__ emb,
    const float* __restrict__ W_ih, const float* __restrict__ w2g_W)
{
    extern __shared__ char smraw[];
    float* As_ = (float*)smraw;                 // [2][128][32]
    float* Bs_ = (float*)(smraw + 32768);       // [2][32][128]
    int*  stok = (int*)(smraw + 65536);         // [128]
    const int tid = threadIdx.x;
    const int n0 = blockIdx.x * 128;
    const int m0 = blockIdx.y * 128;
    const int wid = tid >> 5;
    const int warp_m = wid >> 1;
    const int warp_n = wid & 1;
    uint32_t aB = (uint32_t)__cvta_generic_to_shared(As_);
    uint32_t bB = (uint32_t)__cvta_generic_to_shared(Bs_);

    if (tid < 128) {
        int row = m0 + tid;
        int t = row >> 8, b = row & 255;
        stok[tid] = (t == 0) ? (VOCAB_ + 1) : seqz[b * T_ + t - 1];
    }
    __syncthreads();

    auto issueA = [&](int s, int d) {
        int k0 = s * 32;
        #pragma unroll
        for (int j = 0; j < 4; j++) {
            int idx = tid + j * 256;
            int r = idx >> 3, sg = (idx & 7) << 2;
            cp16(aB + (uint32_t)((d * 4096 + r * 32 + sg) * 4),
                 emb + (size_t)stok[r] * RNN_ + k0 + sg);
        }
    };
    auto issueB = [&](int s, int d) {
        int k0 = s * 32;
        #pragma unroll
        for (int j = 0; j < 4; j++) {
            int idx = tid + j * 256;
            int kr = idx >> 5, c4 = (idx & 31) << 2;
            int kk = k0 + kr;
            const float* src = (n0 < 2048)
                ? W_ih + (size_t)(VIS_ + kk) * 2048 + n0 + c4
                : w2g_W + (size_t)kk * RNN_ + (n0 - 2048) + c4;
            cp16(bB + (uint32_t)((d * 4096 + kr * 128 + c4) * 4), src);
        }
    };

    wmma::fragment<wmma::accumulator, 16, 16, 8, float> acc[2][4];
    #pragma unroll
    for (int i = 0; i < 2; i++)
        #pragma unroll
        for (int j = 0; j < 4; j++) wmma::fill_fragment(acc[i][j], 0.f);

    issueA(0, 0); issueB(0, 0); cp_commit();
    for (int s = 0; s < 16; s++) {
        if (s < 15) { issueA(s + 1, (s + 1) & 1); issueB(s + 1, (s + 1) & 1); cp_commit(); cp_wait<1>(); }
        else        { cp_wait<0>(); }
        __syncthreads();
        int d = s & 1;
        #pragma unroll
        for (int k8 = 0; k8 < 4; k8++) {
            wmma::fragment<wmma::matrix_a, 16, 16, 8, wmma::precision::tf32, wmma::row_major> af[2];
            wmma::fragment<wmma::matrix_b, 16, 16, 8, wmma::precision::tf32, wmma::row_major> bf[4];
            #pragma unroll
            for (int i = 0; i < 2; i++)
                LOAD_A_TF32(af[i], As_ + d * 4096 + (warp_m * 32 + i * 16) * 32 + k8 * 8, 32);
            #pragma unroll
            for (int j = 0; j < 4; j++)
                LOAD_A_TF32(bf[j], Bs_ + d * 4096 + (k8 * 8) * 128 + warp_n * 64 + j * 16, 128);
            #pragma unroll
            for (int i = 0; i < 2; i++)
                #pragma unroll
                for (int j = 0; j < 4; j++)
                    wmma::mma_sync(acc[i][j], af[i], bf[j], acc[i][j]);
        }
        __syncthreads();
    }
    #pragma unroll
    for (int i = 0; i < 2; i++)
        #pragma unroll
        for (int j = 0; j < 4; j++)
            wmma::store_matrix_sync(
                d_WPG + (size_t)(m0 + warp_m * 32 + i * 16) * GEXT + n0 + warp_n * 64 + j * 16,
                acc[i][j], GEXT, wmma::mem_row_major);
}

// =====================================================================
// k_rnn v5: as v4 but K streamed in 4 slices of 128 (half the syncs).
// smem layout (bytes):
//   0      Wres bf16 [512][48]           49152
//   49152  Asb  bf16 [2][128][128]       65536 (alias: prologue f32 A; gsm f32[128][48])
//   114688 vpgr f32  [128][40]           20480
//   135168 wpsm f32  [128][40]           20480
//   155648 cst  f32  [128][8]             4096
//   159744 bscr f32  [2][32][48]         12288
#define RNN_SMEM 172032
__global__ __launch_bounds__(256) void k_rnn(
    const float* __restrict__ vis,
    const float* __restrict__ W_ih,    const float* __restrict__ W_hh,
    const float* __restrict__ b_lstm,
    const float* __restrict__ vis2g_W, const float* __restrict__ vis2g_b,
    const float* __restrict__ h2g_W)
{
    extern __shared__ char smraw[];
    __nv_bfloat16* Wres = (__nv_bfloat16*)smraw;
    __nv_bfloat16* Asb  = (__nv_bfloat16*)(smraw + 49152);
    float* Asf  = (float*)(smraw + 49152);
    float* gsm  = (float*)(smraw + 49152);
    float* vpgr = (float*)(smraw + 114688);
    float* wpsm = (float*)(smraw + 135168);
    float* cst  = (float*)(smraw + 155648);
    float* bscr = (float*)(smraw + 159744);

    const int tid = threadIdx.x;
    const int ct  = blockIdx.x;
    const int wid = tid >> 5;
    const int u0  = (ct >> 1) * 8;
    const int m0  = (ct & 1) * 128;
    unsigned ls = 0;
    uint32_t aB = (uint32_t)__cvta_generic_to_shared(smraw + 49152);
    uint32_t bB = (uint32_t)__cvta_generic_to_shared(bscr);
    uint32_t wpB = (uint32_t)__cvta_generic_to_shared(wpsm);

    #pragma unroll
    for (int j = 0; j < 4; j++) {
        int e = tid + j * 256;
        cst[e] = 0.f;
        int r = e >> 3, u = e & 7;
        d_hbuf[0][(m0 + r) * RNN_ + u0 + u] = __float2bfloat16(0.f);
    }
    #pragma unroll
    for (int j = 0; j < 2; j++) {
        int e = tid + j * 256;
        int d = e >> 8, rr = (e >> 3) & 31, c = 40 + (e & 7);
        bscr[d * 1536 + rr * 48 + c] = 0.f;
    }
    __syncthreads();

    // ---- prologue GEMM (tf32): vis gates, K=1024, 32 slices of 32 ----
    {
        wmma::fragment<wmma::accumulator, 16, 16, 8, float> acc[3];
        #pragma unroll
        for (int f = 0; f < 3; f++) wmma::fill_fragment(acc[f], 0.f);

        auto issA = [&](int s, int d) {
            int k0 = s * 32;
            #pragma unroll
            for (int j = 0; j < 4; j++) {
                int idx = tid + j * 256;
                int r = idx >> 3, sg = (idx & 7) << 2;
                cp16(aB + (uint32_t)((d * 4096 + r * 32 + sg) * 4),
                     vis + (size_t)(m0 + r) * VIS_ + k0 + sg);
            }
        };
        auto issB = [&](int s, int d) {
            int k0 = s * 32;
            #pragma unroll
            for (int j = 0; j < 2; j++) {
                int e = tid + j * 256;
                if (e < 320) {
                    int r = e / 10, q = e % 10;
                    int g = q >> 1, c4 = (q & 1) << 2;
                    int kk = k0 + r;
                    const float* src = (g < 4)
                        ? W_ih + (size_t)kk * 2048 + g * 512 + u0 + c4
                        : vis2g_W + (size_t)kk * RNN_ + u0 + c4;
                    cp16(bB + (uint32_t)((d * 1536 + r * 48 + q * 4) * 4), src);
                }
            }
        };

        issA(0, 0); issB(0, 0); cp_commit();
        for (int s = 0; s < 32; s++) {
            if (s < 31) { issA(s + 1, (s + 1) & 1); issB(s + 1, (s + 1) & 1); cp_commit(); cp_wait<1>(); }
            else        { cp_wait<0>(); }
            __syncthreads();
            int d = s & 1;
            #pragma unroll
            for (int k8 = 0; k8 < 4; k8++) {
                wmma::fragment<wmma::matrix_a, 16, 16, 8, wmma::precision::tf32, wmma::row_major> af;
                LOAD_A_TF32(af, Asf + d * 4096 + (wid * 16) * 32 + k8 * 8, 32);
                #pragma unroll
                for (int f = 0; f < 3; f++) {
                    wmma::fragment<wmma::matrix_b, 16, 16, 8, wmma::precision::tf32, wmma::row_major> bf;
                    LOAD_A_TF32(bf, bscr + d * 1536 + (k8 * 8) * 48 + f * 16, 48);
                    wmma::mma_sync(acc[f], af, bf, acc[f]);
                }
            }
            __syncthreads();
        }
        #pragma unroll
        for (int f = 0; f < 3; f++)
            wmma::store_matrix_sync(gsm + (wid * 16) * 48 + f * 16, acc[f], 48, wmma::mem_row_major);
        __syncthreads();
    }

    #pragma unroll
    for (int j = 0; j < 20; j++) {
        int e = tid + j * 256;
        int r = e / 40, q = e % 40;
        int g = q >> 3, u = q & 7;
        float bias = (g < 4) ? b_lstm[g * 512 + u0 + u] : vis2g_b[u0 + u];
        vpgr[r * 40 + q] = gsm[r * 48 + q] + bias;
    }
    __syncthreads();

    // resident bf16 recurrence weights [512][48]
    #pragma unroll
    for (int j = 0; j < 80; j++) {
        int e = tid + j * 256;
        int k = e / 40, q = e % 40;
        int g = q >> 3, u = q & 7;
        float w = (g < 4) ? W_hh[(size_t)k * 2048 + g * 512 + u0 + u]
                          : h2g_W[(size_t)k * RNN_ + u0 + u];
        Wres[k * 48 + q] = __float2bfloat16(w);
    }
    #pragma unroll
    for (int j = 0; j < 16; j++) {
        int e = tid + j * 256;
        int k = e >> 3, c = 40 + (e & 7);
        Wres[k * 48 + c] = __float2bfloat16(0.f);
    }
    gbar(ls);                                      // barrier #1

    // ---- 64 steps, 4 slices of K=128 ----
    for (int t = 0; t < T_; t++) {
        const __nv_bfloat16* hb = d_hbuf[t & 1];
        __nv_bfloat16* hn = d_hbuf[(t & 1) ^ 1];
        const float* wpbase = d_WPG + (size_t)(t * 256 + m0) * GEXT;

        auto issH = [&](int s, int d) {
            int k0 = s * 128;
            #pragma unroll
            for (int j = 0; j < 8; j++) {
                int idx = tid + j * 256;           // 0..2047
                int r = idx >> 4, c8 = (idx & 15) << 3;
                cp16(aB + (uint32_t)((d * 128 + r) * 128 + c8) * 2,
                     hb + (size_t)(m0 + r) * RNN_ + k0 + c8);
            }
        };
        {
            #pragma unroll
            for (int j = 0; j < 5; j++) {
                int e = tid + j * 256;
                int r = e / 10, q = e % 10;
                int g = q >> 1, half = q & 1;
                cp16(wpB + (uint32_t)((r * 40 + g * 8 + half * 4) * 4),
                     wpbase + (size_t)r * GEXT + g * 512 + u0 + half * 4);
            }
        }

        wmma::fragment<wmma::accumulator, 16, 16, 16, float> acc[3];
        #pragma unroll
        for (int f = 0; f < 3; f++) wmma::fill_fragment(acc[f], 0.f);

        issH(0, 0); cp_commit();
        for (int s = 0; s < 4; s++) {
            if (s < 3) { issH(s + 1, (s + 1) & 1); cp_commit(); cp_wait<1>(); }
            else       { cp_wait<0>(); }
            __syncthreads();
            int d = s & 1;
            #pragma unroll
            for (int k16 = 0; k16 < 8; k16++) {
                wmma::fragment<wmma::matrix_a, 16, 16, 16, __nv_bfloat16, wmma::row_major> af;
                wmma::load_matrix_sync(af, Asb + (d * 128 + wid * 16) * 128 + k16 * 16, 128);
                #pragma unroll
                for (int f = 0; f < 3; f++) {
                    wmma::fragment<wmma::matrix_b, 16, 16, 16, __nv_bfloat16, wmma::row_major> bf;
                    wmma::load_matrix_sync(bf, Wres + (s * 128 + k16 * 16) * 48 + f * 16, 48);
                    wmma::mma_sync(acc[f], af, bf, acc[f]);
                }
            }
            __syncthreads();
        }
        #pragma unroll
        for (int f = 0; f < 3; f++)
            wmma::store_matrix_sync(gsm + (wid * 16) * 48 + f * 16, acc[f], 48, wmma::mem_row_major);
        __syncthreads();

        #pragma unroll
        for (int j = 0; j < 4; j++) {
            int e = tid + j * 256;
            int r = e >> 3, u = e & 7;
            const float* gg = gsm + r * 48;
            const float* vp = vpgr + r * 40;
            const float* wp = wpsm + r * 40;
            float ig = gg[u]      + vp[u]      + wp[u];
            float fg = gg[8 + u]  + vp[8 + u]  + wp[8 + u];
            float g_ = gg[16 + u] + vp[16 + u] + wp[16 + u];
            float og = gg[24 + u] + vp[24 + u] + wp[24 + u];
            float gp = gg[32 + u] + vp[32 + u] + wp[32 + u];
            float cold = cst[e];
            float cn = sig_f(fg) * cold + sig_f(ig) * tanh_f(g_);
            float tc = tanh_f(cn);
            cst[e] = cn;
            hn[(m0 + r) * RNN_ + u0 + u] = __float2bfloat16(sig_f(og) * tc);
            d_Sb[(size_t)(t * 256 + m0 + r) * RNN_ + u0 + u] =
                __float2bfloat16(sig_f(gp) * tc);
        }
        gbar(ls);
    }
    gbar(ls);   // barriers: 1 + 64 + 1 = 66 (even)
}

// =====================================================================
// k_lse v4: 128 rows/CTA, 512 thr / 16 warps = (2 k-halves) x (4 m x 32)
// x (2 n x 32). Chunk 64 cols; B prefetched to registers via LDG during
// compute, stored to single smem buffer. K-halves reduced through Csm.
// Register blocking: 2af+2bf -> 4 mma (1 frag-load/mma).
// =====================================================================
// dyn smem: A bf16[128][512] @0 (131072); B bf16[512][64] @131072 (65536);
//           C f32[128][64] @196608 (32768); s_tgt f32[128] @229376 (512);
//           s_tg int[128] @229888 (512). total 230400.
#define LSE_SMEM 230400
#define NCH 157                                    // ceil(10001/64)
__global__ __launch_bounds__(512) void k_lse(
    const float* __restrict__ out_b,
    const int* __restrict__ seqz, float* __restrict__ out)
{
    extern __shared__ unsigned char dyn[];
    __nv_bfloat16* Asm = (__nv_bfloat16*)dyn;
    __nv_bfloat16* Bsm = (__nv_bfloat16*)(dyn + 131072);
    float*         Csm = (float*)(dyn + 196608);
    float*         s_tgt = (float*)(dyn + 229376);
    int*           s_tg  = (int*)(dyn + 229888);

    const int tid = threadIdx.x;
    const int m0  = blockIdx.x * 128;
    const int wid = tid >> 5;
    const int km  = wid & 1;                       // k-half
    const int wm  = (wid >> 1) & 3;                // 32-row group
    const int wn  = wid >> 3;                      // 32-col group

    if (tid < 128) {
        int r = m0 + tid;
        int t = r >> 8, b = r & 255;
        s_tg[tid] = seqz[b * T_ + t];
    }

    // A tile resident: 128 x 512 bf16 = 8192 uint4
    #pragma unroll
    for (int i = 0; i < 16; i++) {
        int idx = tid + i * 512;
        int r = idx >> 6, c = idx & 63;
        ((uint4*)Asm)[idx] = ((const uint4*)(d_Sb + (size_t)(m0 + r) * RNN_))[c];
    }
    __syncthreads();

    const int row = tid >> 2;                      // 0..127
    const int qtr = tid & 3;                       // 16 cols each
    const int mytg = s_tg[row];
    float rs = 0.f;

    // B register prefetch: 4096 uint4 / 512 thr = 8 per thread
    uint4 breg[8];
    auto ldB = [&](int ch) {
        int v0 = ch * 64;
        #pragma unroll
        for (int j = 0; j < 8; j++) {
            int idx = tid + j * 512;
            int k = idx >> 3, c8 = (idx & 7) << 3;
            breg[j] = *(const uint4*)(d_OWb + (size_t)k * V1P + v0 + c8);
        }
    };
    auto stB = [&]() {
        #pragma unroll
        for (int j = 0; j < 8; j++) {
            int idx = tid + j * 512;
            int k = idx >> 3, c8 = (idx & 7) << 3;
            *(uint4*)(Bsm + k * 64 + c8) = breg[j];
        }
    };

    ldB(0);
    for (int c = 0; c < NCH; c++) {
        stB();
        __syncthreads();                           // B visible
        if (c < NCH - 1) ldB(c + 1);               // overlap next-chunk LDG

        wmma::fragment<wmma::accumulator, 16, 16, 16, float> acc[2][2];
        #pragma unroll
        for (int i = 0; i < 2; i++)
            #pragma unroll
            for (int j = 0; j < 2; j++) wmma::fill_fragment(acc[i][j], 0.f);

        #pragma unroll
        for (int k = 0; k < 16; k++) {
            int kk = km * 16 + k;                  // k16 index 0..31
            wmma::fragment<wmma::matrix_a, 16, 16, 16, __nv_bfloat16, wmma::row_major> af[2];
            wmma::fragment<wmma::matrix_b, 16, 16, 16, __nv_bfloat16, wmma::row_major> bf[2];
            #pragma unroll
            for (int i = 0; i < 2; i++)
                wmma::load_matrix_sync(af[i], Asm + (wm * 32 + i * 16) * 512 + kk * 16, 512);
            #pragma unroll
            for (int j = 0; j < 2; j++)
                wmma::load_matrix_sync(bf[j], Bsm + (kk * 16) * 64 + wn * 32 + j * 16, 64);
            #pragma unroll
            for (int i = 0; i < 2; i++)
                #pragma unroll
                for (int j = 0; j < 2; j++)
                    wmma::mma_sync(acc[i][j], af[i], bf[j], acc[i][j]);
        }

        // k-half reduction through Csm
        if (km == 0) {
            #pragma unroll
            for (int i = 0; i < 2; i++)
                #pragma unroll
                for (int j = 0; j < 2; j++)
                    wmma::store_matrix_sync(Csm + (wm * 32 + i * 16) * 64 + wn * 32 + j * 16,
                                            acc[i][j], 64, wmma::mem_row_major);
        }
        __syncthreads();
        if (km == 1) {
            #pragma unroll
            for (int i = 0; i < 2; i++)
                #pragma unroll
                for (int j = 0; j < 2; j++) {
                    wmma::fragment<wmma::accumulator, 16, 16, 16, float> cf;
                    wmma::load_matrix_sync(cf, Csm + (wm * 32 + i * 16) * 64 + wn * 32 + j * 16,
                                           64, wmma::mem_row_major);
                    #pragma unroll
                    for (int e = 0; e < cf.num_elements; e++)
                        acc[i][j].x[e] += cf.x[e];
                    wmma::store_matrix_sync(Csm + (wm * 32 + i * 16) * 64 + wn * 32 + j * 16,
                                            acc[i][j], 64, wmma::mem_row_major);
                }
        }
        __syncthreads();

        // epilogue: 4 threads/row x 16 cols, packed f16x2 exp
        int v0 = c * 64;
        float lsum = 0.f;
        #pragma unroll
        for (int j = 0; j < 8; j++) {
            int cc = (qtr << 4) + 2 * j;
            int v = v0 + cc;
            float l0 = (v     < V1) ? (Csm[row * 64 + cc]     + out_b[v])     : -1e4f;
            float l1 = (v + 1 < V1) ? (Csm[row * 64 + cc + 1] + out_b[v + 1]) : -1e4f;
            uint32_t h2, e2;
            asm("cvt.rn.f16x2.f32 %0, %1, %2;" : "=r"(h2) : "f"(l1 * LOG2E), "f"(l0 * LOG2E));
            asm("ex2.approx.f16x2 %0, %1;" : "=r"(e2) : "r"(h2));
            __half2 hh = *reinterpret_cast<__half2*>(&e2);
            float2 ff = __half22float2(hh);
            lsum += ff.x + ff.y;
        }
        rs += lsum;
        if (mytg >= v0 + (qtr << 4) && mytg < v0 + (qtr << 4) + 16)
            s_tgt[row] = Csm[row * 64 + (mytg - v0)] + out_b[mytg];
        __syncthreads();                           // protect Bsm/Csm for next chunk
    }

    // reduce rs across the 4 contiguous lanes of each row (same warp)
    rs += __shfl_xor_sync(0xffffffffu, rs, 1);
    rs += __shfl_xor_sync(0xffffffffu, rs, 2);
    if (qtr == 0) {
        int r = m0 + row;
        float lse = logf(rs);
        int t = r >> 8, b = r & 255;
        float mask = (t == 0) ? 1.f : ((seqz[b * T_ + (t - 1)] != 0) ? 1.f : 0.f);
        out[r] = (s_tgt[row] - lse) * mask;
    }
}

// ---------------- launch ----------------
extern "C" void kernel_launch(void* const* d_in, const int* in_sizes, int n_in,
                              void* d_out, int out_size)
{
    const float *vis = 0, *emb = 0, *W_ih = 0, *W_hh = 0, *b_lstm = 0;
    const float *vis2g_W = 0, *vis2g_b = 0, *w2g_W = 0, *h2g_W = 0;
    const float *out_W = 0, *out_b = 0;
    const int *seqz = 0;
    int trio[3]; int ntrio = 0;
    for (int i = 0; i < n_in; i++) {
        switch (in_sizes[i]) {
            case 16384:   seqz    = (const int*)  d_in[i]; break;
            case 5121024: emb     = (const float*)d_in[i]; break;
            case 3145728: W_ih    = (const float*)d_in[i]; break;
            case 1048576: W_hh    = (const float*)d_in[i]; break;
            case 2048:    b_lstm  = (const float*)d_in[i]; break;
            case 524288:  vis2g_W = (const float*)d_in[i]; break;
            case 512:     vis2g_b = (const float*)d_in[i]; break;
            case 5120512: out_W   = (const float*)d_in[i]; break;
            case 10001:   out_b   = (const float*)d_in[i]; break;
            case 262144:  if (ntrio < 3) trio[ntrio++] = i; break;
            default: break;
        }
    }
    if (ntrio == 3) {
        vis   = (const float*)d_in[trio[0]];
        w2g_W = (const float*)d_in[trio[1]];
        h2g_W = (const float*)d_in[trio[2]];
    }
    if (!vis)     vis     = (const float*)d_in[0];
    if (!seqz)    seqz    = (const int*)  d_in[1];
    if (!emb)     emb     = (const float*)d_in[2];
    if (!W_ih)    W_ih    = (const float*)d_in[3];
    if (!W_hh)    W_hh    = (const float*)d_in[4];
    if (!b_lstm)  b_lstm  = (const float*)d_in[5];
    if (!vis2g_W) vis2g_W = (const float*)d_in[6];
    if (!vis2g_b) vis2g_b = (const float*)d_in[7];
    if (!w2g_W)   w2g_W   = (const float*)d_in[8];
    if (!h2g_W)   h2g_W   = (const float*)d_in[9];
    if (!out_W)   out_W   = (const float*)d_in[10];
    if (!out_b)   out_b   = (const float*)d_in[11];
    float* out = (float*)d_out;

    cudaFuncSetAttribute(k_wpg, cudaFuncAttributeMaxDynamicSharedMemorySize, WPG_SMEM);
    cudaFuncSetAttribute(k_rnn, cudaFuncAttributeMaxDynamicSharedMemorySize, RNN_SMEM);
    cudaFuncSetAttribute(k_lse, cudaFuncAttributeMaxDynamicSharedMemorySize, LSE_SMEM);

    k_prep<<<(int)(((size_t)RNN_ * V1P + 255) / 256), 256>>>(out_W);
    k_wpg<<<dim3(20, 128), 256, WPG_SMEM>>>(seqz, emb, W_ih, w2g_W);
    k_rnn<<<NCTA, 256, RNN_SMEM>>>(vis, W_ih, W_hh, b_lstm, vis2g_W, vis2g_b, h2g_W);
    k_lse<<<TB / 128, 512, LSE_SMEM>>>(out_b, seqz, out);
}

// round 15
// speedup vs baseline: 3.9709x; 1.7260x over previous
#include <cuda_runtime.h>
#include <cuda_bf16.h>
#include <cuda_fp16.h>
#include <mma.h>
#include <math.h>
#include <stdint.h>

using namespace nvcuda;

#define B_     256
#define T_     64
#define VOCAB_ 10000
#define V1     10001
#define V1P    10240
#define VIS_   1024
#define RNN_   512
#define GEXT   2560
#define TB     16384
#define NCTA   128
#define LOG2E  1.4426950408889634f

// ---------------- scratch ----------------
__device__ __nv_bfloat16 d_hbuf[2][B_ * RNN_];
__device__ float d_WPG[(size_t)TB * GEXT];            // word-part gates (168 MB)
__device__ __nv_bfloat16 d_Sb [(size_t)TB * RNN_];    // sentinel states bf16
__device__ __nv_bfloat16 d_OWb[(size_t)RNN_ * V1P];   // out_W bf16 padded

__device__ unsigned g_cnt = 0;
__device__ volatile unsigned g_sense = 0;

__device__ __forceinline__ void gbar(unsigned &ls)
{
    __syncthreads();
    if (threadIdx.x == 0) {
        ls ^= 1u;
        __threadfence();
        if (atomicAdd(&g_cnt, 1u) == NCTA - 1u) {
            g_cnt = 0u;
            __threadfence();
            g_sense = ls;
        } else {
            while (g_sense != ls) { }
            __threadfence();
        }
    }
    __syncthreads();
}

__device__ __forceinline__ float tanh_f(float x)
{
    float y;
    asm("tanh.approx.f32 %0, %1;" : "=f"(y) : "f"(x));
    return y;
}
__device__ __forceinline__ float sig_f(float x)
{
    return fmaf(0.5f, tanh_f(0.5f * x), 0.5f);
}

__device__ __forceinline__ void cp16(uint32_t dst, const void* src)
{
    asm volatile("cp.async.cg.shared.global [%0], [%1], 16;" :: "r"(dst), "l"(src));
}
__device__ __forceinline__ void cp_commit()
{
    asm volatile("cp.async.commit_group;" ::: "memory");
}
template<int N> __device__ __forceinline__ void cp_wait()
{
    asm volatile("cp.async.wait_group %0;" :: "n"(N) : "memory");
}

#define LOAD_A_TF32(frag, ptr, ldm) do { \
    wmma::load_matrix_sync(frag, ptr, ldm); \
    for (int _e = 0; _e < (frag).num_elements; _e++) \
        (frag).x[_e] = wmma::__float_to_tf32((frag).x[_e]); \
} while (0)

// ---------------- prep: out_W -> bf16 padded ----------------
__global__ __launch_bounds__(256) void k_prep(const float* __restrict__ out_W)
{
    size_t idx = (size_t)blockIdx.x * 256 + threadIdx.x;
    if (idx >= (size_t)RNN_ * V1P) return;
    int k = (int)(idx / V1P), v = (int)(idx % V1P);
    float w = (v < V1) ? out_W[(size_t)k * V1 + v] : 0.f;
    d_OWb[idx] = __float2bfloat16(w);
}

// =====================================================================
// k_wpg: WPG[16384,2560] = emb[words] @ [W_ih_word | w2g], tf32 WMMA.
// (unchanged from R14)
// =====================================================================
#define WPG_SMEM 66048
__global__ __launch_bounds__(256) void k_wpg(
    const int* __restrict__ seqz, const float* __restrict__ emb,
    const float* __restrict__ W_ih, const float* __restrict__ w2g_W)
{
    extern __shared__ char smraw[];
    float* As_ = (float*)smraw;
    float* Bs_ = (float*)(smraw + 32768);
    int*  stok = (int*)(smraw + 65536);
    const int tid = threadIdx.x;
    const int n0 = blockIdx.x * 128;
    const int m0 = blockIdx.y * 128;
    const int wid = tid >> 5;
    const int warp_m = wid >> 1;
    const int warp_n = wid & 1;
    uint32_t aB = (uint32_t)__cvta_generic_to_shared(As_);
    uint32_t bB = (uint32_t)__cvta_generic_to_shared(Bs_);

    if (tid < 128) {
        int row = m0 + tid;
        int t = row >> 8, b = row & 255;
        stok[tid] = (t == 0) ? (VOCAB_ + 1) : seqz[b * T_ + t - 1];
    }
    __syncthreads();

    auto issueA = [&](int s, int d) {
        int k0 = s * 32;
        #pragma unroll
        for (int j = 0; j < 4; j++) {
            int idx = tid + j * 256;
            int r = idx >> 3, sg = (idx & 7) << 2;
            cp16(aB + (uint32_t)((d * 4096 + r * 32 + sg) * 4),
                 emb + (size_t)stok[r] * RNN_ + k0 + sg);
        }
    };
    auto issueB = [&](int s, int d) {
        int k0 = s * 32;
        #pragma unroll
        for (int j = 0; j < 4; j++) {
            int idx = tid + j * 256;
            int kr = idx >> 5, c4 = (idx & 31) << 2;
            int kk = k0 + kr;
            const float* src = (n0 < 2048)
                ? W_ih + (size_t)(VIS_ + kk) * 2048 + n0 + c4
                : w2g_W + (size_t)kk * RNN_ + (n0 - 2048) + c4;
            cp16(bB + (uint32_t)((d * 4096 + kr * 128 + c4) * 4), src);
        }
    };

    wmma::fragment<wmma::accumulator, 16, 16, 8, float> acc[2][4];
    #pragma unroll
    for (int i = 0; i < 2; i++)
        #pragma unroll
        for (int j = 0; j < 4; j++) wmma::fill_fragment(acc[i][j], 0.f);

    issueA(0, 0); issueB(0, 0); cp_commit();
    for (int s = 0; s < 16; s++) {
        if (s < 15) { issueA(s + 1, (s + 1) & 1); issueB(s + 1, (s + 1) & 1); cp_commit(); cp_wait<1>(); }
        else        { cp_wait<0>(); }
        __syncthreads();
        int d = s & 1;
        #pragma unroll
        for (int k8 = 0; k8 < 4; k8++) {
            wmma::fragment<wmma::matrix_a, 16, 16, 8, wmma::precision::tf32, wmma::row_major> af[2];
            wmma::fragment<wmma::matrix_b, 16, 16, 8, wmma::precision::tf32, wmma::row_major> bf[4];
            #pragma unroll
            for (int i = 0; i < 2; i++)
                LOAD_A_TF32(af[i], As_ + d * 4096 + (warp_m * 32 + i * 16) * 32 + k8 * 8, 32);
            #pragma unroll
            for (int j = 0; j < 4; j++)
                LOAD_A_TF32(bf[j], Bs_ + d * 4096 + (k8 * 8) * 128 + warp_n * 64 + j * 16, 128);
            #pragma unroll
            for (int i = 0; i < 2; i++)
                #pragma unroll
                for (int j = 0; j < 4; j++)
                    wmma::mma_sync(acc[i][j], af[i], bf[j], acc[i][j]);
        }
        __syncthreads();
    }
    #pragma unroll
    for (int i = 0; i < 2; i++)
        #pragma unroll
        for (int j = 0; j < 4; j++)
            wmma::store_matrix_sync(
                d_WPG + (size_t)(m0 + warp_m * 32 + i * 16) * GEXT + n0 + warp_n * 64 + j * 16,
                acc[i][j], GEXT, wmma::mem_row_major);
}

// =====================================================================
// k_rnn v6: v5 + bank-conflict-free smem (padded leading dims).
// smem layout (bytes):
//   0       Wres bf16 [512][56]          57344
//   57344   Asb  bf16 [2][128][136]      69632 (alias: prologue f32 A [2][128][32]=32768; gsm f32 [128][52]=26624)
//   126976  vpgr f32  [128][40]          20480
//   147456  wpsm f32  [128][40]          20480
//   167936  cst  f32  [128][8]            4096
//   172032  bscr f32  [2][32][52]        13312
#define RNN_SMEM 185344
__global__ __launch_bounds__(256) void k_rnn(
    const float* __restrict__ vis,
    const float* __restrict__ W_ih,    const float* __restrict__ W_hh,
    const float* __restrict__ b_lstm,
    const float* __restrict__ vis2g_W, const float* __restrict__ vis2g_b,
    const float* __restrict__ h2g_W)
{
    extern __shared__ char smraw[];
    __nv_bfloat16* Wres = (__nv_bfloat16*)smraw;
    __nv_bfloat16* Asb  = (__nv_bfloat16*)(smraw + 57344);
    float* Asf  = (float*)(smraw + 57344);
    float* gsm  = (float*)(smraw + 57344);
    float* vpgr = (float*)(smraw + 126976);
    float* wpsm = (float*)(smraw + 147456);
    float* cst  = (float*)(smraw + 167936);
    float* bscr = (float*)(smraw + 172032);

    const int tid = threadIdx.x;
    const int ct  = blockIdx.x;
    const int wid = tid >> 5;
    const int u0  = (ct >> 1) * 8;
    const int m0  = (ct & 1) * 128;
    unsigned ls = 0;
    uint32_t aB = (uint32_t)__cvta_generic_to_shared(smraw + 57344);
    uint32_t bB = (uint32_t)__cvta_generic_to_shared(bscr);
    uint32_t wpB = (uint32_t)__cvta_generic_to_shared(wpsm);

    #pragma unroll
    for (int j = 0; j < 4; j++) {
        int e = tid + j * 256;
        cst[e] = 0.f;
        int r = e >> 3, u = e & 7;
        d_hbuf[0][(m0 + r) * RNN_ + u0 + u] = __float2bfloat16(0.f);
    }
    // zero bscr pad cols 40..51 (both buffers)
    #pragma unroll
    for (int j = 0; j < 3; j++) {
        int e = tid + j * 256;
        if (e < 768) {
            int d = e / 384, rr = (e % 384) / 12, c = 40 + (e % 12);
            bscr[d * 1664 + rr * 52 + c] = 0.f;
        }
    }
    __syncthreads();

    // ---- prologue GEMM (tf32): vis gates, K=1024, 32 slices of 32 ----
    {
        wmma::fragment<wmma::accumulator, 16, 16, 8, float> acc[3];
        #pragma unroll
        for (int f = 0; f < 3; f++) wmma::fill_fragment(acc[f], 0.f);

        auto issA = [&](int s, int d) {
            int k0 = s * 32;
            #pragma unroll
            for (int j = 0; j < 4; j++) {
                int idx = tid + j * 256;
                int r = idx >> 3, sg = (idx & 7) << 2;
                cp16(aB + (uint32_t)((d * 4096 + r * 32 + sg) * 4),
                     vis + (size_t)(m0 + r) * VIS_ + k0 + sg);
            }
        };
        auto issB = [&](int s, int d) {
            int k0 = s * 32;
            #pragma unroll
            for (int j = 0; j < 2; j++) {
                int e = tid + j * 256;
                if (e < 320) {
                    int r = e / 10, q = e % 10;
                    int g = q >> 1, c4 = (q & 1) << 2;
                    int kk = k0 + r;
                    const float* src = (g < 4)
                        ? W_ih + (size_t)kk * 2048 + g * 512 + u0 + c4
                        : vis2g_W + (size_t)kk * RNN_ + u0 + c4;
                    cp16(bB + (uint32_t)((d * 1664 + r * 52 + q * 4) * 4), src);
                }
            }
        };

        issA(0, 0); issB(0, 0); cp_commit();
        for (int s = 0; s < 32; s++) {
            if (s < 31) { issA(s + 1, (s + 1) & 1); issB(s + 1, (s + 1) & 1); cp_commit(); cp_wait<1>(); }
            else        { cp_wait<0>(); }
            __syncthreads();
            int d = s & 1;
            #pragma unroll
            for (int k8 = 0; k8 < 4; k8++) {
                wmma::fragment<wmma::matrix_a, 16, 16, 8, wmma::precision::tf32, wmma::row_major> af;
                LOAD_A_TF32(af, Asf + d * 4096 + (wid * 16) * 32 + k8 * 8, 32);
                #pragma unroll
                for (int f = 0; f < 3; f++) {
                    wmma::fragment<wmma::matrix_b, 16, 16, 8, wmma::precision::tf32, wmma::row_major> bf;
                    LOAD_A_TF32(bf, bscr + d * 1664 + (k8 * 8) * 52 + f * 16, 52);
                    wmma::mma_sync(acc[f], af, bf, acc[f]);
                }
            }
            __syncthreads();
        }
        #pragma unroll
        for (int f = 0; f < 3; f++)
            wmma::store_matrix_sync(gsm + (wid * 16) * 52 + f * 16, acc[f], 52, wmma::mem_row_major);
        __syncthreads();
    }

    #pragma unroll
    for (int j = 0; j < 20; j++) {
        int e = tid + j * 256;
        int r = e / 40, q = e % 40;
        int g = q >> 3, u = q & 7;
        float bias = (g < 4) ? b_lstm[g * 512 + u0 + u] : vis2g_b[u0 + u];
        vpgr[r * 40 + q] = gsm[r * 52 + q] + bias;
    }
    __syncthreads();

    // resident bf16 recurrence weights [512][56] (pad cols 40..55 zero)
    #pragma unroll
    for (int j = 0; j < 80; j++) {
        int e = tid + j * 256;
        int k = e / 40, q = e % 40;
        int g = q >> 3, u = q & 7;
        float w = (g < 4) ? W_hh[(size_t)k * 2048 + g * 512 + u0 + u]
                          : h2g_W[(size_t)k * RNN_ + u0 + u];
        Wres[k * 56 + q] = __float2bfloat16(w);
    }
    #pragma unroll
    for (int j = 0; j < 32; j++) {
        int e = tid + j * 256;
        int k = e >> 4, c = 40 + (e & 15);
        Wres[k * 56 + c] = __float2bfloat16(0.f);
    }
    gbar(ls);                                      // barrier #1

    // ---- 64 steps, 4 slices of K=128, padded Asb (lda 136) ----
    for (int t = 0; t < T_; t++) {
        const __nv_bfloat16* hb = d_hbuf[t & 1];
        __nv_bfloat16* hn = d_hbuf[(t & 1) ^ 1];
        const float* wpbase = d_WPG + (size_t)(t * 256 + m0) * GEXT;

        auto issH = [&](int s, int d) {
            int k0 = s * 128;
            #pragma unroll
            for (int j = 0; j < 8; j++) {
                int idx = tid + j * 256;           // 0..2047
                int r = idx >> 4, c8 = (idx & 15) << 3;
                cp16(aB + (uint32_t)(((d * 128 + r) * 136 + c8) * 2),
                     hb + (size_t)(m0 + r) * RNN_ + k0 + c8);
            }
        };
        {
            #pragma unroll
            for (int j = 0; j < 5; j++) {
                int e = tid + j * 256;
                int r = e / 10, q = e % 10;
                int g = q >> 1, half = q & 1;
                cp16(wpB + (uint32_t)((r * 40 + g * 8 + half * 4) * 4),
                     wpbase + (size_t)r * GEXT + g * 512 + u0 + half * 4);
            }
        }

        wmma::fragment<wmma::accumulator, 16, 16, 16, float> acc[3];
        #pragma unroll
        for (int f = 0; f < 3; f++) wmma::fill_fragment(acc[f], 0.f);

        issH(0, 0); cp_commit();
        for (int s = 0; s < 4; s++) {
            if (s < 3) { issH(s + 1, (s + 1) & 1); cp_commit(); cp_wait<1>(); }
            else       { cp_wait<0>(); }
            __syncthreads();
            int d = s & 1;
            #pragma unroll
            for (int k16 = 0; k16 < 8; k16++) {
                wmma::fragment<wmma::matrix_a, 16, 16, 16, __nv_bfloat16, wmma::row_major> af;
                wmma::load_matrix_sync(af, Asb + (d * 128 + wid * 16) * 136 + k16 * 16, 136);
                #pragma unroll
                for (int f = 0; f < 3; f++) {
                    wmma::fragment<wmma::matrix_b, 16, 16, 16, __nv_bfloat16, wmma::row_major> bf;
                    wmma::load_matrix_sync(bf, Wres + (s * 128 + k16 * 16) * 56 + f * 16, 56);
                    wmma::mma_sync(acc[f], af, bf, acc[f]);
                }
            }
            __syncthreads();
        }
        #pragma unroll
        for (int f = 0; f < 3; f++)
            wmma::store_matrix_sync(gsm + (wid * 16) * 52 + f * 16, acc[f], 52, wmma::mem_row_major);
        __syncthreads();

        #pragma unroll
        for (int j = 0; j < 4; j++) {
            int e = tid + j * 256;
            int r = e >> 3, u = e & 7;
            const float* gg = gsm + r * 52;
            const float* vp = vpgr + r * 40;
            const float* wp = wpsm + r * 40;
            float ig = gg[u]      + vp[u]      + wp[u];
            float fg = gg[8 + u]  + vp[8 + u]  + wp[8 + u];
            float g_ = gg[16 + u] + vp[16 + u] + wp[16 + u];
            float og = gg[24 + u] + vp[24 + u] + wp[24 + u];
            float gp = gg[32 + u] + vp[32 + u] + wp[32 + u];
            float cold = cst[e];
            float cn = sig_f(fg) * cold + sig_f(ig) * tanh_f(g_);
            float tc = tanh_f(cn);
            cst[e] = cn;
            hn[(m0 + r) * RNN_ + u0 + u] = __float2bfloat16(sig_f(og) * tc);
            d_Sb[(size_t)(t * 256 + m0 + r) * RNN_ + u0 + u] =
                __float2bfloat16(sig_f(gp) * tc);
        }
        gbar(ls);
    }
    gbar(ls);   // barriers: 1 + 64 + 1 = 66 (even)
}

// =====================================================================
// k_lse v5: conflict-free padded smem. 128 rows/CTA, 512 thr / 16 warps
// = (2 k-halves) x (8 m-groups of 16 rows) x (32 cols). Chunk = 32 cols,
// B prefetched via registers (4 x uint4). C double-buffered (3 syncs/chunk).
// smem: A bf16[128][520] @0 (133120); B bf16[512][40] @133120 (40960);
//       C f32[2][128][36] @174080 (36864). total 210944.
// =====================================================================
#define LSE_SMEM 210944
#define NCH 313                                    // ceil(10001/32)
__global__ __launch_bounds__(512) void k_lse(
    const float* __restrict__ out_b,
    const int* __restrict__ seqz, float* __restrict__ out)
{
    extern __shared__ unsigned char dyn[];
    __nv_bfloat16* Asm = (__nv_bfloat16*)dyn;              // lda 520
    __nv_bfloat16* Bsm = (__nv_bfloat16*)(dyn + 133120);   // ldb 40
    float*         Csm = (float*)(dyn + 174080);           // 2 x [128][36]
    __shared__ float s_tgt[128];
    __shared__ int   s_tg[128];

    const int tid = threadIdx.x;
    const int m0  = blockIdx.x * 128;
    const int wid = tid >> 5;
    const int km  = wid & 1;                       // k-half
    const int wm  = wid >> 1;                      // 0..7 (16-row group)

    if (tid < 128) {
        int r = m0 + tid;
        int t = r >> 8, b = r & 255;
        s_tg[tid] = seqz[b * T_ + t];
    }

    // A tile resident: 128 x 512 -> padded lda 520
    #pragma unroll
    for (int i = 0; i < 16; i++) {
        int idx = tid + i * 512;                   // 0..8191
        int r = idx >> 6, c = idx & 63;
        *(uint4*)(Asm + r * 520 + c * 8) =
            ((const uint4*)(d_Sb + (size_t)(m0 + r) * RNN_))[c];
    }
    __syncthreads();

    const int row = tid >> 2;                      // 0..127
    const int qtr = tid & 3;                       // 8 cols each
    const int mytg = s_tg[row];
    float rs = 0.f;

    // B register prefetch: 2048 uint4 / 512 thr = 4 per thread
    uint4 breg[4];
    auto ldB = [&](int ch) {
        int v0 = ch * 32;
        #pragma unroll
        for (int j = 0; j < 4; j++) {
            int idx = tid + j * 512;
            int k = idx >> 2, c8 = (idx & 3) << 3;
            breg[j] = *(const uint4*)(d_OWb + (size_t)k * V1P + v0 + c8);
        }
    };
    auto stB = [&]() {
        #pragma unroll
        for (int j = 0; j < 4; j++) {
            int idx = tid + j * 512;
            int k = idx >> 2, c8 = (idx & 3) << 3;
            *(uint4*)(Bsm + k * 40 + c8) = breg[j];
        }
    };

    ldB(0);
    for (int c = 0; c < NCH; c++) {
        stB();
        __syncthreads();                           // B visible (prev epilogue done)
        if (c < NCH - 1) ldB(c + 1);               // overlap next-chunk LDG

        float* Cp = Csm + (c & 1) * (128 * 36);

        wmma::fragment<wmma::accumulator, 16, 16, 16, float> acc[2];
        wmma::fill_fragment(acc[0], 0.f);
        wmma::fill_fragment(acc[1], 0.f);
        #pragma unroll
        for (int k = 0; k < 16; k++) {
            int kk = km * 256 + k * 16;
            wmma::fragment<wmma::matrix_a, 16, 16, 16, __nv_bfloat16, wmma::row_major> af;
            wmma::load_matrix_sync(af, Asm + (wm * 16) * 520 + kk, 520);
            #pragma unroll
            for (int j = 0; j < 2; j++) {
                wmma::fragment<wmma::matrix_b, 16, 16, 16, __nv_bfloat16, wmma::row_major> bf;
                wmma::load_matrix_sync(bf, Bsm + kk * 40 + j * 16, 40);
                wmma::mma_sync(acc[j], af, bf, acc[j]);
            }
        }

        if (km == 0) {
            #pragma unroll
            for (int j = 0; j < 2; j++)
                wmma::store_matrix_sync(Cp + (wm * 16) * 36 + j * 16, acc[j], 36,
                                        wmma::mem_row_major);
        }
        __syncthreads();
        if (km == 1) {
            #pragma unroll
            for (int j = 0; j < 2; j++) {
                wmma::fragment<wmma::accumulator, 16, 16, 16, float> cf;
                wmma::load_matrix_sync(cf, Cp + (wm * 16) * 36 + j * 16, 36,
                                       wmma::mem_row_major);
                #pragma unroll
                for (int e = 0; e < cf.num_elements; e++)
                    acc[j].x[e] += cf.x[e];
                wmma::store_matrix_sync(Cp + (wm * 16) * 36 + j * 16, acc[j], 36,
                                        wmma::mem_row_major);
            }
        }
        __syncthreads();

        // epilogue: 4 threads/row x 8 cols, packed f16x2 exp
        int v0 = c * 32;
        float lsum = 0.f;
        #pragma unroll
        for (int j = 0; j < 4; j++) {
            int cc = (qtr << 3) + 2 * j;
            int v = v0 + cc;
            float l0 = (v     < V1) ? (Cp[row * 36 + cc]     + out_b[v])     : -1e4f;
            float l1 = (v + 1 < V1) ? (Cp[row * 36 + cc + 1] + out_b[v + 1]) : -1e4f;
            uint32_t h2, e2;
            asm("cvt.rn.f16x2.f32 %0, %1, %2;" : "=r"(h2) : "f"(l1 * LOG2E), "f"(l0 * LOG2E));
            asm("ex2.approx.f16x2 %0, %1;" : "=r"(e2) : "r"(h2));
            __half2 hh = *reinterpret_cast<__half2*>(&e2);
            float2 ff = __half22float2(hh);
            lsum += ff.x + ff.y;
        }
        rs += lsum;
        if (mytg >= v0 + (qtr << 3) && mytg < v0 + (qtr << 3) + 8)
            s_tgt[row] = Cp[row * 36 + (mytg - v0)] + out_b[mytg];
        // no trailing sync: next stB touches only Bsm; Csm parity alternates
    }

    // reduce rs across the 4 lanes of each row (same warp)
    rs += __shfl_xor_sync(0xffffffffu, rs, 1);
    rs += __shfl_xor_sync(0xffffffffu, rs, 2);
    __syncthreads();                               // s_tgt complete
    if (qtr == 0) {
        int r = m0 + row;
        float lse = logf(rs);
        int t = r >> 8, b = r & 255;
        float mask = (t == 0) ? 1.f : ((seqz[b * T_ + (t - 1)] != 0) ? 1.f : 0.f);
        out[r] = (s_tgt[row] - lse) * mask;
    }
}

// ---------------- launch ----------------
extern "C" void kernel_launch(void* const* d_in, const int* in_sizes, int n_in,
                              void* d_out, int out_size)
{
    const float *vis = 0, *emb = 0, *W_ih = 0, *W_hh = 0, *b_lstm = 0;
    const float *vis2g_W = 0, *vis2g_b = 0, *w2g_W = 0, *h2g_W = 0;
    const float *out_W = 0, *out_b = 0;
    const int *seqz = 0;
    int trio[3]; int ntrio = 0;
    for (int i = 0; i < n_in; i++) {
        switch (in_sizes[i]) {
            case 16384:   seqz    = (const int*)  d_in[i]; break;
            case 5121024: emb     = (const float*)d_in[i]; break;
            case 3145728: W_ih    = (const float*)d_in[i]; break;
            case 1048576: W_hh    = (const float*)d_in[i]; break;
            case 2048:    b_lstm  = (const float*)d_in[i]; break;
            case 524288:  vis2g_W = (const float*)d_in[i]; break;
            case 512:     vis2g_b = (const float*)d_in[i]; break;
            case 5120512: out_W   = (const float*)d_in[i]; break;
            case 10001:   out_b   = (const float*)d_in[i]; break;
            case 262144:  if (ntrio < 3) trio[ntrio++] = i; break;
            default: break;
        }
    }
    if (ntrio == 3) {
        vis   = (const float*)d_in[trio[0]];
        w2g_W = (const float*)d_in[trio[1]];
        h2g_W = (const float*)d_in[trio[2]];
    }
    if (!vis)     vis     = (const float*)d_in[0];
    if (!seqz)    seqz    = (const int*)  d_in[1];
    if (!emb)     emb     = (const float*)d_in[2];
    if (!W_ih)    W_ih    = (const float*)d_in[3];
    if (!W_hh)    W_hh    = (const float*)d_in[4];
    if (!b_lstm)  b_lstm  = (const float*)d_in[5];
    if (!vis2g_W) vis2g_W = (const float*)d_in[6];
    if (!vis2g_b) vis2g_b = (const float*)d_in[7];
    if (!w2g_W)   w2g_W   = (const float*)d_in[8];
    if (!h2g_W)   h2g_W   = (const float*)d_in[9];
    if (!out_W)   out_W   = (const float*)d_in[10];
    if (!out_b)   out_b   = (const float*)d_in[11];
    float* out = (float*)d_out;

    cudaFuncSetAttribute(k_wpg, cudaFuncAttributeMaxDynamicSharedMemorySize, WPG_SMEM);
    cudaFuncSetAttribute(k_rnn, cudaFuncAttributeMaxDynamicSharedMemorySize, RNN_SMEM);
    cudaFuncSetAttribute(k_lse, cudaFuncAttributeMaxDynamicSharedMemorySize, LSE_SMEM);

    k_prep<<<(int)(((size_t)RNN_ * V1P + 255) / 256), 256>>>(out_W);
    k_wpg<<<dim3(20, 128), 256, WPG_SMEM>>>(seqz, emb, W_ih, w2g_W);
    k_rnn<<<NCTA, 256, RNN_SMEM>>>(vis, W_ih, W_hh, b_lstm, vis2g_W, vis2g_b, h2g_W);
    k_lse<<<TB / 128, 512, LSE_SMEM>>>(out_b, seqz, out);
}

// round 17
// speedup vs baseline: 5.3178x; 1.3392x over previous
#include <cuda_runtime.h>
#include <cuda_bf16.h>
#include <cuda_fp16.h>
#include <mma.h>
#include <math.h>
#include <stdint.h>

using namespace nvcuda;

#define B_     256
#define T_     64
#define VOCAB_ 10000
#define V1     10001
#define V1P    10240
#define VIS_   1024
#define RNN_   512
#define GEXT   2560
#define TB     16384
#define NCTA   128
#define LOG2E  1.4426950408889634f

// ---------------- scratch ----------------
__device__ __nv_bfloat16 d_hbuf[2][B_ * RNN_];
__device__ float d_WPG[(size_t)TB * GEXT];            // word-part gates (168 MB)
__device__ __nv_bfloat16 d_Sb [(size_t)TB * RNN_];    // sentinel states bf16
__device__ __nv_bfloat16 d_OWb[(size_t)RNN_ * V1P];   // out_W bf16 padded
__device__ __nv_bfloat16 d_embB[(size_t)(VOCAB_ + 2) * RNN_]; // emb bf16 (10 MB)
__device__ __nv_bfloat16 d_WWb[(size_t)RNN_ * GEXT];  // [W_ih_word | w2g] bf16 [k][n]

__device__ unsigned g_cnt = 0;
__device__ volatile unsigned g_sense = 0;

__device__ __forceinline__ void gbar(unsigned &ls)
{
    __syncthreads();
    if (threadIdx.x == 0) {
        ls ^= 1u;
        __threadfence();
        if (atomicAdd(&g_cnt, 1u) == NCTA - 1u) {
            g_cnt = 0u;
            __threadfence();
            g_sense = ls;
        } else {
            while (g_sense != ls) { }
            __threadfence();
        }
    }
    __syncthreads();
}

__device__ __forceinline__ float tanh_f(float x)
{
    float y;
    asm("tanh.approx.f32 %0, %1;" : "=f"(y) : "f"(x));
    return y;
}
__device__ __forceinline__ float sig_f(float x)
{
    return fmaf(0.5f, tanh_f(0.5f * x), 0.5f);
}

__device__ __forceinline__ void cp16(uint32_t dst, const void* src)
{
    asm volatile("cp.async.cg.shared.global [%0], [%1], 16;" :: "r"(dst), "l"(src));
}
__device__ __forceinline__ void cp_commit()
{
    asm volatile("cp.async.commit_group;" ::: "memory");
}
template<int N> __device__ __forceinline__ void cp_wait()
{
    asm volatile("cp.async.wait_group %0;" :: "n"(N) : "memory");
}

#define LOAD_A_TF32(frag, ptr, ldm) do { \
    wmma::load_matrix_sync(frag, ptr, ldm); \
    for (int _e = 0; _e < (frag).num_elements; _e++) \
        (frag).x[_e] = wmma::__float_to_tf32((frag).x[_e]); \
} while (0)

// ---------------- prep kernels ----------------
__global__ __launch_bounds__(256) void k_prep(const float* __restrict__ out_W)
{
    size_t idx = (size_t)blockIdx.x * 256 + threadIdx.x;
    if (idx >= (size_t)RNN_ * V1P) return;
    int k = (int)(idx / V1P), v = (int)(idx % V1P);
    float w = (v < V1) ? out_W[(size_t)k * V1 + v] : 0.f;
    d_OWb[idx] = __float2bfloat16(w);
}

__global__ __launch_bounds__(512) void k_prepE(const float* __restrict__ emb)
{
    size_t idx = (size_t)blockIdx.x * 512 + threadIdx.x;
    d_embB[idx] = __float2bfloat16(emb[idx]);
}

// d_WWb[k][n] (n over [W_ih_word 2048 | w2g 512])
__global__ __launch_bounds__(256) void k_prepW(
    const float* __restrict__ W_ih, const float* __restrict__ w2g_W)
{
    size_t idx = (size_t)blockIdx.x * 256 + threadIdx.x;
    if (idx >= (size_t)RNN_ * GEXT) return;
    int k = (int)(idx / GEXT), n = (int)(idx % GEXT);
    float w = (n < 2048) ? W_ih[(size_t)(VIS_ + k) * 2048 + n]
                         : w2g_W[(size_t)k * RNN_ + (n - 2048)];
    d_WWb[idx] = __float2bfloat16(w);
}

// =====================================================================
// k_wpg v2: WPG[16384,2560] = embB[words] @ WWb, bf16 k16 WMMA.
// Tiles: A [2][128][40] bf16 (pad 40), B [2][32][136] bf16 (pad 136).
// 8 warps = 4 warp_m (32 rows) x 2 warp_n (64 cols); acc[2][4].
// =====================================================================
#define WPG_SMEM (20480 + 17408 + 512 + 128)
__global__ __launch_bounds__(256) void k_wpg(const int* __restrict__ seqz)
{
    extern __shared__ char smraw[];
    __nv_bfloat16* As_ = (__nv_bfloat16*)smraw;             // [2][128][40] = 20480 B
    __nv_bfloat16* Bs_ = (__nv_bfloat16*)(smraw + 20480);   // [2][32][136] = 17408 B
    int* stok = (int*)(smraw + 37888);                      // [128]
    const int tid = threadIdx.x;
    const int n0 = blockIdx.x * 128;
    const int m0 = blockIdx.y * 128;
    const int wid = tid >> 5;
    const int warp_m = wid >> 1;                            // 0..3
    const int warp_n = wid & 1;                             // 0..1
    uint32_t aB = (uint32_t)__cvta_generic_to_shared(As_);
    uint32_t bB = (uint32_t)__cvta_generic_to_shared(Bs_);

    if (tid < 128) {
        int row = m0 + tid;
        int t = row >> 8, b = row & 255;
        stok[tid] = (t == 0) ? (VOCAB_ + 1) : seqz[b * T_ + t - 1];
    }
    __syncthreads();

    auto issueA = [&](int s, int d) {
        int k0 = s * 32;
        #pragma unroll
        for (int j = 0; j < 2; j++) {
            int idx = tid + j * 256;            // 0..511
            int r = idx >> 2, c8 = (idx & 3) << 3;
            cp16(aB + (uint32_t)(((d * 128 + r) * 40 + c8) * 2),
                 d_embB + (size_t)stok[r] * RNN_ + k0 + c8);
        }
    };
    auto issueB = [&](int s, int d) {
        int k0 = s * 32;
        #pragma unroll
        for (int j = 0; j < 2; j++) {
            int idx = tid + j * 256;            // 0..511
            int kr = idx >> 4, c8 = (idx & 15) << 3;
            cp16(bB + (uint32_t)(((d * 32 + kr) * 136 + c8) * 2),
                 d_WWb + (size_t)(k0 + kr) * GEXT + n0 + c8);
        }
    };

    wmma::fragment<wmma::accumulator, 16, 16, 16, float> acc[2][4];
    #pragma unroll
    for (int i = 0; i < 2; i++)
        #pragma unroll
        for (int j = 0; j < 4; j++) wmma::fill_fragment(acc[i][j], 0.f);

    issueA(0, 0); issueB(0, 0); cp_commit();
    for (int s = 0; s < 16; s++) {
        if (s < 15) { issueA(s + 1, (s + 1) & 1); issueB(s + 1, (s + 1) & 1); cp_commit(); cp_wait<1>(); }
        else        { cp_wait<0>(); }
        __syncthreads();
        int d = s & 1;
        #pragma unroll
        for (int k16 = 0; k16 < 2; k16++) {
            wmma::fragment<wmma::matrix_a, 16, 16, 16, __nv_bfloat16, wmma::row_major> af[2];
            wmma::fragment<wmma::matrix_b, 16, 16, 16, __nv_bfloat16, wmma::row_major> bf[4];
            #pragma unroll
            for (int i = 0; i < 2; i++)
                wmma::load_matrix_sync(af[i], As_ + (d * 128 + warp_m * 32 + i * 16) * 40 + k16 * 16, 40);
            #pragma unroll
            for (int j = 0; j < 4; j++)
                wmma::load_matrix_sync(bf[j], Bs_ + (d * 32 + k16 * 16) * 136 + warp_n * 64 + j * 16, 136);
            #pragma unroll
            for (int i = 0; i < 2; i++)
                #pragma unroll
                for (int j = 0; j < 4; j++)
                    wmma::mma_sync(acc[i][j], af[i], bf[j], acc[i][j]);
        }
        __syncthreads();
    }
    #pragma unroll
    for (int i = 0; i < 2; i++)
        #pragma unroll
        for (int j = 0; j < 4; j++)
            wmma::store_matrix_sync(
                d_WPG + (size_t)(m0 + warp_m * 32 + i * 16) * GEXT + n0 + warp_n * 64 + j * 16,
                acc[i][j], GEXT, wmma::mem_row_major);
}

// =====================================================================
// k_rnn v6 (unchanged from R15): bank-conflict-free padded smem.
// =====================================================================
#define RNN_SMEM 185344
__global__ __launch_bounds__(256) void k_rnn(
    const float* __restrict__ vis,
    const float* __restrict__ W_ih,    const float* __restrict__ W_hh,
    const float* __restrict__ b_lstm,
    const float* __restrict__ vis2g_W, const float* __restrict__ vis2g_b,
    const float* __restrict__ h2g_W)
{
    extern __shared__ char smraw[];
    __nv_bfloat16* Wres = (__nv_bfloat16*)smraw;
    __nv_bfloat16* Asb  = (__nv_bfloat16*)(smraw + 57344);
    float* Asf  = (float*)(smraw + 57344);
    float* gsm  = (float*)(smraw + 57344);
    float* vpgr = (float*)(smraw + 126976);
    float* wpsm = (float*)(smraw + 147456);
    float* cst  = (float*)(smraw + 167936);
    float* bscr = (float*)(smraw + 172032);

    const int tid = threadIdx.x;
    const int ct  = blockIdx.x;
    const int wid = tid >> 5;
    const int u0  = (ct >> 1) * 8;
    const int m0  = (ct & 1) * 128;
    unsigned ls = 0;
    uint32_t aB = (uint32_t)__cvta_generic_to_shared(smraw + 57344);
    uint32_t bB = (uint32_t)__cvta_generic_to_shared(bscr);
    uint32_t wpB = (uint32_t)__cvta_generic_to_shared(wpsm);

    #pragma unroll
    for (int j = 0; j < 4; j++) {
        int e = tid + j * 256;
        cst[e] = 0.f;
        int r = e >> 3, u = e & 7;
        d_hbuf[0][(m0 + r) * RNN_ + u0 + u] = __float2bfloat16(0.f);
    }
    #pragma unroll
    for (int j = 0; j < 3; j++) {
        int e = tid + j * 256;
        if (e < 768) {
            int d = e / 384, rr = (e % 384) / 12, c = 40 + (e % 12);
            bscr[d * 1664 + rr * 52 + c] = 0.f;
        }
    }
    __syncthreads();

    {
        wmma::fragment<wmma::accumulator, 16, 16, 8, float> acc[3];
        #pragma unroll
        for (int f = 0; f < 3; f++) wmma::fill_fragment(acc[f], 0.f);

        auto issA = [&](int s, int d) {
            int k0 = s * 32;
            #pragma unroll
            for (int j = 0; j < 4; j++) {
                int idx = tid + j * 256;
                int r = idx >> 3, sg = (idx & 7) << 2;
                cp16(aB + (uint32_t)((d * 4096 + r * 32 + sg) * 4),
                     vis + (size_t)(m0 + r) * VIS_ + k0 + sg);
            }
        };
        auto issB = [&](int s, int d) {
            int k0 = s * 32;
            #pragma unroll
            for (int j = 0; j < 2; j++) {
                int e = tid + j * 256;
                if (e < 320) {
                    int r = e / 10, q = e % 10;
                    int g = q >> 1, c4 = (q & 1) << 2;
                    int kk = k0 + r;
                    const float* src = (g < 4)
                        ? W_ih + (size_t)kk * 2048 + g * 512 + u0 + c4
                        : vis2g_W + (size_t)kk * RNN_ + u0 + c4;
                    cp16(bB + (uint32_t)((d * 1664 + r * 52 + q * 4) * 4), src);
                }
            }
        };

        issA(0, 0); issB(0, 0); cp_commit();
        for (int s = 0; s < 32; s++) {
            if (s < 31) { issA(s + 1, (s + 1) & 1); issB(s + 1, (s + 1) & 1); cp_commit(); cp_wait<1>(); }
            else        { cp_wait<0>(); }
            __syncthreads();
            int d = s & 1;
            #pragma unroll
            for (int k8 = 0; k8 < 4; k8++) {
                wmma::fragment<wmma::matrix_a, 16, 16, 8, wmma::precision::tf32, wmma::row_major> af;
                LOAD_A_TF32(af, Asf + d * 4096 + (wid * 16) * 32 + k8 * 8, 32);
                #pragma unroll
                for (int f = 0; f < 3; f++) {
                    wmma::fragment<wmma::matrix_b, 16, 16, 8, wmma::precision::tf32, wmma::row_major> bf;
                    LOAD_A_TF32(bf, bscr + d * 1664 + (k8 * 8) * 52 + f * 16, 52);
                    wmma::mma_sync(acc[f], af, bf, acc[f]);
                }
            }
            __syncthreads();
        }
        #pragma unroll
        for (int f = 0; f < 3; f++)
            wmma::store_matrix_sync(gsm + (wid * 16) * 52 + f * 16, acc[f], 52, wmma::mem_row_major);
        __syncthreads();
    }

    #pragma unroll
    for (int j = 0; j < 20; j++) {
        int e = tid + j * 256;
        int r = e / 40, q = e % 40;
        int g = q >> 3, u = q & 7;
        float bias = (g < 4) ? b_lstm[g * 512 + u0 + u] : vis2g_b[u0 + u];
        vpgr[r * 40 + q] = gsm[r * 52 + q] + bias;
    }
    __syncthreads();

    #pragma unroll
    for (int j = 0; j < 80; j++) {
        int e = tid + j * 256;
        int k = e / 40, q = e % 40;
        int g = q >> 3, u = q & 7;
        float w = (g < 4) ? W_hh[(size_t)k * 2048 + g * 512 + u0 + u]
                          : h2g_W[(size_t)k * RNN_ + u0 + u];
        Wres[k * 56 + q] = __float2bfloat16(w);
    }
    #pragma unroll
    for (int j = 0; j < 32; j++) {
        int e = tid + j * 256;
        int k = e >> 4, c = 40 + (e & 15);
        Wres[k * 56 + c] = __float2bfloat16(0.f);
    }
    gbar(ls);

    for (int t = 0; t < T_; t++) {
        const __nv_bfloat16* hb = d_hbuf[t & 1];
        __nv_bfloat16* hn = d_hbuf[(t & 1) ^ 1];
        const float* wpbase = d_WPG + (size_t)(t * 256 + m0) * GEXT;

        auto issH = [&](int s, int d) {
            int k0 = s * 128;
            #pragma unroll
            for (int j = 0; j < 8; j++) {
                int idx = tid + j * 256;
                int r = idx >> 4, c8 = (idx & 15) << 3;
                cp16(aB + (uint32_t)(((d * 128 + r) * 136 + c8) * 2),
                     hb + (size_t)(m0 + r) * RNN_ + k0 + c8);
            }
        };
        {
            #pragma unroll
            for (int j = 0; j < 5; j++) {
                int e = tid + j * 256;
                int r = e / 10, q = e % 10;
                int g = q >> 1, half = q & 1;
                cp16(wpB + (uint32_t)((r * 40 + g * 8 + half * 4) * 4),
                     wpbase + (size_t)r * GEXT + g * 512 + u0 + half * 4);
            }
        }

        wmma::fragment<wmma::accumulator, 16, 16, 16, float> acc[3];
        #pragma unroll
        for (int f = 0; f < 3; f++) wmma::fill_fragment(acc[f], 0.f);

        issH(0, 0); cp_commit();
        for (int s = 0; s < 4; s++) {
            if (s < 3) { issH(s + 1, (s + 1) & 1); cp_commit(); cp_wait<1>(); }
            else       { cp_wait<0>(); }
            __syncthreads();
            int d = s & 1;
            #pragma unroll
            for (int k16 = 0; k16 < 8; k16++) {
                wmma::fragment<wmma::matrix_a, 16, 16, 16, __nv_bfloat16, wmma::row_major> af;
                wmma::load_matrix_sync(af, Asb + (d * 128 + wid * 16) * 136 + k16 * 16, 136);
                #pragma unroll
                for (int f = 0; f < 3; f++) {
                    wmma::fragment<wmma::matrix_b, 16, 16, 16, __nv_bfloat16, wmma::row_major> bf;
                    wmma::load_matrix_sync(bf, Wres + (s * 128 + k16 * 16) * 56 + f * 16, 56);
                    wmma::mma_sync(acc[f], af, bf, acc[f]);
                }
            }
            __syncthreads();
        }
        #pragma unroll
        for (int f = 0; f < 3; f++)
            wmma::store_matrix_sync(gsm + (wid * 16) * 52 + f * 16, acc[f], 52, wmma::mem_row_major);
        __syncthreads();

        #pragma unroll
        for (int j = 0; j < 4; j++) {
            int e = tid + j * 256;
            int r = e >> 3, u = e & 7;
            const float* gg = gsm + r * 52;
            const float* vp = vpgr + r * 40;
            const float* wp = wpsm + r * 40;
            float ig = gg[u]      + vp[u]      + wp[u];
            float fg = gg[8 + u]  + vp[8 + u]  + wp[8 + u];
            float g_ = gg[16 + u] + vp[16 + u] + wp[16 + u];
            float og = gg[24 + u] + vp[24 + u] + wp[24 + u];
            float gp = gg[32 + u] + vp[32 + u] + wp[32 + u];
            float cold = cst[e];
            float cn = sig_f(fg) * cold + sig_f(ig) * tanh_f(g_);
            float tc = tanh_f(cn);
            cst[e] = cn;
            hn[(m0 + r) * RNN_ + u0 + u] = __float2bfloat16(sig_f(og) * tc);
            d_Sb[(size_t)(t * 256 + m0 + r) * RNN_ + u0 + u] =
                __float2bfloat16(sig_f(gp) * tc);
        }
        gbar(ls);
    }
    gbar(ls);   // barriers: 1 + 64 + 1 = 66 (even)
}

// =====================================================================
// k_lse v7: R15 layout + 2x2 register blocking. 256 thr / 8 warps =
// (2 k-halves) x (4 m-groups of 32 rows); each warp 32x32 with af[2],
// bf[2] -> 4 mma per load pair (1.0 frag-load/mma, half B redundancy).
// smem: A bf16[128][520] @0 (133120); B bf16[512][40] @133120 (40960);
//       C f32[2][128][36] @174080 (36864). total 210944.
// =====================================================================
#define LSE_SMEM 210944
#define NCH 313                                    // ceil(10001/32)
__global__ __launch_bounds__(256) void k_lse(
    const float* __restrict__ out_b,
    const int* __restrict__ seqz, float* __restrict__ out)
{
    extern __shared__ unsigned char dyn[];
    __nv_bfloat16* Asm = (__nv_bfloat16*)dyn;              // lda 520
    __nv_bfloat16* Bsm = (__nv_bfloat16*)(dyn + 133120);   // ldb 40
    float*         Csm = (float*)(dyn + 174080);           // 2 x [128][36]
    __shared__ float s_tgt[128];
    __shared__ int   s_tg[128];

    const int tid = threadIdx.x;
    const int m0  = blockIdx.x * 128;
    const int wid = tid >> 5;
    const int km  = wid & 1;                       // k-half
    const int wm  = wid >> 1;                      // 0..3 (32-row group)

    if (tid < 128) {
        int r = m0 + tid;
        int t = r >> 8, b = r & 255;
        s_tg[tid] = seqz[b * T_ + t];
    }

    // A tile resident: 128 x 512 -> padded lda 520 (8192 uint4 / 256 thr)
    #pragma unroll
    for (int i = 0; i < 32; i++) {
        int idx = tid + i * 256;                   // 0..8191
        int r = idx >> 6, c = idx & 63;
        *(uint4*)(Asm + r * 520 + c * 8) =
            ((const uint4*)(d_Sb + (size_t)(m0 + r) * RNN_))[c];
    }
    __syncthreads();

    const int row = tid >> 1;                      // 0..127
    const int qtr = tid & 1;                       // 16 cols each
    const int mytg = s_tg[row];
    float rs = 0.f;

    // B register prefetch: 2048 uint4 / 256 thr = 8 per thread
    uint4 breg[8];
    auto ldB = [&](int ch) {
        int v0 = ch * 32;
        #pragma unroll
        for (int j = 0; j < 8; j++) {
            int idx = tid + j * 256;
            int k = idx >> 2, c8 = (idx & 3) << 3;
            breg[j] = *(const uint4*)(d_OWb + (size_t)k * V1P + v0 + c8);
        }
    };
    auto stB = [&]() {
        #pragma unroll
        for (int j = 0; j < 8; j++) {
            int idx = tid + j * 256;
            int k = idx >> 2, c8 = (idx & 3) << 3;
            *(uint4*)(Bsm + k * 40 + c8) = breg[j];
        }
    };

    ldB(0);
    for (int c = 0; c < NCH; c++) {
        stB();
        __syncthreads();                           // B visible
        if (c < NCH - 1) ldB(c + 1);               // overlap next-chunk LDG

        float* Cp = Csm + (c & 1) * (128 * 36);

        wmma::fragment<wmma::accumulator, 16, 16, 16, float> acc[2][2];
        #pragma unroll
        for (int i = 0; i < 2; i++)
            #pragma unroll
            for (int j = 0; j < 2; j++) wmma::fill_fragment(acc[i][j], 0.f);

        #pragma unroll
        for (int k = 0; k < 16; k++) {
            int kk = km * 256 + k * 16;
            wmma::fragment<wmma::matrix_a, 16, 16, 16, __nv_bfloat16, wmma::row_major> af[2];
            wmma::fragment<wmma::matrix_b, 16, 16, 16, __nv_bfloat16, wmma::row_major> bf[2];
            #pragma unroll
            for (int i = 0; i < 2; i++)
                wmma::load_matrix_sync(af[i], Asm + (wm * 32 + i * 16) * 520 + kk, 520);
            #pragma unroll
            for (int j = 0; j < 2; j++)
                wmma::load_matrix_sync(bf[j], Bsm + kk * 40 + j * 16, 40);
            #pragma unroll
            for (int i = 0; i < 2; i++)
                #pragma unroll
                for (int j = 0; j < 2; j++)
                    wmma::mma_sync(acc[i][j], af[i], bf[j], acc[i][j]);
        }

        if (km == 0) {
            #pragma unroll
            for (int i = 0; i < 2; i++)
                #pragma unroll
                for (int j = 0; j < 2; j++)
                    wmma::store_matrix_sync(Cp + (wm * 32 + i * 16) * 36 + j * 16,
                                            acc[i][j], 36, wmma::mem_row_major);
        }
        __syncthreads();
        if (km == 1) {
            #pragma unroll
            for (int i = 0; i < 2; i++)
                #pragma unroll
                for (int j = 0; j < 2; j++) {
                    wmma::fragment<wmma::accumulator, 16, 16, 16, float> cf;
                    wmma::load_matrix_sync(cf, Cp + (wm * 32 + i * 16) * 36 + j * 16, 36,
                                           wmma::mem_row_major);
                    #pragma unroll
                    for (int e = 0; e < cf.num_elements; e++)
                        acc[i][j].x[e] += cf.x[e];
                    wmma::store_matrix_sync(Cp + (wm * 32 + i * 16) * 36 + j * 16,
                                            acc[i][j], 36, wmma::mem_row_major);
                }
        }
        __syncthreads();

        // epilogue: 2 threads/row x 16 cols, packed f16x2 exp
        int v0 = c * 32;
        float lsum = 0.f;
        #pragma unroll
        for (int j = 0; j < 8; j++) {
            int cc = (qtr << 4) + 2 * j;
            int v = v0 + cc;
            float l0 = (v     < V1) ? (Cp[row * 36 + cc]     + out_b[v])     : -1e4f;
            float l1 = (v + 1 < V1) ? (Cp[row * 36 + cc + 1] + out_b[v + 1]) : -1e4f;
            uint32_t h2, e2;
            asm("cvt.rn.f16x2.f32 %0, %1, %2;" : "=r"(h2) : "f"(l1 * LOG2E), "f"(l0 * LOG2E));
            asm("ex2.approx.f16x2 %0, %1;" : "=r"(e2) : "r"(h2));
            __half2 hh = *reinterpret_cast<__half2*>(&e2);
            float2 ff = __half22float2(hh);
            lsum += ff.x + ff.y;
        }
        rs += lsum;
        if (mytg >= v0 + (qtr << 4) && mytg < v0 + (qtr << 4) + 16)
            s_tgt[row] = Cp[row * 36 + (mytg - v0)] + out_b[mytg];
        // no trailing sync: next stB touches only Bsm; Csm parity alternates
    }

    // reduce rs across the 2 lanes of each row (same warp)
    rs += __shfl_xor_sync(0xffffffffu, rs, 1);
    __syncthreads();                               // s_tgt complete
    if (qtr == 0) {
        int r = m0 + row;
        float lse = logf(rs);
        int t = r >> 8, b = r & 255;
        float mask = (t == 0) ? 1.f : ((seqz[b * T_ + (t - 1)] != 0) ? 1.f : 0.f);
        out[r] = (s_tgt[row] - lse) * mask;
    }
}

// ---------------- launch ----------------
extern "C" void kernel_launch(void* const* d_in, const int* in_sizes, int n_in,
                              void* d_out, int out_size)
{
    const float *vis = 0, *emb = 0, *W_ih = 0, *W_hh = 0, *b_lstm = 0;
    const float *vis2g_W = 0, *vis2g_b = 0, *w2g_W = 0, *h2g_W = 0;
    const float *out_W = 0, *out_b = 0;
    const int *seqz = 0;
    int trio[3]; int ntrio = 0;
    for (int i = 0; i < n_in; i++) {
        switch (in_sizes[i]) {
            case 16384:   seqz    = (const int*)  d_in[i]; break;
            case 5121024: emb     = (const float*)d_in[i]; break;
            case 3145728: W_ih    = (const float*)d_in[i]; break;
            case 1048576: W_hh    = (const float*)d_in[i]; break;
            case 2048:    b_lstm  = (const float*)d_in[i]; break;
            case 524288:  vis2g_W = (const float*)d_in[i]; break;
            case 512:     vis2g_b = (const float*)d_in[i]; break;
            case 5120512: out_W   = (const float*)d_in[i]; break;
            case 10001:   out_b   = (const float*)d_in[i]; break;
            case 262144:  if (ntrio < 3) trio[ntrio++] = i; break;
            default: break;
        }
    }
    if (ntrio == 3) {
        vis   = (const float*)d_in[trio[0]];
        w2g_W = (const float*)d_in[trio[1]];
        h2g_W = (const float*)d_in[trio[2]];
    }
    if (!vis)     vis     = (const float*)d_in[0];
    if (!seqz)    seqz    = (const int*)  d_in[1];
    if (!emb)     emb     = (const float*)d_in[2];
    if (!W_ih)    W_ih    = (const float*)d_in[3];
    if (!W_hh)    W_hh    = (const float*)d_in[4];
    if (!b_lstm)  b_lstm  = (const float*)d_in[5];
    if (!vis2g_W) vis2g_W = (const float*)d_in[6];
    if (!vis2g_b) vis2g_b = (const float*)d_in[7];
    if (!w2g_W)   w2g_W   = (const float*)d_in[8];
    if (!h2g_W)   h2g_W   = (const float*)d_in[9];
    if (!out_W)   out_W   = (const float*)d_in[10];
    if (!out_b)   out_b   = (const float*)d_in[11];
    float* out = (float*)d_out;

    cudaFuncSetAttribute(k_wpg, cudaFuncAttributeMaxDynamicSharedMemorySize, WPG_SMEM);
    cudaFuncSetAttribute(k_rnn, cudaFuncAttributeMaxDynamicSharedMemorySize, RNN_SMEM);
    cudaFuncSetAttribute(k_lse, cudaFuncAttributeMaxDynamicSharedMemorySize, LSE_SMEM);

    k_prep<<<(int)(((size_t)RNN_ * V1P + 255) / 256), 256>>>(out_W);
    k_prepE<<<(int)(((size_t)(VOCAB_ + 2) * RNN_) / 512), 512>>>(emb);
    k_prepW<<<(int)(((size_t)RNN_ * GEXT + 255) / 256), 256>>>(W_ih, w2g_W);
    k_wpg<<<dim3(20, 128), 256, WPG_SMEM>>>(seqz);
    k_rnn<<<NCTA, 256, RNN_SMEM>>>(vis, W_ih, W_hh, b_lstm, vis2g_W, vis2g_b, h2g_W);
    k_lse<<<TB / 128, 256, LSE_SMEM>>>(out_b, seqz, out);
}